// round 10
// baseline (speedup 1.0000x reference)
#include <cuda_runtime.h>
#include <cuda_fp16.h>
#include <cstdint>

#define NN 100000
#define NE 600000
#define HD 128

// ---------------- scratch (static device memory; no allocs) ----------------
static __device__ float  g_x  [NN * HD];
static __device__ float  g_y  [NN * HD];
static __device__ float  g_agg[NN * HD];          // node-head hidden B
static __device__ __half g_pairAh[NN * 256];      // [node][0:128)=er A-part, [128:256)=ea A-part
static __device__ __half g_pairBh[NN * 256];      // [node][0:128)=er B-part, [128:256)=ea B-part
static __device__ int    g_deg[NN];
static __device__ int    g_rowptr[NN + 1];
static __device__ int    g_cursor[NN];
static __device__ int    g_col[2 * NE];
static __device__ float  g_invdeg[NN];
static __device__ int    g_tmp[NN];
static __device__ int    g_bsum[128];
static __device__ uint32_t g_pw[12 * 16384];      // packed tf32 weights, fragment order

// ---------------- tf32 helpers ----------------
__device__ __forceinline__ uint32_t f2tf(float f)
{
    uint32_t r;
    asm("cvt.rna.tf32.f32 %0, %1;" : "=r"(r) : "f"(f));
    return r;
}

#define MMA8(c, a0, a1, a2, a3, b0, b1)                                     \
    asm volatile("mma.sync.aligned.m16n8k8.row.col.f32.tf32.tf32.f32 "      \
                 "{%0,%1,%2,%3},{%4,%5,%6,%7},{%8,%9},{%0,%1,%2,%3};"       \
                 : "+f"((c)[0]), "+f"((c)[1]), "+f"((c)[2]), "+f"((c)[3])   \
                 : "r"(a0), "r"(a1), "r"(a2), "r"(a3), "r"(b0), "r"(b1))

// ---------------- weight pre-pack: 12 matrices of 128x128 into fragment order ----------------
struct PackSrc { const float* s[12]; };

__global__ void k_pack(PackSrc ps)
{
    int idx = blockIdx.x * 256 + threadIdx.x;
    if (idx >= 12 * 16384) return;
    int m = idx >> 14, e = idx & 16383;
    int k = e >> 7, nn2 = e & 127;
    int kstep = k >> 3, kin = k & 7, ntile = nn2 >> 3, nin = nn2 & 7;
    int lane = (nin << 2) | (kin & 3);
    int dest = (((kstep << 4) + ntile) << 6) + (lane << 1) + (kin >> 2);
    g_pw[m * 16384 + dest] = f2tf(__ldg(&ps.s[m][e]));
}

// ---------------- encoder: x = node_feats(8) @ W_enc + b_enc ----------------
__global__ void k_encoder(const float* __restrict__ ns, const float* __restrict__ pobs,
                          const int* __restrict__ pmask, const float* __restrict__ Wenc,
                          const float* __restrict__ benc, float* __restrict__ x, int n)
{
    __shared__ float sW[8 * HD];
    __shared__ float sb[HD];
    for (int i = threadIdx.x; i < 8 * HD; i += blockDim.x) sW[i] = Wenc[i];
    for (int i = threadIdx.x; i < HD; i += blockDim.x) sb[i] = benc[i];
    __syncthreads();
    int idx = blockIdx.x * blockDim.x + threadIdx.x;
    if (idx >= n * HD) return;
    int node = idx >> 7, h = idx & 127;
    float f0 = ns[node * 6 + 0], f1 = ns[node * 6 + 1], f2 = ns[node * 6 + 2];
    float f3 = ns[node * 6 + 3], f4 = ns[node * 6 + 4], f5 = ns[node * 6 + 5];
    float f6 = pobs[node];
    float f7 = (float)pmask[node];
    float o = sb[h];
    o += f0 * sW[0 * HD + h] + f1 * sW[1 * HD + h] + f2 * sW[2 * HD + h] + f3 * sW[3 * HD + h];
    o += f4 * sW[4 * HD + h] + f5 * sW[5 * HD + h] + f6 * sW[6 * HD + h] + f7 * sW[7 * HD + h];
    x[idx] = o;
}

// ---------------- CSR build ----------------
__global__ void k_zero_deg(int n)
{
    int i = blockIdx.x * blockDim.x + threadIdx.x;
    if (i < n) g_deg[i] = 0;
}

__global__ void k_deg(const int* __restrict__ ei, int ne)
{
    int e = blockIdx.x * blockDim.x + threadIdx.x;
    if (e >= ne) return;
    int s = ei[e], d = ei[ne + e];
    atomicAdd(&g_deg[s], 1);
    atomicAdd(&g_deg[d], 1);
}

__global__ void k_scan_local(int n)
{
    __shared__ int sh[1024];
    int t = threadIdx.x;
    int i = blockIdx.x * 1024 + t;
    int v = (i < n) ? g_deg[i] : 0;
    sh[t] = v;
    __syncthreads();
    for (int off = 1; off < 1024; off <<= 1) {
        int tv = (t >= off) ? sh[t - off] : 0;
        __syncthreads();
        sh[t] += tv;
        __syncthreads();
    }
    if (i < n) g_tmp[i] = sh[t];
    if (t == 1023) g_bsum[blockIdx.x] = sh[1023];
}

__global__ void k_scan_bsum(int nb)
{
    if (threadIdx.x == 0) {
        int acc = 0;
        for (int b = 0; b < nb; b++) { int tv = g_bsum[b]; g_bsum[b] = acc; acc += tv; }
    }
}

__global__ void k_scan_final(int n)
{
    int i = blockIdx.x * blockDim.x + threadIdx.x;
    if (i >= n) return;
    int incl = g_tmp[i] + g_bsum[i >> 10];
    g_rowptr[i + 1] = incl;
    int d = g_deg[i];
    g_cursor[i] = incl - d;
    g_invdeg[i] = 1.0f / (float)(d > 0 ? d : 1);
    if (i == 0) g_rowptr[0] = 0;
}

__global__ void k_fill(const int* __restrict__ ei, int ne)
{
    int e = blockIdx.x * blockDim.x + threadIdx.x;
    if (e >= ne) return;
    int s = ei[e], d = ei[ne + e];
    int p = atomicAdd(&g_cursor[d], 1);
    g_col[p] = s;
    int q = atomicAdd(&g_cursor[s], 1);
    g_col[q] = d;
}

// ---------------- fused GNN layer: agg-gather in-kernel + dual MMA ----------------
// C = op(A@W0 + mean_neigh(A)@W1 + bias). Block 256 thr / 8 warps, tile 64x128.
// sA staged from A rows; sA2 gathered (warp = 8 rows, lane = 4 cols, x4 unroll).
__global__ void __launch_bounds__(256) k_gemm_layer(
    const float* __restrict__ A,
    const uint32_t* __restrict__ pW0, const uint32_t* __restrict__ pW1,
    const float* __restrict__ bias, float* __restrict__ C, int n, int relu)
{
    extern __shared__ uint32_t sm[];
    uint32_t* sA  = sm;
    uint32_t* sA2 = sm + 8448;

    int tid = threadIdx.x;
    int wid = tid >> 5, lane = tid & 31;
    int row0 = blockIdx.x * 64;

    for (int idx = tid; idx < 8192; idx += 256) {
        int r = idx >> 7, cc = idx & 127;
        int gr = row0 + r;
        sA[r * 132 + cc] = (gr < n) ? f2tf(A[(size_t)gr * HD + cc]) : 0u;
    }

    // gather neighbor means directly into sA2
    int c4 = lane * 4;
#pragma unroll 1
    for (int i = 0; i < 8; i++) {
        int lr = wid * 8 + i;
        int gr = row0 + lr;
        float4 acc = make_float4(0.f, 0.f, 0.f, 0.f);
        if (gr < n) {
            int beg = g_rowptr[gr], end = g_rowptr[gr + 1];
            int it = beg;
            for (; it + 4 <= end; it += 4) {
                int n0 = g_col[it], n1 = g_col[it + 1], n2 = g_col[it + 2], n3 = g_col[it + 3];
                float4 v0 = *reinterpret_cast<const float4*>(&A[(size_t)n0 * HD + c4]);
                float4 v1 = *reinterpret_cast<const float4*>(&A[(size_t)n1 * HD + c4]);
                float4 v2 = *reinterpret_cast<const float4*>(&A[(size_t)n2 * HD + c4]);
                float4 v3 = *reinterpret_cast<const float4*>(&A[(size_t)n3 * HD + c4]);
                acc.x += v0.x + v1.x + v2.x + v3.x;
                acc.y += v0.y + v1.y + v2.y + v3.y;
                acc.z += v0.z + v1.z + v2.z + v3.z;
                acc.w += v0.w + v1.w + v2.w + v3.w;
            }
            for (; it < end; it++) {
                int nb = g_col[it];
                float4 v = *reinterpret_cast<const float4*>(&A[(size_t)nb * HD + c4]);
                acc.x += v.x; acc.y += v.y; acc.z += v.z; acc.w += v.w;
            }
            float sc = g_invdeg[gr];
            acc.x *= sc; acc.y *= sc; acc.z *= sc; acc.w *= sc;
        }
        sA2[lr * 132 + c4 + 0] = f2tf(acc.x);
        sA2[lr * 132 + c4 + 1] = f2tf(acc.y);
        sA2[lr * 132 + c4 + 2] = f2tf(acc.z);
        sA2[lr * 132 + c4 + 3] = f2tf(acc.w);
    }
    __syncthreads();

    int tg = lane & 3, gid = lane >> 2;
    int nt0 = wid * 2;

    float acc[4][8];
#pragma unroll
    for (int s = 0; s < 4; s++)
#pragma unroll
        for (int j = 0; j < 8; j++) acc[s][j] = 0.f;

    const uint2* B0 = reinterpret_cast<const uint2*>(pW0) + (nt0 * 32 + lane);
    const uint2* B1 = reinterpret_cast<const uint2*>(pW1) + (nt0 * 32 + lane);

#pragma unroll 4
    for (int ks = 0; ks < 16; ks++) {
        uint2 b0 = __ldg(B0 + ks * 512);
        uint2 b1 = __ldg(B0 + ks * 512 + 32);
        uint2 d0 = __ldg(B1 + ks * 512);
        uint2 d1 = __ldg(B1 + ks * 512 + 32);
        int ca = ks * 8 + tg;
#pragma unroll
        for (int s = 0; s < 4; s++) {
            int rb = (s * 16 + gid) * 132;
            uint32_t a0 = sA[rb + ca];
            uint32_t a1 = sA[rb + 8 * 132 + ca];
            uint32_t a2 = sA[rb + ca + 4];
            uint32_t a3 = sA[rb + 8 * 132 + ca + 4];
            MMA8(acc[s], a0, a1, a2, a3, b0.x, b0.y);
            MMA8(acc[s] + 4, a0, a1, a2, a3, b1.x, b1.y);
            uint32_t e0 = sA2[rb + ca];
            uint32_t e1 = sA2[rb + 8 * 132 + ca];
            uint32_t e2 = sA2[rb + ca + 4];
            uint32_t e3 = sA2[rb + 8 * 132 + ca + 4];
            MMA8(acc[s], e0, e1, e2, e3, d0.x, d0.y);
            MMA8(acc[s] + 4, e0, e1, e2, e3, d1.x, d1.y);
        }
    }

    int cbase = wid * 16;
    float bb[4];
    bb[0] = __ldg(&bias[cbase + 2 * tg]);
    bb[1] = __ldg(&bias[cbase + 2 * tg + 1]);
    bb[2] = __ldg(&bias[cbase + 8 + 2 * tg]);
    bb[3] = __ldg(&bias[cbase + 8 + 2 * tg + 1]);
#pragma unroll
    for (int s = 0; s < 4; s++) {
#pragma unroll
        for (int t = 0; t < 2; t++) {
            int col = cbase + t * 8 + 2 * tg;
            int r = row0 + s * 16 + gid;
            float v0 = acc[s][t * 4 + 0] + bb[t * 2 + 0];
            float v1 = acc[s][t * 4 + 1] + bb[t * 2 + 1];
            float v2 = acc[s][t * 4 + 2] + bb[t * 2 + 0];
            float v3 = acc[s][t * 4 + 3] + bb[t * 2 + 1];
            if (relu) {
                v0 = fmaxf(v0, 0.f); v1 = fmaxf(v1, 0.f);
                v2 = fmaxf(v2, 0.f); v3 = fmaxf(v3, 0.f);
            }
            if (r < n)
                *reinterpret_cast<float2*>(&C[(size_t)r * HD + col]) = make_float2(v0, v1);
            if (r + 8 < n)
                *reinterpret_cast<float2*>(&C[(size_t)(r + 8) * HD + col]) = make_float2(v2, v3);
        }
    }
}

// ---------------- GEMM (dual-C): C0 = op(A@W0+b0), C1 = op(A@W1+b1), one A staging ----------------
// HALFOUT: write __half2 (pair tables); else float2.
template <bool HALFOUT>
__global__ void __launch_bounds__(256) k_gemm_dualC(
    const float* __restrict__ A,
    const uint32_t* __restrict__ pW0, const uint32_t* __restrict__ pW1,
    const float* __restrict__ bias0, const float* __restrict__ bias1,
    void* __restrict__ C0v, void* __restrict__ C1v, int cstride, int n, int relu)
{
    extern __shared__ uint32_t sm[];
    uint32_t* sA = sm;

    int tid = threadIdx.x;
    int row0 = blockIdx.x * 64;
    for (int idx = tid; idx < 8192; idx += 256) {
        int r = idx >> 7, cc = idx & 127;
        int gr = row0 + r;
        sA[r * 132 + cc] = (gr < n) ? f2tf(A[(size_t)gr * HD + cc]) : 0u;
    }
    __syncthreads();

    int wid = tid >> 5, lane = tid & 31;
    int tg = lane & 3, gid = lane >> 2;
    int nt0 = wid * 2;

    float acc0[4][8], acc1[4][8];
#pragma unroll
    for (int s = 0; s < 4; s++)
#pragma unroll
        for (int j = 0; j < 8; j++) { acc0[s][j] = 0.f; acc1[s][j] = 0.f; }

    const uint2* B0 = reinterpret_cast<const uint2*>(pW0) + (nt0 * 32 + lane);
    const uint2* B1 = reinterpret_cast<const uint2*>(pW1) + (nt0 * 32 + lane);

#pragma unroll 4
    for (int ks = 0; ks < 16; ks++) {
        uint2 b0 = __ldg(B0 + ks * 512);
        uint2 b1 = __ldg(B0 + ks * 512 + 32);
        uint2 d0 = __ldg(B1 + ks * 512);
        uint2 d1 = __ldg(B1 + ks * 512 + 32);
        int ca = ks * 8 + tg;
#pragma unroll
        for (int s = 0; s < 4; s++) {
            int rb = (s * 16 + gid) * 132;
            uint32_t a0 = sA[rb + ca];
            uint32_t a1 = sA[rb + 8 * 132 + ca];
            uint32_t a2 = sA[rb + ca + 4];
            uint32_t a3 = sA[rb + 8 * 132 + ca + 4];
            MMA8(acc0[s], a0, a1, a2, a3, b0.x, b0.y);
            MMA8(acc0[s] + 4, a0, a1, a2, a3, b1.x, b1.y);
            MMA8(acc1[s], a0, a1, a2, a3, d0.x, d0.y);
            MMA8(acc1[s] + 4, a0, a1, a2, a3, d1.x, d1.y);
        }
    }

    int cbase = wid * 16;
    float bb0[4] = {0.f, 0.f, 0.f, 0.f}, bb1[4] = {0.f, 0.f, 0.f, 0.f};
    if (bias0) {
        bb0[0] = __ldg(&bias0[cbase + 2 * tg]);
        bb0[1] = __ldg(&bias0[cbase + 2 * tg + 1]);
        bb0[2] = __ldg(&bias0[cbase + 8 + 2 * tg]);
        bb0[3] = __ldg(&bias0[cbase + 8 + 2 * tg + 1]);
    }
    if (bias1) {
        bb1[0] = __ldg(&bias1[cbase + 2 * tg]);
        bb1[1] = __ldg(&bias1[cbase + 2 * tg + 1]);
        bb1[2] = __ldg(&bias1[cbase + 8 + 2 * tg]);
        bb1[3] = __ldg(&bias1[cbase + 8 + 2 * tg + 1]);
    }
#pragma unroll
    for (int s = 0; s < 4; s++) {
#pragma unroll
        for (int t = 0; t < 2; t++) {
            int col = cbase + t * 8 + 2 * tg;
            int r = row0 + s * 16 + gid;
            float u0 = acc0[s][t * 4 + 0] + bb0[t * 2 + 0];
            float u1 = acc0[s][t * 4 + 1] + bb0[t * 2 + 1];
            float u2 = acc0[s][t * 4 + 2] + bb0[t * 2 + 0];
            float u3 = acc0[s][t * 4 + 3] + bb0[t * 2 + 1];
            float v0 = acc1[s][t * 4 + 0] + bb1[t * 2 + 0];
            float v1 = acc1[s][t * 4 + 1] + bb1[t * 2 + 1];
            float v2 = acc1[s][t * 4 + 2] + bb1[t * 2 + 0];
            float v3 = acc1[s][t * 4 + 3] + bb1[t * 2 + 1];
            if (relu) {
                u0 = fmaxf(u0, 0.f); u1 = fmaxf(u1, 0.f);
                u2 = fmaxf(u2, 0.f); u3 = fmaxf(u3, 0.f);
                v0 = fmaxf(v0, 0.f); v1 = fmaxf(v1, 0.f);
                v2 = fmaxf(v2, 0.f); v3 = fmaxf(v3, 0.f);
            }
            if (HALFOUT) {
                __half* C0 = (__half*)C0v;
                __half* C1 = (__half*)C1v;
                if (r < n) {
                    *reinterpret_cast<__half2*>(&C0[(size_t)r * cstride + col]) = __floats2half2_rn(u0, u1);
                    *reinterpret_cast<__half2*>(&C1[(size_t)r * cstride + col]) = __floats2half2_rn(v0, v1);
                }
                if (r + 8 < n) {
                    *reinterpret_cast<__half2*>(&C0[(size_t)(r + 8) * cstride + col]) = __floats2half2_rn(u2, u3);
                    *reinterpret_cast<__half2*>(&C1[(size_t)(r + 8) * cstride + col]) = __floats2half2_rn(v2, v3);
                }
            } else {
                float* C0 = (float*)C0v;
                float* C1 = (float*)C1v;
                if (r < n) {
                    *reinterpret_cast<float2*>(&C0[(size_t)r * cstride + col]) = make_float2(u0, u1);
                    *reinterpret_cast<float2*>(&C1[(size_t)r * cstride + col]) = make_float2(v0, v1);
                }
                if (r + 8 < n) {
                    *reinterpret_cast<float2*>(&C0[(size_t)(r + 8) * cstride + col]) = make_float2(u2, u3);
                    *reinterpret_cast<float2*>(&C1[(size_t)(r + 8) * cstride + col]) = make_float2(v2, v3);
                }
            }
        }
    }
}

// ---------------- node-head second stage: out = hidden . W2 + b2 (two heads) ----------------
__global__ void k_headreduce(const float* __restrict__ ha, const float* __restrict__ w2a,
                             const float* __restrict__ b2a,
                             const float* __restrict__ hb, const float* __restrict__ w2b,
                             const float* __restrict__ b2b,
                             float* __restrict__ pa, float* __restrict__ pb, int n)
{
    __shared__ float swa[128], swb[128];
    int tid = threadIdx.x;
    if (tid < 128) { swa[tid] = w2a[tid]; swb[tid] = w2b[tid]; }
    __syncthreads();
    int node = (blockIdx.x * blockDim.x + tid) >> 5;
    int lane = tid & 31;
    if (node >= n) return;
    float4 va = *reinterpret_cast<const float4*>(&ha[(size_t)node * HD + lane * 4]);
    float4 wa = *reinterpret_cast<const float4*>(&swa[lane * 4]);
    float sa = va.x * wa.x + va.y * wa.y + va.z * wa.z + va.w * wa.w;
    float4 vb = *reinterpret_cast<const float4*>(&hb[(size_t)node * HD + lane * 4]);
    float4 wb = *reinterpret_cast<const float4*>(&swb[lane * 4]);
    float sb = vb.x * wb.x + vb.y * wb.y + vb.z * wb.z + vb.w * wb.w;
#pragma unroll
    for (int off = 16; off; off >>= 1) {
        sa += __shfl_xor_sync(0xffffffffu, sa, off);
        sb += __shfl_xor_sync(0xffffffffu, sb, off);
    }
    if (lane == 0) {
        pa[node] = sa + __ldg(&b2a[0]);
        pb[node] = sb + __ldg(&b2b[0]);
    }
}

// ---------------- edge heads: one warp per edge, fp16 pair tables ----------------
__global__ void k_edge(const int* __restrict__ ei,
                       const float* __restrict__ estat, const float* __restrict__ qobs,
                       const int* __restrict__ qmask,
                       const float* __restrict__ erW1, const float* __restrict__ erb1,
                       const float* __restrict__ erW2, const float* __restrict__ erb2,
                       const float* __restrict__ eaW1, const float* __restrict__ eab1,
                       const float* __restrict__ eaW2, const float* __restrict__ eab2,
                       float* __restrict__ qhat, float* __restrict__ elog, int ne)
{
    __shared__ float sE[2][8 * HD];  // per head: rows 0-5 = W1[256+r], 6 = b1, 7 = W2
    int tid = threadIdx.x;
    for (int idx = tid; idx < 2 * 8 * HD; idx += blockDim.x) {
        int h = idx / (8 * HD);
        int rem = idx - h * 8 * HD;
        int r = rem >> 7, c = rem & 127;
        const float* W1 = h ? eaW1 : erW1;
        const float* b1 = h ? eab1 : erb1;
        const float* W2 = h ? eaW2 : erW2;
        float v;
        if (r < 6) v = W1[(256 + r) * HD + c];
        else if (r == 6) v = b1[c];
        else v = W2[c];
        sE[h][rem] = v;
    }
    __syncthreads();

    int w = (blockIdx.x * blockDim.x + tid) >> 5;
    int lane = tid & 31;
    if (w >= ne) return;
    int s = ei[w], d = ei[ne + w];
    float e0 = estat[w * 4 + 0], e1 = estat[w * 4 + 1];
    float e2 = estat[w * 4 + 2], e3 = estat[w * 4 + 3];
    float qo = qobs[w], qm = (float)qmask[w];
    int c = lane * 4;

    const __half* srcA = &g_pairAh[(size_t)s * 256];
    const __half* dstB = &g_pairBh[(size_t)d * 256];

#pragma unroll
    for (int h = 0; h < 2; h++) {
        const float* S = sE[h];
        int off = h * 128 + c;
        uint2 ua = *reinterpret_cast<const uint2*>(&srcA[off]);
        uint2 ub = *reinterpret_cast<const uint2*>(&dstB[off]);
        const __half2* pa = reinterpret_cast<const __half2*>(&ua);
        const __half2* pb = reinterpret_cast<const __half2*>(&ub);
        float2 a01 = __half22float2(pa[0]), a23 = __half22float2(pa[1]);
        float2 b01 = __half22float2(pb[0]), b23 = __half22float2(pb[1]);
        float av[4] = {a01.x, a01.y, a23.x, a23.y};
        float bv[4] = {b01.x, b01.y, b23.x, b23.y};
        float acc = 0.f;
#pragma unroll
        for (int t = 0; t < 4; t++) {
            int cc = c + t;
            float hv = av[t] + bv[t] + e0 * S[cc] + e1 * S[HD + cc] + e2 * S[2 * HD + cc]
                     + e3 * S[3 * HD + cc] + qo * S[4 * HD + cc] + qm * S[5 * HD + cc]
                     + S[6 * HD + cc];
            hv = fmaxf(hv, 0.f);
            acc += hv * S[7 * HD + cc];
        }
#pragma unroll
        for (int off2 = 16; off2; off2 >>= 1) acc += __shfl_xor_sync(0xffffffffu, acc, off2);
        if (lane == 0) {
            if (h == 0) qhat[w] = acc + __ldg(&erb2[0]);
            else        elog[w] = acc + __ldg(&eab2[0]);
        }
    }
}

// ---------------- launch ----------------
extern "C" void kernel_launch(void* const* d_in, const int* in_sizes, int n_in,
                              void* d_out, int out_size)
{
    const int*   ei           = (const int*)d_in[0];   // edge_index is int32 (jax x64 disabled)
    const float* node_static  = (const float*)d_in[1];
    const float* edge_static  = (const float*)d_in[2];
    const float* p_obs        = (const float*)d_in[3];
    const float* q_obs        = (const float*)d_in[4];
    const int*   p_mask       = (const int*)d_in[5];
    const int*   q_mask       = (const int*)d_in[6];
    const float* W_enc        = (const float*)d_in[7];
    const float* b_enc        = (const float*)d_in[8];
    const float* W_self       = (const float*)d_in[9];
    const float* W_neigh      = (const float*)d_in[10];
    const float* b_gnn        = (const float*)d_in[11];
    const float* nrW1 = (const float*)d_in[12]; const float* nrb1 = (const float*)d_in[13];
    const float* nrW2 = (const float*)d_in[14]; const float* nrb2 = (const float*)d_in[15];
    const float* naW1 = (const float*)d_in[16]; const float* nab1 = (const float*)d_in[17];
    const float* naW2 = (const float*)d_in[18]; const float* nab2 = (const float*)d_in[19];
    const float* erW1 = (const float*)d_in[20]; const float* erb1 = (const float*)d_in[21];
    const float* erW2 = (const float*)d_in[22]; const float* erb2 = (const float*)d_in[23];
    const float* eaW1 = (const float*)d_in[24]; const float* eab1 = (const float*)d_in[25];
    const float* eaW2 = (const float*)d_in[26]; const float* eab2 = (const float*)d_in[27];

    int n  = in_sizes[3];  // N (p_obs)
    int ne = in_sizes[4];  // E (q_obs)

    float* out   = (float*)d_out;
    float* p_hat = out;
    float* q_hat = out + n;
    float* nlog  = out + n + ne;
    float* elog  = out + 2 * n + ne;

    float *gx, *gy, *gagg;
    __half *gpa, *gpb;
    uint32_t* gpw;
    cudaGetSymbolAddress((void**)&gx,   g_x);
    cudaGetSymbolAddress((void**)&gy,   g_y);
    cudaGetSymbolAddress((void**)&gagg, g_agg);
    cudaGetSymbolAddress((void**)&gpa,  g_pairAh);
    cudaGetSymbolAddress((void**)&gpb,  g_pairBh);
    cudaGetSymbolAddress((void**)&gpw,  g_pw);

    const int SM_LAYER = 2 * 8448 * 4;  // 67584 B
    const int SM_ONEA  = 8448 * 4;      // 33792 B
    cudaFuncSetAttribute(k_gemm_layer, cudaFuncAttributeMaxDynamicSharedMemorySize, SM_LAYER);
    cudaFuncSetAttribute(k_gemm_dualC<true>,  cudaFuncAttributeMaxDynamicSharedMemorySize, SM_ONEA);
    cudaFuncSetAttribute(k_gemm_dualC<false>, cudaFuncAttributeMaxDynamicSharedMemorySize, SM_ONEA);

    // pre-pack the 12 weight matrices: 0-2 Wself[l], 3-5 Wneigh[l], 6 nrW1, 7 naW1,
    // 8 erW1 top, 9 erW1 bot, 10 eaW1 top, 11 eaW1 bot
    PackSrc ps;
    ps.s[0] = W_self;                ps.s[1] = W_self + 16384;  ps.s[2] = W_self + 32768;
    ps.s[3] = W_neigh;               ps.s[4] = W_neigh + 16384; ps.s[5] = W_neigh + 32768;
    ps.s[6] = nrW1;                  ps.s[7] = naW1;
    ps.s[8] = erW1;                  ps.s[9] = erW1 + 16384;
    ps.s[10] = eaW1;                 ps.s[11] = eaW1 + 16384;
    k_pack<<<(12 * 16384 + 255) / 256, 256>>>(ps);

    k_encoder<<<(n * HD + 255) / 256, 256>>>(node_static, p_obs, p_mask, W_enc, b_enc, gx, n);
    k_zero_deg<<<(n + 255) / 256, 256>>>(n);
    k_deg<<<(ne + 255) / 256, 256>>>(ei, ne);
    int nb = (n + 1023) / 1024;
    k_scan_local<<<nb, 1024>>>(n);
    k_scan_bsum<<<1, 32>>>(nb);
    k_scan_final<<<(n + 255) / 256, 256>>>(n);
    k_fill<<<(ne + 255) / 256, 256>>>(ei, ne);

    int gblocks = (n + 63) / 64;
    const float* xin = gx;
    float* xout = gy;
    for (int l = 0; l < 3; l++) {
        k_gemm_layer<<<gblocks, 256, SM_LAYER>>>(xin,
                                                 gpw + l * 16384, gpw + (3 + l) * 16384,
                                                 b_gnn + l * HD, xout, n, (l < 2) ? 1 : 0);
        const float* t = xin;
        xin = xout;
        xout = (float*)t;
    }
    const float* xf = xin;  // final node embeddings (g_y); g_x and g_agg now free

    // node heads: hidden = relu(xf@W1+b1) into g_x / g_agg (fp32), then warp-reduce with W2
    k_gemm_dualC<false><<<gblocks, 256, SM_ONEA>>>(xf, gpw + 6 * 16384, gpw + 7 * 16384,
                                                   nrb1, nab1, gx, gagg, HD, n, 1);
    k_headreduce<<<(n * 32 + 255) / 256, 256>>>(gx, nrW2, nrb2, gagg, naW2, nab2, p_hat, nlog, n);

    // edge-head per-node precompute (interleaved fp16): er -> cols [0,128), ea -> cols [128,256)
    k_gemm_dualC<true><<<gblocks, 256, SM_ONEA>>>(xf, gpw + 8 * 16384, gpw + 9 * 16384,
                                                  nullptr, nullptr, gpa, gpb, 256, n, 0);
    k_gemm_dualC<true><<<gblocks, 256, SM_ONEA>>>(xf, gpw + 10 * 16384, gpw + 11 * 16384,
                                                  nullptr, nullptr, gpa + 128, gpb + 128, 256, n, 0);

    k_edge<<<(ne * 32 + 255) / 256, 256>>>(ei, edge_static, q_obs, q_mask,
                                           erW1, erb1, erW2, erb2,
                                           eaW1, eab1, eaW2, eab2,
                                           q_hat, elog, ne);
}

// round 11
// speedup vs baseline: 1.0335x; 1.0335x over previous
#include <cuda_runtime.h>
#include <cuda_fp16.h>
#include <cstdint>

#define NN 100000
#define NE 600000
#define HD 128

// ---------------- scratch (static device memory; no allocs) ----------------
static __device__ float  g_x  [NN * HD];
static __device__ float  g_y  [NN * HD];
static __device__ float  g_agg[NN * HD];
static __device__ __half g_pairAh[NN * 256];      // [node][0:128)=er A-part, [128:256)=ea A-part
static __device__ __half g_pairBh[NN * 256];      // [node][0:128)=er B-part, [128:256)=ea B-part
static __device__ int    g_deg[NN];
static __device__ int    g_rowptr[NN + 1];
static __device__ int    g_cursor[NN];
static __device__ int    g_col[2 * NE];
static __device__ float  g_invdeg[NN];
static __device__ int    g_tmp[NN];
static __device__ int    g_bsum[128];
static __device__ uint32_t g_pw[12 * 16384];      // packed tf32 weights, fragment order

// ---------------- tf32 helpers ----------------
__device__ __forceinline__ uint32_t f2tf(float f)
{
    uint32_t r;
    asm("cvt.rna.tf32.f32 %0, %1;" : "=r"(r) : "f"(f));
    return r;
}

#define MMA8(c, a0, a1, a2, a3, b0, b1)                                     \
    asm volatile("mma.sync.aligned.m16n8k8.row.col.f32.tf32.tf32.f32 "      \
                 "{%0,%1,%2,%3},{%4,%5,%6,%7},{%8,%9},{%0,%1,%2,%3};"       \
                 : "+f"((c)[0]), "+f"((c)[1]), "+f"((c)[2]), "+f"((c)[3])   \
                 : "r"(a0), "r"(a1), "r"(a2), "r"(a3), "r"(b0), "r"(b1))

// ---------------- weight pre-pack: 12 matrices of 128x128 into fragment order ----------------
struct PackSrc { const float* s[12]; };

__global__ void k_pack(PackSrc ps)
{
    int idx = blockIdx.x * 256 + threadIdx.x;
    if (idx >= 12 * 16384) return;
    int m = idx >> 14, e = idx & 16383;
    int k = e >> 7, nn2 = e & 127;
    int kstep = k >> 3, kin = k & 7, ntile = nn2 >> 3, nin = nn2 & 7;
    int lane = (nin << 2) | (kin & 3);
    int dest = (((kstep << 4) + ntile) << 6) + (lane << 1) + (kin >> 2);
    g_pw[m * 16384 + dest] = f2tf(__ldg(&ps.s[m][e]));
}

// ---------------- encoder: x = node_feats(8) @ W_enc + b_enc ----------------
__global__ void k_encoder(const float* __restrict__ ns, const float* __restrict__ pobs,
                          const int* __restrict__ pmask, const float* __restrict__ Wenc,
                          const float* __restrict__ benc, float* __restrict__ x, int n)
{
    __shared__ float sW[8 * HD];
    __shared__ float sb[HD];
    for (int i = threadIdx.x; i < 8 * HD; i += blockDim.x) sW[i] = Wenc[i];
    for (int i = threadIdx.x; i < HD; i += blockDim.x) sb[i] = benc[i];
    __syncthreads();
    int idx = blockIdx.x * blockDim.x + threadIdx.x;
    if (idx >= n * HD) return;
    int node = idx >> 7, h = idx & 127;
    float f0 = ns[node * 6 + 0], f1 = ns[node * 6 + 1], f2 = ns[node * 6 + 2];
    float f3 = ns[node * 6 + 3], f4 = ns[node * 6 + 4], f5 = ns[node * 6 + 5];
    float f6 = pobs[node];
    float f7 = (float)pmask[node];
    float o = sb[h];
    o += f0 * sW[0 * HD + h] + f1 * sW[1 * HD + h] + f2 * sW[2 * HD + h] + f3 * sW[3 * HD + h];
    o += f4 * sW[4 * HD + h] + f5 * sW[5 * HD + h] + f6 * sW[6 * HD + h] + f7 * sW[7 * HD + h];
    x[idx] = o;
}

// ---------------- CSR build ----------------
__global__ void k_zero_deg(int n)
{
    int i = blockIdx.x * blockDim.x + threadIdx.x;
    if (i < n) g_deg[i] = 0;
}

__global__ void k_deg(const int* __restrict__ ei, int ne)
{
    int e = blockIdx.x * blockDim.x + threadIdx.x;
    if (e >= ne) return;
    int s = ei[e], d = ei[ne + e];
    atomicAdd(&g_deg[s], 1);
    atomicAdd(&g_deg[d], 1);
}

__global__ void k_scan_local(int n)
{
    __shared__ int sh[1024];
    int t = threadIdx.x;
    int i = blockIdx.x * 1024 + t;
    int v = (i < n) ? g_deg[i] : 0;
    sh[t] = v;
    __syncthreads();
    for (int off = 1; off < 1024; off <<= 1) {
        int tv = (t >= off) ? sh[t - off] : 0;
        __syncthreads();
        sh[t] += tv;
        __syncthreads();
    }
    if (i < n) g_tmp[i] = sh[t];
    if (t == 1023) g_bsum[blockIdx.x] = sh[1023];
}

__global__ void k_scan_bsum(int nb)
{
    if (threadIdx.x == 0) {
        int acc = 0;
        for (int b = 0; b < nb; b++) { int tv = g_bsum[b]; g_bsum[b] = acc; acc += tv; }
    }
}

__global__ void k_scan_final(int n)
{
    int i = blockIdx.x * blockDim.x + threadIdx.x;
    if (i >= n) return;
    int incl = g_tmp[i] + g_bsum[i >> 10];
    g_rowptr[i + 1] = incl;
    int d = g_deg[i];
    g_cursor[i] = incl - d;
    g_invdeg[i] = 1.0f / (float)(d > 0 ? d : 1);
    if (i == 0) g_rowptr[0] = 0;
}

__global__ void k_fill(const int* __restrict__ ei, int ne)
{
    int e = blockIdx.x * blockDim.x + threadIdx.x;
    if (e >= ne) return;
    int s = ei[e], d = ei[ne + e];
    int p = atomicAdd(&g_cursor[d], 1);
    g_col[p] = s;
    int q = atomicAdd(&g_cursor[s], 1);
    g_col[q] = d;
}

// ---------------- mean aggregation: one warp per node, x4 unrolled (MLP=4) ----------------
__global__ void k_agg(const float* __restrict__ x, float* __restrict__ agg, int n)
{
    int w = (blockIdx.x * blockDim.x + threadIdx.x) >> 5;
    int lane = threadIdx.x & 31;
    if (w >= n) return;
    int beg = g_rowptr[w], end = g_rowptr[w + 1];
    float4 acc = make_float4(0.f, 0.f, 0.f, 0.f);
    int i = beg;
    int c = lane * 4;
    for (; i + 4 <= end; i += 4) {
        int n0 = g_col[i], n1 = g_col[i + 1], n2 = g_col[i + 2], n3 = g_col[i + 3];
        float4 v0 = *reinterpret_cast<const float4*>(&x[(size_t)n0 * HD + c]);
        float4 v1 = *reinterpret_cast<const float4*>(&x[(size_t)n1 * HD + c]);
        float4 v2 = *reinterpret_cast<const float4*>(&x[(size_t)n2 * HD + c]);
        float4 v3 = *reinterpret_cast<const float4*>(&x[(size_t)n3 * HD + c]);
        acc.x += v0.x + v1.x + v2.x + v3.x;
        acc.y += v0.y + v1.y + v2.y + v3.y;
        acc.z += v0.z + v1.z + v2.z + v3.z;
        acc.w += v0.w + v1.w + v2.w + v3.w;
    }
    for (; i < end; i++) {
        int nb = g_col[i];
        float4 v = *reinterpret_cast<const float4*>(&x[(size_t)nb * HD + c]);
        acc.x += v.x; acc.y += v.y; acc.z += v.z; acc.w += v.w;
    }
    float sc = g_invdeg[w];
    acc.x *= sc; acc.y *= sc; acc.z *= sc; acc.w *= sc;
    *reinterpret_cast<float4*>(&agg[(size_t)w * HD + c]) = acc;
}

// ---------------- GEMM (dual-A): C = op(A@W0 + A2@W1 + bias) ----------------
__global__ void __launch_bounds__(256) k_gemm_dualA(
    const float* __restrict__ A, const float* __restrict__ A2,
    const uint32_t* __restrict__ pW0, const uint32_t* __restrict__ pW1,
    const float* __restrict__ bias, float* __restrict__ C, int n, int relu)
{
    extern __shared__ uint32_t sm[];
    uint32_t* sA  = sm;
    uint32_t* sA2 = sm + 8448;

    int tid = threadIdx.x;
    int row0 = blockIdx.x * 64;
    for (int idx = tid; idx < 8192; idx += 256) {
        int r = idx >> 7, cc = idx & 127;
        int gr = row0 + r;
        bool ok = gr < n;
        sA [r * 132 + cc] = ok ? f2tf(A [(size_t)gr * HD + cc]) : 0u;
        sA2[r * 132 + cc] = ok ? f2tf(A2[(size_t)gr * HD + cc]) : 0u;
    }
    __syncthreads();

    int wid = tid >> 5, lane = tid & 31;
    int tg = lane & 3, gid = lane >> 2;
    int nt0 = wid * 2;

    float acc[4][8];
#pragma unroll
    for (int s = 0; s < 4; s++)
#pragma unroll
        for (int j = 0; j < 8; j++) acc[s][j] = 0.f;

    const uint2* B0 = reinterpret_cast<const uint2*>(pW0) + (nt0 * 32 + lane);
    const uint2* B1 = reinterpret_cast<const uint2*>(pW1) + (nt0 * 32 + lane);

#pragma unroll 4
    for (int ks = 0; ks < 16; ks++) {
        uint2 b0 = __ldg(B0 + ks * 512);
        uint2 b1 = __ldg(B0 + ks * 512 + 32);
        uint2 d0 = __ldg(B1 + ks * 512);
        uint2 d1 = __ldg(B1 + ks * 512 + 32);
        int ca = ks * 8 + tg;
#pragma unroll
        for (int s = 0; s < 4; s++) {
            int rb = (s * 16 + gid) * 132;
            uint32_t a0 = sA[rb + ca];
            uint32_t a1 = sA[rb + 8 * 132 + ca];
            uint32_t a2 = sA[rb + ca + 4];
            uint32_t a3 = sA[rb + 8 * 132 + ca + 4];
            MMA8(acc[s], a0, a1, a2, a3, b0.x, b0.y);
            MMA8(acc[s] + 4, a0, a1, a2, a3, b1.x, b1.y);
            uint32_t e0 = sA2[rb + ca];
            uint32_t e1 = sA2[rb + 8 * 132 + ca];
            uint32_t e2 = sA2[rb + ca + 4];
            uint32_t e3 = sA2[rb + 8 * 132 + ca + 4];
            MMA8(acc[s], e0, e1, e2, e3, d0.x, d0.y);
            MMA8(acc[s] + 4, e0, e1, e2, e3, d1.x, d1.y);
        }
    }

    int cbase = wid * 16;
    float bb[4];
    bb[0] = __ldg(&bias[cbase + 2 * tg]);
    bb[1] = __ldg(&bias[cbase + 2 * tg + 1]);
    bb[2] = __ldg(&bias[cbase + 8 + 2 * tg]);
    bb[3] = __ldg(&bias[cbase + 8 + 2 * tg + 1]);
#pragma unroll
    for (int s = 0; s < 4; s++) {
#pragma unroll
        for (int t = 0; t < 2; t++) {
            int col = cbase + t * 8 + 2 * tg;
            int r = row0 + s * 16 + gid;
            float v0 = acc[s][t * 4 + 0] + bb[t * 2 + 0];
            float v1 = acc[s][t * 4 + 1] + bb[t * 2 + 1];
            float v2 = acc[s][t * 4 + 2] + bb[t * 2 + 0];
            float v3 = acc[s][t * 4 + 3] + bb[t * 2 + 1];
            if (relu) {
                v0 = fmaxf(v0, 0.f); v1 = fmaxf(v1, 0.f);
                v2 = fmaxf(v2, 0.f); v3 = fmaxf(v3, 0.f);
            }
            if (r < n)
                *reinterpret_cast<float2*>(&C[(size_t)r * HD + col]) = make_float2(v0, v1);
            if (r + 8 < n)
                *reinterpret_cast<float2*>(&C[(size_t)(r + 8) * HD + col]) = make_float2(v2, v3);
        }
    }
}

// ---------------- GEMM (dual-C): C0 = op(A@W0+b0), C1 = op(A@W1+b1), one A staging ----------------
// HALFOUT: write __half2 (pair tables); else float2.
template <bool HALFOUT>
__global__ void __launch_bounds__(256) k_gemm_dualC(
    const float* __restrict__ A,
    const uint32_t* __restrict__ pW0, const uint32_t* __restrict__ pW1,
    const float* __restrict__ bias0, const float* __restrict__ bias1,
    void* __restrict__ C0v, void* __restrict__ C1v, int cstride, int n, int relu)
{
    extern __shared__ uint32_t sm[];
    uint32_t* sA = sm;

    int tid = threadIdx.x;
    int row0 = blockIdx.x * 64;
    for (int idx = tid; idx < 8192; idx += 256) {
        int r = idx >> 7, cc = idx & 127;
        int gr = row0 + r;
        sA[r * 132 + cc] = (gr < n) ? f2tf(A[(size_t)gr * HD + cc]) : 0u;
    }
    __syncthreads();

    int wid = tid >> 5, lane = tid & 31;
    int tg = lane & 3, gid = lane >> 2;
    int nt0 = wid * 2;

    float acc0[4][8], acc1[4][8];
#pragma unroll
    for (int s = 0; s < 4; s++)
#pragma unroll
        for (int j = 0; j < 8; j++) { acc0[s][j] = 0.f; acc1[s][j] = 0.f; }

    const uint2* B0 = reinterpret_cast<const uint2*>(pW0) + (nt0 * 32 + lane);
    const uint2* B1 = reinterpret_cast<const uint2*>(pW1) + (nt0 * 32 + lane);

#pragma unroll 4
    for (int ks = 0; ks < 16; ks++) {
        uint2 b0 = __ldg(B0 + ks * 512);
        uint2 b1 = __ldg(B0 + ks * 512 + 32);
        uint2 d0 = __ldg(B1 + ks * 512);
        uint2 d1 = __ldg(B1 + ks * 512 + 32);
        int ca = ks * 8 + tg;
#pragma unroll
        for (int s = 0; s < 4; s++) {
            int rb = (s * 16 + gid) * 132;
            uint32_t a0 = sA[rb + ca];
            uint32_t a1 = sA[rb + 8 * 132 + ca];
            uint32_t a2 = sA[rb + ca + 4];
            uint32_t a3 = sA[rb + 8 * 132 + ca + 4];
            MMA8(acc0[s], a0, a1, a2, a3, b0.x, b0.y);
            MMA8(acc0[s] + 4, a0, a1, a2, a3, b1.x, b1.y);
            MMA8(acc1[s], a0, a1, a2, a3, d0.x, d0.y);
            MMA8(acc1[s] + 4, a0, a1, a2, a3, d1.x, d1.y);
        }
    }

    int cbase = wid * 16;
    float bb0[4] = {0.f, 0.f, 0.f, 0.f}, bb1[4] = {0.f, 0.f, 0.f, 0.f};
    if (bias0) {
        bb0[0] = __ldg(&bias0[cbase + 2 * tg]);
        bb0[1] = __ldg(&bias0[cbase + 2 * tg + 1]);
        bb0[2] = __ldg(&bias0[cbase + 8 + 2 * tg]);
        bb0[3] = __ldg(&bias0[cbase + 8 + 2 * tg + 1]);
    }
    if (bias1) {
        bb1[0] = __ldg(&bias1[cbase + 2 * tg]);
        bb1[1] = __ldg(&bias1[cbase + 2 * tg + 1]);
        bb1[2] = __ldg(&bias1[cbase + 8 + 2 * tg]);
        bb1[3] = __ldg(&bias1[cbase + 8 + 2 * tg + 1]);
    }
#pragma unroll
    for (int s = 0; s < 4; s++) {
#pragma unroll
        for (int t = 0; t < 2; t++) {
            int col = cbase + t * 8 + 2 * tg;
            int r = row0 + s * 16 + gid;
            float u0 = acc0[s][t * 4 + 0] + bb0[t * 2 + 0];
            float u1 = acc0[s][t * 4 + 1] + bb0[t * 2 + 1];
            float u2 = acc0[s][t * 4 + 2] + bb0[t * 2 + 0];
            float u3 = acc0[s][t * 4 + 3] + bb0[t * 2 + 1];
            float v0 = acc1[s][t * 4 + 0] + bb1[t * 2 + 0];
            float v1 = acc1[s][t * 4 + 1] + bb1[t * 2 + 1];
            float v2 = acc1[s][t * 4 + 2] + bb1[t * 2 + 0];
            float v3 = acc1[s][t * 4 + 3] + bb1[t * 2 + 1];
            if (relu) {
                u0 = fmaxf(u0, 0.f); u1 = fmaxf(u1, 0.f);
                u2 = fmaxf(u2, 0.f); u3 = fmaxf(u3, 0.f);
                v0 = fmaxf(v0, 0.f); v1 = fmaxf(v1, 0.f);
                v2 = fmaxf(v2, 0.f); v3 = fmaxf(v3, 0.f);
            }
            if (HALFOUT) {
                __half* C0 = (__half*)C0v;
                __half* C1 = (__half*)C1v;
                if (r < n) {
                    *reinterpret_cast<__half2*>(&C0[(size_t)r * cstride + col]) = __floats2half2_rn(u0, u1);
                    *reinterpret_cast<__half2*>(&C1[(size_t)r * cstride + col]) = __floats2half2_rn(v0, v1);
                }
                if (r + 8 < n) {
                    *reinterpret_cast<__half2*>(&C0[(size_t)(r + 8) * cstride + col]) = __floats2half2_rn(u2, u3);
                    *reinterpret_cast<__half2*>(&C1[(size_t)(r + 8) * cstride + col]) = __floats2half2_rn(v2, v3);
                }
            } else {
                float* C0 = (float*)C0v;
                float* C1 = (float*)C1v;
                if (r < n) {
                    *reinterpret_cast<float2*>(&C0[(size_t)r * cstride + col]) = make_float2(u0, u1);
                    *reinterpret_cast<float2*>(&C1[(size_t)r * cstride + col]) = make_float2(v0, v1);
                }
                if (r + 8 < n) {
                    *reinterpret_cast<float2*>(&C0[(size_t)(r + 8) * cstride + col]) = make_float2(u2, u3);
                    *reinterpret_cast<float2*>(&C1[(size_t)(r + 8) * cstride + col]) = make_float2(v2, v3);
                }
            }
        }
    }
}

// ---------------- node-head second stage: out = hidden . W2 + b2 (two heads) ----------------
__global__ void k_headreduce(const float* __restrict__ ha, const float* __restrict__ w2a,
                             const float* __restrict__ b2a,
                             const float* __restrict__ hb, const float* __restrict__ w2b,
                             const float* __restrict__ b2b,
                             float* __restrict__ pa, float* __restrict__ pb, int n)
{
    __shared__ float swa[128], swb[128];
    int tid = threadIdx.x;
    if (tid < 128) { swa[tid] = w2a[tid]; swb[tid] = w2b[tid]; }
    __syncthreads();
    int node = (blockIdx.x * blockDim.x + tid) >> 5;
    int lane = tid & 31;
    if (node >= n) return;
    float4 va = *reinterpret_cast<const float4*>(&ha[(size_t)node * HD + lane * 4]);
    float4 wa = *reinterpret_cast<const float4*>(&swa[lane * 4]);
    float sa = va.x * wa.x + va.y * wa.y + va.z * wa.z + va.w * wa.w;
    float4 vb = *reinterpret_cast<const float4*>(&hb[(size_t)node * HD + lane * 4]);
    float4 wb = *reinterpret_cast<const float4*>(&swb[lane * 4]);
    float sb = vb.x * wb.x + vb.y * wb.y + vb.z * wb.z + vb.w * wb.w;
#pragma unroll
    for (int off = 16; off; off >>= 1) {
        sa += __shfl_xor_sync(0xffffffffu, sa, off);
        sb += __shfl_xor_sync(0xffffffffu, sb, off);
    }
    if (lane == 0) {
        pa[node] = sa + __ldg(&b2a[0]);
        pb[node] = sb + __ldg(&b2b[0]);
    }
}

// ---------------- edge heads: one warp per edge, fp16 pair tables ----------------
__global__ void k_edge(const int* __restrict__ ei,
                       const float* __restrict__ estat, const float* __restrict__ qobs,
                       const int* __restrict__ qmask,
                       const float* __restrict__ erW1, const float* __restrict__ erb1,
                       const float* __restrict__ erW2, const float* __restrict__ erb2,
                       const float* __restrict__ eaW1, const float* __restrict__ eab1,
                       const float* __restrict__ eaW2, const float* __restrict__ eab2,
                       float* __restrict__ qhat, float* __restrict__ elog, int ne)
{
    __shared__ float sE[2][8 * HD];  // per head: rows 0-5 = W1[256+r], 6 = b1, 7 = W2
    int tid = threadIdx.x;
    for (int idx = tid; idx < 2 * 8 * HD; idx += blockDim.x) {
        int h = idx / (8 * HD);
        int rem = idx - h * 8 * HD;
        int r = rem >> 7, c = rem & 127;
        const float* W1 = h ? eaW1 : erW1;
        const float* b1 = h ? eab1 : erb1;
        const float* W2 = h ? eaW2 : erW2;
        float v;
        if (r < 6) v = W1[(256 + r) * HD + c];
        else if (r == 6) v = b1[c];
        else v = W2[c];
        sE[h][rem] = v;
    }
    __syncthreads();

    int w = (blockIdx.x * blockDim.x + tid) >> 5;
    int lane = tid & 31;
    if (w >= ne) return;
    int s = ei[w], d = ei[ne + w];
    float e0 = estat[w * 4 + 0], e1 = estat[w * 4 + 1];
    float e2 = estat[w * 4 + 2], e3 = estat[w * 4 + 3];
    float qo = qobs[w], qm = (float)qmask[w];
    int c = lane * 4;

    const __half* srcA = &g_pairAh[(size_t)s * 256];
    const __half* dstB = &g_pairBh[(size_t)d * 256];

#pragma unroll
    for (int h = 0; h < 2; h++) {
        const float* S = sE[h];
        int off = h * 128 + c;
        uint2 ua = *reinterpret_cast<const uint2*>(&srcA[off]);
        uint2 ub = *reinterpret_cast<const uint2*>(&dstB[off]);
        const __half2* pa = reinterpret_cast<const __half2*>(&ua);
        const __half2* pb = reinterpret_cast<const __half2*>(&ub);
        float2 a01 = __half22float2(pa[0]), a23 = __half22float2(pa[1]);
        float2 b01 = __half22float2(pb[0]), b23 = __half22float2(pb[1]);
        float av[4] = {a01.x, a01.y, a23.x, a23.y};
        float bv[4] = {b01.x, b01.y, b23.x, b23.y};
        float acc = 0.f;
#pragma unroll
        for (int t = 0; t < 4; t++) {
            int cc = c + t;
            float hv = av[t] + bv[t] + e0 * S[cc] + e1 * S[HD + cc] + e2 * S[2 * HD + cc]
                     + e3 * S[3 * HD + cc] + qo * S[4 * HD + cc] + qm * S[5 * HD + cc]
                     + S[6 * HD + cc];
            hv = fmaxf(hv, 0.f);
            acc += hv * S[7 * HD + cc];
        }
#pragma unroll
        for (int off2 = 16; off2; off2 >>= 1) acc += __shfl_xor_sync(0xffffffffu, acc, off2);
        if (lane == 0) {
            if (h == 0) qhat[w] = acc + __ldg(&erb2[0]);
            else        elog[w] = acc + __ldg(&eab2[0]);
        }
    }
}

// ---------------- launch ----------------
extern "C" void kernel_launch(void* const* d_in, const int* in_sizes, int n_in,
                              void* d_out, int out_size)
{
    const int*   ei           = (const int*)d_in[0];   // edge_index is int32 (jax x64 disabled)
    const float* node_static  = (const float*)d_in[1];
    const float* edge_static  = (const float*)d_in[2];
    const float* p_obs        = (const float*)d_in[3];
    const float* q_obs        = (const float*)d_in[4];
    const int*   p_mask       = (const int*)d_in[5];
    const int*   q_mask       = (const int*)d_in[6];
    const float* W_enc        = (const float*)d_in[7];
    const float* b_enc        = (const float*)d_in[8];
    const float* W_self       = (const float*)d_in[9];
    const float* W_neigh      = (const float*)d_in[10];
    const float* b_gnn        = (const float*)d_in[11];
    const float* nrW1 = (const float*)d_in[12]; const float* nrb1 = (const float*)d_in[13];
    const float* nrW2 = (const float*)d_in[14]; const float* nrb2 = (const float*)d_in[15];
    const float* naW1 = (const float*)d_in[16]; const float* nab1 = (const float*)d_in[17];
    const float* naW2 = (const float*)d_in[18]; const float* nab2 = (const float*)d_in[19];
    const float* erW1 = (const float*)d_in[20]; const float* erb1 = (const float*)d_in[21];
    const float* erW2 = (const float*)d_in[22]; const float* erb2 = (const float*)d_in[23];
    const float* eaW1 = (const float*)d_in[24]; const float* eab1 = (const float*)d_in[25];
    const float* eaW2 = (const float*)d_in[26]; const float* eab2 = (const float*)d_in[27];

    int n  = in_sizes[3];  // N (p_obs)
    int ne = in_sizes[4];  // E (q_obs)

    float* out   = (float*)d_out;
    float* p_hat = out;
    float* q_hat = out + n;
    float* nlog  = out + n + ne;
    float* elog  = out + 2 * n + ne;

    float *gx, *gy, *gagg;
    __half *gpa, *gpb;
    uint32_t* gpw;
    cudaGetSymbolAddress((void**)&gx,   g_x);
    cudaGetSymbolAddress((void**)&gy,   g_y);
    cudaGetSymbolAddress((void**)&gagg, g_agg);
    cudaGetSymbolAddress((void**)&gpa,  g_pairAh);
    cudaGetSymbolAddress((void**)&gpb,  g_pairBh);
    cudaGetSymbolAddress((void**)&gpw,  g_pw);

    const int SM_DUALA = 2 * 8448 * 4;  // 67584 B
    const int SM_ONEA  = 8448 * 4;      // 33792 B
    cudaFuncSetAttribute(k_gemm_dualA, cudaFuncAttributeMaxDynamicSharedMemorySize, SM_DUALA);
    cudaFuncSetAttribute(k_gemm_dualC<true>,  cudaFuncAttributeMaxDynamicSharedMemorySize, SM_ONEA);
    cudaFuncSetAttribute(k_gemm_dualC<false>, cudaFuncAttributeMaxDynamicSharedMemorySize, SM_ONEA);

    // pre-pack the 12 weight matrices: 0-2 Wself[l], 3-5 Wneigh[l], 6 nrW1, 7 naW1,
    // 8 erW1 top, 9 erW1 bot, 10 eaW1 top, 11 eaW1 bot
    PackSrc ps;
    ps.s[0] = W_self;                ps.s[1] = W_self + 16384;  ps.s[2] = W_self + 32768;
    ps.s[3] = W_neigh;               ps.s[4] = W_neigh + 16384; ps.s[5] = W_neigh + 32768;
    ps.s[6] = nrW1;                  ps.s[7] = naW1;
    ps.s[8] = erW1;                  ps.s[9] = erW1 + 16384;
    ps.s[10] = eaW1;                 ps.s[11] = eaW1 + 16384;
    k_pack<<<(12 * 16384 + 255) / 256, 256>>>(ps);

    k_encoder<<<(n * HD + 255) / 256, 256>>>(node_static, p_obs, p_mask, W_enc, b_enc, gx, n);
    k_zero_deg<<<(n + 255) / 256, 256>>>(n);
    k_deg<<<(ne + 255) / 256, 256>>>(ei, ne);
    int nb = (n + 1023) / 1024;
    k_scan_local<<<nb, 1024>>>(n);
    k_scan_bsum<<<1, 32>>>(nb);
    k_scan_final<<<(n + 255) / 256, 256>>>(n);
    k_fill<<<(ne + 255) / 256, 256>>>(ei, ne);

    int gblocks = (n + 63) / 64;
    const float* xin = gx;
    float* xout = gy;
    for (int l = 0; l < 3; l++) {
        k_agg<<<(n * 32 + 255) / 256, 256>>>(xin, gagg, n);
        k_gemm_dualA<<<gblocks, 256, SM_DUALA>>>(xin, gagg,
                                                 gpw + l * 16384, gpw + (3 + l) * 16384,
                                                 b_gnn + l * HD, xout, n, (l < 2) ? 1 : 0);
        const float* t = xin;
        xin = xout;
        xout = (float*)t;
    }
    const float* xf = xin;  // final node embeddings (g_y); g_x and g_agg now free

    // node heads: hidden = relu(xf@W1+b1) into g_x / g_agg (fp32), then warp-reduce with W2
    k_gemm_dualC<false><<<gblocks, 256, SM_ONEA>>>(xf, gpw + 6 * 16384, gpw + 7 * 16384,
                                                   nrb1, nab1, gx, gagg, HD, n, 1);
    k_headreduce<<<(n * 32 + 255) / 256, 256>>>(gx, nrW2, nrb2, gagg, naW2, nab2, p_hat, nlog, n);

    // edge-head per-node precompute (interleaved fp16): er -> cols [0,128), ea -> cols [128,256)
    k_gemm_dualC<true><<<gblocks, 256, SM_ONEA>>>(xf, gpw + 8 * 16384, gpw + 9 * 16384,
                                                  nullptr, nullptr, gpa, gpb, 256, n, 0);
    k_gemm_dualC<true><<<gblocks, 256, SM_ONEA>>>(xf, gpw + 10 * 16384, gpw + 11 * 16384,
                                                  nullptr, nullptr, gpa + 128, gpb + 128, 256, n, 0);

    k_edge<<<(ne * 32 + 255) / 256, 256>>>(ei, edge_static, q_obs, q_mask,
                                           erW1, erb1, erW2, erb2,
                                           eaW1, eab1, eaW2, eab2,
                                           q_hat, elog, ne);
}

// round 12
// speedup vs baseline: 1.1897x; 1.1512x over previous
#include <cuda_runtime.h>
#include <cuda_fp16.h>
#include <cstdint>

#define NN 100000
#define NE 600000
#define HD 128
#define EPW 16   // edges per warp in k_edge

// ---------------- scratch (static device memory; no allocs) ----------------
static __device__ float  g_x  [NN * HD];
static __device__ float  g_y  [NN * HD];
static __device__ float  g_agg[NN * HD];
static __device__ __half g_pairAh[NN * 256];      // [node][0:128)=er A-part, [128:256)=ea A-part
static __device__ __half g_pairBh[NN * 256];      // [node][0:128)=er B-part, [128:256)=ea B-part
static __device__ int    g_deg[NN];
static __device__ int    g_rowptr[NN + 1];
static __device__ int    g_cursor[NN];
static __device__ int    g_col[2 * NE];
static __device__ float  g_invdeg[NN];
static __device__ int    g_tmp[NN];
static __device__ int    g_bsum[128];
static __device__ uint32_t g_pw[12 * 16384];      // packed tf32 weights, fragment order

// ---------------- tf32 helpers ----------------
__device__ __forceinline__ uint32_t f2tf(float f)
{
    uint32_t r;
    asm("cvt.rna.tf32.f32 %0, %1;" : "=r"(r) : "f"(f));
    return r;
}

#define MMA8(c, a0, a1, a2, a3, b0, b1)                                     \
    asm volatile("mma.sync.aligned.m16n8k8.row.col.f32.tf32.tf32.f32 "      \
                 "{%0,%1,%2,%3},{%4,%5,%6,%7},{%8,%9},{%0,%1,%2,%3};"       \
                 : "+f"((c)[0]), "+f"((c)[1]), "+f"((c)[2]), "+f"((c)[3])   \
                 : "r"(a0), "r"(a1), "r"(a2), "r"(a3), "r"(b0), "r"(b1))

// ---------------- weight pre-pack: 12 matrices of 128x128 into fragment order ----------------
struct PackSrc { const float* s[12]; };

__global__ void k_pack(PackSrc ps)
{
    int idx = blockIdx.x * 256 + threadIdx.x;
    if (idx >= 12 * 16384) return;
    int m = idx >> 14, e = idx & 16383;
    int k = e >> 7, nn2 = e & 127;
    int kstep = k >> 3, kin = k & 7, ntile = nn2 >> 3, nin = nn2 & 7;
    int lane = (nin << 2) | (kin & 3);
    int dest = (((kstep << 4) + ntile) << 6) + (lane << 1) + (kin >> 2);
    g_pw[m * 16384 + dest] = f2tf(__ldg(&ps.s[m][e]));
}

// ---------------- encoder: x = node_feats(8) @ W_enc + b_enc ----------------
__global__ void k_encoder(const float* __restrict__ ns, const float* __restrict__ pobs,
                          const int* __restrict__ pmask, const float* __restrict__ Wenc,
                          const float* __restrict__ benc, float* __restrict__ x, int n)
{
    __shared__ float sW[8 * HD];
    __shared__ float sb[HD];
    for (int i = threadIdx.x; i < 8 * HD; i += blockDim.x) sW[i] = Wenc[i];
    for (int i = threadIdx.x; i < HD; i += blockDim.x) sb[i] = benc[i];
    __syncthreads();
    int idx = blockIdx.x * blockDim.x + threadIdx.x;
    if (idx >= n * HD) return;
    int node = idx >> 7, h = idx & 127;
    float f0 = ns[node * 6 + 0], f1 = ns[node * 6 + 1], f2 = ns[node * 6 + 2];
    float f3 = ns[node * 6 + 3], f4 = ns[node * 6 + 4], f5 = ns[node * 6 + 5];
    float f6 = pobs[node];
    float f7 = (float)pmask[node];
    float o = sb[h];
    o += f0 * sW[0 * HD + h] + f1 * sW[1 * HD + h] + f2 * sW[2 * HD + h] + f3 * sW[3 * HD + h];
    o += f4 * sW[4 * HD + h] + f5 * sW[5 * HD + h] + f6 * sW[6 * HD + h] + f7 * sW[7 * HD + h];
    x[idx] = o;
}

// ---------------- CSR build ----------------
__global__ void k_zero_deg(int n)
{
    int i = blockIdx.x * blockDim.x + threadIdx.x;
    if (i < n) g_deg[i] = 0;
}

__global__ void k_deg(const int* __restrict__ ei, int ne)
{
    int e = blockIdx.x * blockDim.x + threadIdx.x;
    if (e >= ne) return;
    int s = ei[e], d = ei[ne + e];
    atomicAdd(&g_deg[s], 1);
    atomicAdd(&g_deg[d], 1);
}

__global__ void k_scan_local(int n)
{
    __shared__ int sh[1024];
    int t = threadIdx.x;
    int i = blockIdx.x * 1024 + t;
    int v = (i < n) ? g_deg[i] : 0;
    sh[t] = v;
    __syncthreads();
    for (int off = 1; off < 1024; off <<= 1) {
        int tv = (t >= off) ? sh[t - off] : 0;
        __syncthreads();
        sh[t] += tv;
        __syncthreads();
    }
    if (i < n) g_tmp[i] = sh[t];
    if (t == 1023) g_bsum[blockIdx.x] = sh[1023];
}

__global__ void k_scan_bsum(int nb)
{
    if (threadIdx.x == 0) {
        int acc = 0;
        for (int b = 0; b < nb; b++) { int tv = g_bsum[b]; g_bsum[b] = acc; acc += tv; }
    }
}

__global__ void k_scan_final(int n)
{
    int i = blockIdx.x * blockDim.x + threadIdx.x;
    if (i >= n) return;
    int incl = g_tmp[i] + g_bsum[i >> 10];
    g_rowptr[i + 1] = incl;
    int d = g_deg[i];
    g_cursor[i] = incl - d;
    g_invdeg[i] = 1.0f / (float)(d > 0 ? d : 1);
    if (i == 0) g_rowptr[0] = 0;
}

__global__ void k_fill(const int* __restrict__ ei, int ne)
{
    int e = blockIdx.x * blockDim.x + threadIdx.x;
    if (e >= ne) return;
    int s = ei[e], d = ei[ne + e];
    int p = atomicAdd(&g_cursor[d], 1);
    g_col[p] = s;
    int q = atomicAdd(&g_cursor[s], 1);
    g_col[q] = d;
}

// ---------------- mean aggregation: one warp per node, x4 unrolled (MLP=4) ----------------
__global__ void k_agg(const float* __restrict__ x, float* __restrict__ agg, int n)
{
    int w = (blockIdx.x * blockDim.x + threadIdx.x) >> 5;
    int lane = threadIdx.x & 31;
    if (w >= n) return;
    int beg = g_rowptr[w], end = g_rowptr[w + 1];
    float4 acc = make_float4(0.f, 0.f, 0.f, 0.f);
    int i = beg;
    int c = lane * 4;
    for (; i + 4 <= end; i += 4) {
        int n0 = g_col[i], n1 = g_col[i + 1], n2 = g_col[i + 2], n3 = g_col[i + 3];
        float4 v0 = *reinterpret_cast<const float4*>(&x[(size_t)n0 * HD + c]);
        float4 v1 = *reinterpret_cast<const float4*>(&x[(size_t)n1 * HD + c]);
        float4 v2 = *reinterpret_cast<const float4*>(&x[(size_t)n2 * HD + c]);
        float4 v3 = *reinterpret_cast<const float4*>(&x[(size_t)n3 * HD + c]);
        acc.x += v0.x + v1.x + v2.x + v3.x;
        acc.y += v0.y + v1.y + v2.y + v3.y;
        acc.z += v0.z + v1.z + v2.z + v3.z;
        acc.w += v0.w + v1.w + v2.w + v3.w;
    }
    for (; i < end; i++) {
        int nb = g_col[i];
        float4 v = *reinterpret_cast<const float4*>(&x[(size_t)nb * HD + c]);
        acc.x += v.x; acc.y += v.y; acc.z += v.z; acc.w += v.w;
    }
    float sc = g_invdeg[w];
    acc.x *= sc; acc.y *= sc; acc.z *= sc; acc.w *= sc;
    *reinterpret_cast<float4*>(&agg[(size_t)w * HD + c]) = acc;
}

// ---------------- GEMM (dual-A): C = op(A@W0 + A2@W1 + bias) ----------------
__global__ void __launch_bounds__(256) k_gemm_dualA(
    const float* __restrict__ A, const float* __restrict__ A2,
    const uint32_t* __restrict__ pW0, const uint32_t* __restrict__ pW1,
    const float* __restrict__ bias, float* __restrict__ C, int n, int relu)
{
    extern __shared__ uint32_t sm[];
    uint32_t* sA  = sm;
    uint32_t* sA2 = sm + 8448;

    int tid = threadIdx.x;
    int row0 = blockIdx.x * 64;
    for (int idx = tid; idx < 8192; idx += 256) {
        int r = idx >> 7, cc = idx & 127;
        int gr = row0 + r;
        bool ok = gr < n;
        sA [r * 132 + cc] = ok ? f2tf(A [(size_t)gr * HD + cc]) : 0u;
        sA2[r * 132 + cc] = ok ? f2tf(A2[(size_t)gr * HD + cc]) : 0u;
    }
    __syncthreads();

    int wid = tid >> 5, lane = tid & 31;
    int tg = lane & 3, gid = lane >> 2;
    int nt0 = wid * 2;

    float acc[4][8];
#pragma unroll
    for (int s = 0; s < 4; s++)
#pragma unroll
        for (int j = 0; j < 8; j++) acc[s][j] = 0.f;

    const uint2* B0 = reinterpret_cast<const uint2*>(pW0) + (nt0 * 32 + lane);
    const uint2* B1 = reinterpret_cast<const uint2*>(pW1) + (nt0 * 32 + lane);

#pragma unroll 4
    for (int ks = 0; ks < 16; ks++) {
        uint2 b0 = __ldg(B0 + ks * 512);
        uint2 b1 = __ldg(B0 + ks * 512 + 32);
        uint2 d0 = __ldg(B1 + ks * 512);
        uint2 d1 = __ldg(B1 + ks * 512 + 32);
        int ca = ks * 8 + tg;
#pragma unroll
        for (int s = 0; s < 4; s++) {
            int rb = (s * 16 + gid) * 132;
            uint32_t a0 = sA[rb + ca];
            uint32_t a1 = sA[rb + 8 * 132 + ca];
            uint32_t a2 = sA[rb + ca + 4];
            uint32_t a3 = sA[rb + 8 * 132 + ca + 4];
            MMA8(acc[s], a0, a1, a2, a3, b0.x, b0.y);
            MMA8(acc[s] + 4, a0, a1, a2, a3, b1.x, b1.y);
            uint32_t e0 = sA2[rb + ca];
            uint32_t e1 = sA2[rb + 8 * 132 + ca];
            uint32_t e2 = sA2[rb + ca + 4];
            uint32_t e3 = sA2[rb + 8 * 132 + ca + 4];
            MMA8(acc[s], e0, e1, e2, e3, d0.x, d0.y);
            MMA8(acc[s] + 4, e0, e1, e2, e3, d1.x, d1.y);
        }
    }

    int cbase = wid * 16;
    float bb[4];
    bb[0] = __ldg(&bias[cbase + 2 * tg]);
    bb[1] = __ldg(&bias[cbase + 2 * tg + 1]);
    bb[2] = __ldg(&bias[cbase + 8 + 2 * tg]);
    bb[3] = __ldg(&bias[cbase + 8 + 2 * tg + 1]);
#pragma unroll
    for (int s = 0; s < 4; s++) {
#pragma unroll
        for (int t = 0; t < 2; t++) {
            int col = cbase + t * 8 + 2 * tg;
            int r = row0 + s * 16 + gid;
            float v0 = acc[s][t * 4 + 0] + bb[t * 2 + 0];
            float v1 = acc[s][t * 4 + 1] + bb[t * 2 + 1];
            float v2 = acc[s][t * 4 + 2] + bb[t * 2 + 0];
            float v3 = acc[s][t * 4 + 3] + bb[t * 2 + 1];
            if (relu) {
                v0 = fmaxf(v0, 0.f); v1 = fmaxf(v1, 0.f);
                v2 = fmaxf(v2, 0.f); v3 = fmaxf(v3, 0.f);
            }
            if (r < n)
                *reinterpret_cast<float2*>(&C[(size_t)r * HD + col]) = make_float2(v0, v1);
            if (r + 8 < n)
                *reinterpret_cast<float2*>(&C[(size_t)(r + 8) * HD + col]) = make_float2(v2, v3);
        }
    }
}

// ---------------- merged head GEMMs: stage xf once, run 3 weight-pairs ----------------
// phase 0: nodehead hidden (fp32 + bias + relu) -> o0f/o1f stride 128
// phase 1: er pair tables (fp16) -> pa/pb stride 256 col offset 0
// phase 2: ea pair tables (fp16) -> pa/pb stride 256 col offset 128
struct HeadArgs {
    const uint32_t* pw0[3];
    const uint32_t* pw1[3];
    const float* b0;
    const float* b1;
    float* o0f;
    float* o1f;
    __half* pa;
    __half* pb;
};

__device__ __forceinline__ void mma_pair(
    const uint32_t* __restrict__ sA,
    const uint32_t* __restrict__ pW0, const uint32_t* __restrict__ pW1,
    int lane, int tg, int gid, int nt0, float acc0[4][8], float acc1[4][8])
{
#pragma unroll
    for (int s = 0; s < 4; s++)
#pragma unroll
        for (int j = 0; j < 8; j++) { acc0[s][j] = 0.f; acc1[s][j] = 0.f; }

    const uint2* B0 = reinterpret_cast<const uint2*>(pW0) + (nt0 * 32 + lane);
    const uint2* B1 = reinterpret_cast<const uint2*>(pW1) + (nt0 * 32 + lane);

#pragma unroll 4
    for (int ks = 0; ks < 16; ks++) {
        uint2 b0 = __ldg(B0 + ks * 512);
        uint2 b1 = __ldg(B0 + ks * 512 + 32);
        uint2 d0 = __ldg(B1 + ks * 512);
        uint2 d1 = __ldg(B1 + ks * 512 + 32);
        int ca = ks * 8 + tg;
#pragma unroll
        for (int s = 0; s < 4; s++) {
            int rb = (s * 16 + gid) * 132;
            uint32_t a0 = sA[rb + ca];
            uint32_t a1 = sA[rb + 8 * 132 + ca];
            uint32_t a2 = sA[rb + ca + 4];
            uint32_t a3 = sA[rb + 8 * 132 + ca + 4];
            MMA8(acc0[s], a0, a1, a2, a3, b0.x, b0.y);
            MMA8(acc0[s] + 4, a0, a1, a2, a3, b1.x, b1.y);
            MMA8(acc1[s], a0, a1, a2, a3, d0.x, d0.y);
            MMA8(acc1[s] + 4, a0, a1, a2, a3, d1.x, d1.y);
        }
    }
}

__global__ void __launch_bounds__(256) k_gemm_heads(
    const float* __restrict__ A, HeadArgs ha, int n)
{
    extern __shared__ uint32_t sm[];
    uint32_t* sA = sm;

    int tid = threadIdx.x;
    int row0 = blockIdx.x * 64;
    for (int idx = tid; idx < 8192; idx += 256) {
        int r = idx >> 7, cc = idx & 127;
        int gr = row0 + r;
        sA[r * 132 + cc] = (gr < n) ? f2tf(A[(size_t)gr * HD + cc]) : 0u;
    }
    __syncthreads();

    int wid = tid >> 5, lane = tid & 31;
    int tg = lane & 3, gid = lane >> 2;
    int nt0 = wid * 2;
    int cbase = wid * 16;

    float acc0[4][8], acc1[4][8];

    // ---- phase 0: nodehead hidden, fp32 + bias + relu, stride 128 ----
    mma_pair(sA, ha.pw0[0], ha.pw1[0], lane, tg, gid, nt0, acc0, acc1);
    {
        float bb0[4], bb1[4];
        bb0[0] = __ldg(&ha.b0[cbase + 2 * tg]);
        bb0[1] = __ldg(&ha.b0[cbase + 2 * tg + 1]);
        bb0[2] = __ldg(&ha.b0[cbase + 8 + 2 * tg]);
        bb0[3] = __ldg(&ha.b0[cbase + 8 + 2 * tg + 1]);
        bb1[0] = __ldg(&ha.b1[cbase + 2 * tg]);
        bb1[1] = __ldg(&ha.b1[cbase + 2 * tg + 1]);
        bb1[2] = __ldg(&ha.b1[cbase + 8 + 2 * tg]);
        bb1[3] = __ldg(&ha.b1[cbase + 8 + 2 * tg + 1]);
#pragma unroll
        for (int s = 0; s < 4; s++) {
#pragma unroll
            for (int t = 0; t < 2; t++) {
                int col = cbase + t * 8 + 2 * tg;
                int r = row0 + s * 16 + gid;
                float u0 = fmaxf(acc0[s][t * 4 + 0] + bb0[t * 2 + 0], 0.f);
                float u1 = fmaxf(acc0[s][t * 4 + 1] + bb0[t * 2 + 1], 0.f);
                float u2 = fmaxf(acc0[s][t * 4 + 2] + bb0[t * 2 + 0], 0.f);
                float u3 = fmaxf(acc0[s][t * 4 + 3] + bb0[t * 2 + 1], 0.f);
                float v0 = fmaxf(acc1[s][t * 4 + 0] + bb1[t * 2 + 0], 0.f);
                float v1 = fmaxf(acc1[s][t * 4 + 1] + bb1[t * 2 + 1], 0.f);
                float v2 = fmaxf(acc1[s][t * 4 + 2] + bb1[t * 2 + 0], 0.f);
                float v3 = fmaxf(acc1[s][t * 4 + 3] + bb1[t * 2 + 1], 0.f);
                if (r < n) {
                    *reinterpret_cast<float2*>(&ha.o0f[(size_t)r * HD + col]) = make_float2(u0, u1);
                    *reinterpret_cast<float2*>(&ha.o1f[(size_t)r * HD + col]) = make_float2(v0, v1);
                }
                if (r + 8 < n) {
                    *reinterpret_cast<float2*>(&ha.o0f[(size_t)(r + 8) * HD + col]) = make_float2(u2, u3);
                    *reinterpret_cast<float2*>(&ha.o1f[(size_t)(r + 8) * HD + col]) = make_float2(v2, v3);
                }
            }
        }
    }

    // ---- phases 1,2: pair tables, fp16, stride 256, col offset 0 / 128 ----
#pragma unroll 1
    for (int ph = 1; ph < 3; ph++) {
        mma_pair(sA, ha.pw0[ph], ha.pw1[ph], lane, tg, gid, nt0, acc0, acc1);
        int coff = (ph - 1) * 128;
#pragma unroll
        for (int s = 0; s < 4; s++) {
#pragma unroll
            for (int t = 0; t < 2; t++) {
                int col = coff + cbase + t * 8 + 2 * tg;
                int r = row0 + s * 16 + gid;
                if (r < n) {
                    *reinterpret_cast<__half2*>(&ha.pa[(size_t)r * 256 + col]) =
                        __floats2half2_rn(acc0[s][t * 4 + 0], acc0[s][t * 4 + 1]);
                    *reinterpret_cast<__half2*>(&ha.pb[(size_t)r * 256 + col]) =
                        __floats2half2_rn(acc1[s][t * 4 + 0], acc1[s][t * 4 + 1]);
                }
                if (r + 8 < n) {
                    *reinterpret_cast<__half2*>(&ha.pa[(size_t)(r + 8) * 256 + col]) =
                        __floats2half2_rn(acc0[s][t * 4 + 2], acc0[s][t * 4 + 3]);
                    *reinterpret_cast<__half2*>(&ha.pb[(size_t)(r + 8) * 256 + col]) =
                        __floats2half2_rn(acc1[s][t * 4 + 2], acc1[s][t * 4 + 3]);
                }
            }
        }
    }
}

// ---------------- node-head second stage: out = hidden . W2 + b2 (two heads) ----------------
__global__ void k_headreduce(const float* __restrict__ ha, const float* __restrict__ w2a,
                             const float* __restrict__ b2a,
                             const float* __restrict__ hb, const float* __restrict__ w2b,
                             const float* __restrict__ b2b,
                             float* __restrict__ pa, float* __restrict__ pb, int n)
{
    __shared__ float swa[128], swb[128];
    int tid = threadIdx.x;
    if (tid < 128) { swa[tid] = w2a[tid]; swb[tid] = w2b[tid]; }
    __syncthreads();
    int node = (blockIdx.x * blockDim.x + tid) >> 5;
    int lane = tid & 31;
    if (node >= n) return;
    float4 va = *reinterpret_cast<const float4*>(&ha[(size_t)node * HD + lane * 4]);
    float4 wa = *reinterpret_cast<const float4*>(&swa[lane * 4]);
    float sa = va.x * wa.x + va.y * wa.y + va.z * wa.z + va.w * wa.w;
    float4 vb = *reinterpret_cast<const float4*>(&hb[(size_t)node * HD + lane * 4]);
    float4 wb = *reinterpret_cast<const float4*>(&swb[lane * 4]);
    float sb = vb.x * wb.x + vb.y * wb.y + vb.z * wb.z + vb.w * wb.w;
#pragma unroll
    for (int off = 16; off; off >>= 1) {
        sa += __shfl_xor_sync(0xffffffffu, sa, off);
        sb += __shfl_xor_sync(0xffffffffu, sb, off);
    }
    if (lane == 0) {
        pa[node] = sa + __ldg(&b2a[0]);
        pb[node] = sb + __ldg(&b2b[0]);
    }
}

// ---------------- edge heads: EPW edges per warp, fp16 pair tables ----------------
__global__ void k_edge(const int* __restrict__ ei,
                       const float* __restrict__ estat, const float* __restrict__ qobs,
                       const int* __restrict__ qmask,
                       const float* __restrict__ erW1, const float* __restrict__ erb1,
                       const float* __restrict__ erW2, const float* __restrict__ erb2,
                       const float* __restrict__ eaW1, const float* __restrict__ eab1,
                       const float* __restrict__ eaW2, const float* __restrict__ eab2,
                       float* __restrict__ qhat, float* __restrict__ elog, int ne)
{
    __shared__ float sE[2][8 * HD];  // per head: rows 0-5 = W1[256+r], 6 = b1, 7 = W2
    int tid = threadIdx.x;
    for (int idx = tid; idx < 2 * 8 * HD; idx += blockDim.x) {
        int h = idx / (8 * HD);
        int rem = idx - h * 8 * HD;
        int r = rem >> 7, c = rem & 127;
        const float* W1 = h ? eaW1 : erW1;
        const float* b1 = h ? eab1 : erb1;
        const float* W2 = h ? eaW2 : erW2;
        float v;
        if (r < 6) v = W1[(256 + r) * HD + c];
        else if (r == 6) v = b1[c];
        else v = W2[c];
        sE[h][rem] = v;
    }
    __syncthreads();

    int warpg = (blockIdx.x * blockDim.x + tid) >> 5;
    int lane = tid & 31;
    int ebase = warpg * EPW;
    if (ebase >= ne) return;
    int eend = min(ebase + EPW, ne);
    int c = lane * 4;
    float eb2r = __ldg(&erb2[0]);
    float eb2a = __ldg(&eab2[0]);

    for (int e = ebase; e < eend; e++) {
        int s = __ldg(&ei[e]), d = __ldg(&ei[ne + e]);
        const __half* srcA = &g_pairAh[(size_t)s * 256];
        const __half* dstB = &g_pairBh[(size_t)d * 256];
        // prefetch all 4 gathers (MLP=4)
        uint2 ua0 = *reinterpret_cast<const uint2*>(&srcA[c]);
        uint2 ub0 = *reinterpret_cast<const uint2*>(&dstB[c]);
        uint2 ua1 = *reinterpret_cast<const uint2*>(&srcA[128 + c]);
        uint2 ub1 = *reinterpret_cast<const uint2*>(&dstB[128 + c]);

        float e0 = __ldg(&estat[e * 4 + 0]), e1 = __ldg(&estat[e * 4 + 1]);
        float e2 = __ldg(&estat[e * 4 + 2]), e3 = __ldg(&estat[e * 4 + 3]);
        float qo = __ldg(&qobs[e]), qm = (float)__ldg(&qmask[e]);

        float acc0 = 0.f, acc1 = 0.f;
        {
            const float* S = sE[0];
            const __half2* pa = reinterpret_cast<const __half2*>(&ua0);
            const __half2* pb = reinterpret_cast<const __half2*>(&ub0);
            float2 a01 = __half22float2(pa[0]), a23 = __half22float2(pa[1]);
            float2 b01 = __half22float2(pb[0]), b23 = __half22float2(pb[1]);
            float av[4] = {a01.x, a01.y, a23.x, a23.y};
            float bv[4] = {b01.x, b01.y, b23.x, b23.y};
#pragma unroll
            for (int t = 0; t < 4; t++) {
                int cc = c + t;
                float hv = av[t] + bv[t] + e0 * S[cc] + e1 * S[HD + cc] + e2 * S[2 * HD + cc]
                         + e3 * S[3 * HD + cc] + qo * S[4 * HD + cc] + qm * S[5 * HD + cc]
                         + S[6 * HD + cc];
                hv = fmaxf(hv, 0.f);
                acc0 += hv * S[7 * HD + cc];
            }
        }
        {
            const float* S = sE[1];
            const __half2* pa = reinterpret_cast<const __half2*>(&ua1);
            const __half2* pb = reinterpret_cast<const __half2*>(&ub1);
            float2 a01 = __half22float2(pa[0]), a23 = __half22float2(pa[1]);
            float2 b01 = __half22float2(pb[0]), b23 = __half22float2(pb[1]);
            float av[4] = {a01.x, a01.y, a23.x, a23.y};
            float bv[4] = {b01.x, b01.y, b23.x, b23.y};
#pragma unroll
            for (int t = 0; t < 4; t++) {
                int cc = c + t;
                float hv = av[t] + bv[t] + e0 * S[cc] + e1 * S[HD + cc] + e2 * S[2 * HD + cc]
                         + e3 * S[3 * HD + cc] + qo * S[4 * HD + cc] + qm * S[5 * HD + cc]
                         + S[6 * HD + cc];
                hv = fmaxf(hv, 0.f);
                acc1 += hv * S[7 * HD + cc];
            }
        }
        // interleaved dual reduction
#pragma unroll
        for (int off = 16; off; off >>= 1) {
            acc0 += __shfl_xor_sync(0xffffffffu, acc0, off);
            acc1 += __shfl_xor_sync(0xffffffffu, acc1, off);
        }
        if (lane == 0) {
            qhat[e] = acc0 + eb2r;
            elog[e] = acc1 + eb2a;
        }
    }
}

// ---------------- launch ----------------
extern "C" void kernel_launch(void* const* d_in, const int* in_sizes, int n_in,
                              void* d_out, int out_size)
{
    const int*   ei           = (const int*)d_in[0];   // edge_index is int32 (jax x64 disabled)
    const float* node_static  = (const float*)d_in[1];
    const float* edge_static  = (const float*)d_in[2];
    const float* p_obs        = (const float*)d_in[3];
    const float* q_obs        = (const float*)d_in[4];
    const int*   p_mask       = (const int*)d_in[5];
    const int*   q_mask       = (const int*)d_in[6];
    const float* W_enc        = (const float*)d_in[7];
    const float* b_enc        = (const float*)d_in[8];
    const float* W_self       = (const float*)d_in[9];
    const float* W_neigh      = (const float*)d_in[10];
    const float* b_gnn        = (const float*)d_in[11];
    const float* nrW1 = (const float*)d_in[12]; const float* nrb1 = (const float*)d_in[13];
    const float* nrW2 = (const float*)d_in[14]; const float* nrb2 = (const float*)d_in[15];
    const float* naW1 = (const float*)d_in[16]; const float* nab1 = (const float*)d_in[17];
    const float* naW2 = (const float*)d_in[18]; const float* nab2 = (const float*)d_in[19];
    const float* erW1 = (const float*)d_in[20]; const float* erb1 = (const float*)d_in[21];
    const float* erW2 = (const float*)d_in[22]; const float* erb2 = (const float*)d_in[23];
    const float* eaW1 = (const float*)d_in[24]; const float* eab1 = (const float*)d_in[25];
    const float* eaW2 = (const float*)d_in[26]; const float* eab2 = (const float*)d_in[27];

    int n  = in_sizes[3];  // N (p_obs)
    int ne = in_sizes[4];  // E (q_obs)

    float* out   = (float*)d_out;
    float* p_hat = out;
    float* q_hat = out + n;
    float* nlog  = out + n + ne;
    float* elog  = out + 2 * n + ne;

    float *gx, *gy, *gagg;
    __half *gpa, *gpb;
    uint32_t* gpw;
    cudaGetSymbolAddress((void**)&gx,   g_x);
    cudaGetSymbolAddress((void**)&gy,   g_y);
    cudaGetSymbolAddress((void**)&gagg, g_agg);
    cudaGetSymbolAddress((void**)&gpa,  g_pairAh);
    cudaGetSymbolAddress((void**)&gpb,  g_pairBh);
    cudaGetSymbolAddress((void**)&gpw,  g_pw);

    const int SM_DUALA = 2 * 8448 * 4;  // 67584 B
    const int SM_ONEA  = 8448 * 4;      // 33792 B
    cudaFuncSetAttribute(k_gemm_dualA, cudaFuncAttributeMaxDynamicSharedMemorySize, SM_DUALA);
    cudaFuncSetAttribute(k_gemm_heads, cudaFuncAttributeMaxDynamicSharedMemorySize, SM_ONEA);

    // pre-pack the 12 weight matrices: 0-2 Wself[l], 3-5 Wneigh[l], 6 nrW1, 7 naW1,
    // 8 erW1 top, 9 erW1 bot, 10 eaW1 top, 11 eaW1 bot
    PackSrc ps;
    ps.s[0] = W_self;                ps.s[1] = W_self + 16384;  ps.s[2] = W_self + 32768;
    ps.s[3] = W_neigh;               ps.s[4] = W_neigh + 16384; ps.s[5] = W_neigh + 32768;
    ps.s[6] = nrW1;                  ps.s[7] = naW1;
    ps.s[8] = erW1;                  ps.s[9] = erW1 + 16384;
    ps.s[10] = eaW1;                 ps.s[11] = eaW1 + 16384;
    k_pack<<<(12 * 16384 + 255) / 256, 256>>>(ps);

    k_encoder<<<(n * HD + 255) / 256, 256>>>(node_static, p_obs, p_mask, W_enc, b_enc, gx, n);
    k_zero_deg<<<(n + 255) / 256, 256>>>(n);
    k_deg<<<(ne + 255) / 256, 256>>>(ei, ne);
    int nb = (n + 1023) / 1024;
    k_scan_local<<<nb, 1024>>>(n);
    k_scan_bsum<<<1, 32>>>(nb);
    k_scan_final<<<(n + 255) / 256, 256>>>(n);
    k_fill<<<(ne + 255) / 256, 256>>>(ei, ne);

    int gblocks = (n + 63) / 64;
    const float* xin = gx;
    float* xout = gy;
    for (int l = 0; l < 3; l++) {
        k_agg<<<(n * 32 + 255) / 256, 256>>>(xin, gagg, n);
        k_gemm_dualA<<<gblocks, 256, SM_DUALA>>>(xin, gagg,
                                                 gpw + l * 16384, gpw + (3 + l) * 16384,
                                                 b_gnn + l * HD, xout, n, (l < 2) ? 1 : 0);
        const float* t = xin;
        xin = xout;
        xout = (float*)t;
    }
    const float* xf = xin;  // final node embeddings (g_y); g_x and g_agg now free

    // all head GEMMs in one launch: nodehead hidden -> gx/gagg; pair tables -> gpa/gpb
    HeadArgs ha;
    ha.pw0[0] = gpw + 6 * 16384;  ha.pw1[0] = gpw + 7 * 16384;
    ha.pw0[1] = gpw + 8 * 16384;  ha.pw1[1] = gpw + 9 * 16384;
    ha.pw0[2] = gpw + 10 * 16384; ha.pw1[2] = gpw + 11 * 16384;
    ha.b0 = nrb1; ha.b1 = nab1;
    ha.o0f = gx;  ha.o1f = gagg;
    ha.pa = gpa;  ha.pb = gpb;
    k_gemm_heads<<<gblocks, 256, SM_ONEA>>>(xf, ha, n);

    k_headreduce<<<(n * 32 + 255) / 256, 256>>>(gx, nrW2, nrb2, gagg, naW2, nab2, p_hat, nlog, n);

    int eblocks = (ne + 8 * EPW - 1) / (8 * EPW);
    k_edge<<<eblocks, 256>>>(ei, edge_static, q_obs, q_mask,
                             erW1, erb1, erW2, erb2,
                             eaW1, eab1, eaW2, eab2,
                             q_hat, elog, ne);
}

// round 13
// speedup vs baseline: 1.2094x; 1.0165x over previous
#include <cuda_runtime.h>
#include <cuda_fp16.h>
#include <cstdint>

#define NN 100000
#define NE 600000
#define HD 128
#define EPW 16   // edges per warp in k_edge

// ---------------- scratch (static device memory; no allocs) ----------------
static __device__ float  g_x  [NN * HD];
static __device__ float  g_y  [NN * HD];
static __device__ float  g_agg[NN * HD];
static __device__ __half g_xh0[NN * HD];          // fp16 shadow of x (ping)
static __device__ __half g_xh1[NN * HD];          // fp16 shadow of x (pong)
static __device__ __half g_pairAh[NN * 256];      // [node][0:128)=er A-part, [128:256)=ea A-part
static __device__ __half g_pairBh[NN * 256];      // [node][0:128)=er B-part, [128:256)=ea B-part
static __device__ int    g_deg[NN];
static __device__ int    g_rowptr[NN + 1];
static __device__ int    g_cursor[NN];
static __device__ int    g_col[2 * NE];
static __device__ float  g_invdeg[NN];
static __device__ int    g_tmp[NN];
static __device__ int    g_bsum[128];
static __device__ uint32_t g_pw[12 * 16384];      // packed tf32 weights, fragment order

// ---------------- tf32 helpers ----------------
__device__ __forceinline__ uint32_t f2tf(float f)
{
    uint32_t r;
    asm("cvt.rna.tf32.f32 %0, %1;" : "=r"(r) : "f"(f));
    return r;
}

#define MMA8(c, a0, a1, a2, a3, b0, b1)                                     \
    asm volatile("mma.sync.aligned.m16n8k8.row.col.f32.tf32.tf32.f32 "      \
                 "{%0,%1,%2,%3},{%4,%5,%6,%7},{%8,%9},{%0,%1,%2,%3};"       \
                 : "+f"((c)[0]), "+f"((c)[1]), "+f"((c)[2]), "+f"((c)[3])   \
                 : "r"(a0), "r"(a1), "r"(a2), "r"(a3), "r"(b0), "r"(b1))

// ---------------- weight pre-pack: 12 matrices of 128x128 into fragment order ----------------
struct PackSrc { const float* s[12]; };

__global__ void k_pack(PackSrc ps)
{
    int idx = blockIdx.x * 256 + threadIdx.x;
    if (idx >= 12 * 16384) return;
    int m = idx >> 14, e = idx & 16383;
    int k = e >> 7, nn2 = e & 127;
    int kstep = k >> 3, kin = k & 7, ntile = nn2 >> 3, nin = nn2 & 7;
    int lane = (nin << 2) | (kin & 3);
    int dest = (((kstep << 4) + ntile) << 6) + (lane << 1) + (kin >> 2);
    g_pw[m * 16384 + dest] = f2tf(__ldg(&ps.s[m][e]));
}

// ---------------- encoder: x = node_feats(8) @ W_enc + b_enc (fp32 + fp16 shadow) ----------------
__global__ void k_encoder(const float* __restrict__ ns, const float* __restrict__ pobs,
                          const int* __restrict__ pmask, const float* __restrict__ Wenc,
                          const float* __restrict__ benc, float* __restrict__ x,
                          __half* __restrict__ xh, int n)
{
    __shared__ float sW[8 * HD];
    __shared__ float sb[HD];
    for (int i = threadIdx.x; i < 8 * HD; i += blockDim.x) sW[i] = Wenc[i];
    for (int i = threadIdx.x; i < HD; i += blockDim.x) sb[i] = benc[i];
    __syncthreads();
    int idx = blockIdx.x * blockDim.x + threadIdx.x;
    if (idx >= n * HD) return;
    int node = idx >> 7, h = idx & 127;
    float f0 = ns[node * 6 + 0], f1 = ns[node * 6 + 1], f2 = ns[node * 6 + 2];
    float f3 = ns[node * 6 + 3], f4 = ns[node * 6 + 4], f5 = ns[node * 6 + 5];
    float f6 = pobs[node];
    float f7 = (float)pmask[node];
    float o = sb[h];
    o += f0 * sW[0 * HD + h] + f1 * sW[1 * HD + h] + f2 * sW[2 * HD + h] + f3 * sW[3 * HD + h];
    o += f4 * sW[4 * HD + h] + f5 * sW[5 * HD + h] + f6 * sW[6 * HD + h] + f7 * sW[7 * HD + h];
    x[idx] = o;
    xh[idx] = __float2half_rn(o);
}

// ---------------- CSR build ----------------
__global__ void k_zero_deg(int n)
{
    int i = blockIdx.x * blockDim.x + threadIdx.x;
    if (i < n) g_deg[i] = 0;
}

__global__ void k_deg(const int* __restrict__ ei, int ne)
{
    int e = blockIdx.x * blockDim.x + threadIdx.x;
    if (e >= ne) return;
    int s = ei[e], d = ei[ne + e];
    atomicAdd(&g_deg[s], 1);
    atomicAdd(&g_deg[d], 1);
}

__global__ void k_scan_local(int n)
{
    __shared__ int sh[1024];
    int t = threadIdx.x;
    int i = blockIdx.x * 1024 + t;
    int v = (i < n) ? g_deg[i] : 0;
    sh[t] = v;
    __syncthreads();
    for (int off = 1; off < 1024; off <<= 1) {
        int tv = (t >= off) ? sh[t - off] : 0;
        __syncthreads();
        sh[t] += tv;
        __syncthreads();
    }
    if (i < n) g_tmp[i] = sh[t];
    if (t == 1023) g_bsum[blockIdx.x] = sh[1023];
}

__global__ void k_scan_bsum(int nb)
{
    if (threadIdx.x == 0) {
        int acc = 0;
        for (int b = 0; b < nb; b++) { int tv = g_bsum[b]; g_bsum[b] = acc; acc += tv; }
    }
}

__global__ void k_scan_final(int n)
{
    int i = blockIdx.x * blockDim.x + threadIdx.x;
    if (i >= n) return;
    int incl = g_tmp[i] + g_bsum[i >> 10];
    g_rowptr[i + 1] = incl;
    int d = g_deg[i];
    g_cursor[i] = incl - d;
    g_invdeg[i] = 1.0f / (float)(d > 0 ? d : 1);
    if (i == 0) g_rowptr[0] = 0;
}

__global__ void k_fill(const int* __restrict__ ei, int ne)
{
    int e = blockIdx.x * blockDim.x + threadIdx.x;
    if (e >= ne) return;
    int s = ei[e], d = ei[ne + e];
    int p = atomicAdd(&g_cursor[d], 1);
    g_col[p] = s;
    int q = atomicAdd(&g_cursor[s], 1);
    g_col[q] = d;
}

// ---------------- mean aggregation: one warp per node, fp16 gathers, x4 unrolled ----------------
__global__ void k_agg(const __half* __restrict__ xh, float* __restrict__ agg, int n)
{
    int w = (blockIdx.x * blockDim.x + threadIdx.x) >> 5;
    int lane = threadIdx.x & 31;
    if (w >= n) return;
    int beg = g_rowptr[w], end = g_rowptr[w + 1];
    float acc0 = 0.f, acc1 = 0.f, acc2 = 0.f, acc3 = 0.f;
    int i = beg;
    int c = lane * 4;
    for (; i + 4 <= end; i += 4) {
        int n0 = g_col[i], n1 = g_col[i + 1], n2 = g_col[i + 2], n3 = g_col[i + 3];
        uint2 u0 = *reinterpret_cast<const uint2*>(&xh[(size_t)n0 * HD + c]);
        uint2 u1 = *reinterpret_cast<const uint2*>(&xh[(size_t)n1 * HD + c]);
        uint2 u2 = *reinterpret_cast<const uint2*>(&xh[(size_t)n2 * HD + c]);
        uint2 u3 = *reinterpret_cast<const uint2*>(&xh[(size_t)n3 * HD + c]);
        const __half2* p0 = reinterpret_cast<const __half2*>(&u0);
        const __half2* p1 = reinterpret_cast<const __half2*>(&u1);
        const __half2* p2 = reinterpret_cast<const __half2*>(&u2);
        const __half2* p3 = reinterpret_cast<const __half2*>(&u3);
        float2 a0 = __half22float2(p0[0]), a1 = __half22float2(p0[1]);
        float2 b0 = __half22float2(p1[0]), b1 = __half22float2(p1[1]);
        float2 c0 = __half22float2(p2[0]), c1 = __half22float2(p2[1]);
        float2 d0 = __half22float2(p3[0]), d1 = __half22float2(p3[1]);
        acc0 += a0.x + b0.x + c0.x + d0.x;
        acc1 += a0.y + b0.y + c0.y + d0.y;
        acc2 += a1.x + b1.x + c1.x + d1.x;
        acc3 += a1.y + b1.y + c1.y + d1.y;
    }
    for (; i < end; i++) {
        int nb = g_col[i];
        uint2 u = *reinterpret_cast<const uint2*>(&xh[(size_t)nb * HD + c]);
        const __half2* p = reinterpret_cast<const __half2*>(&u);
        float2 a0 = __half22float2(p[0]), a1 = __half22float2(p[1]);
        acc0 += a0.x; acc1 += a0.y; acc2 += a1.x; acc3 += a1.y;
    }
    float sc = g_invdeg[w];
    float4 r = make_float4(acc0 * sc, acc1 * sc, acc2 * sc, acc3 * sc);
    *reinterpret_cast<float4*>(&agg[(size_t)w * HD + c]) = r;
}

// ---------------- GEMM (dual-A): C = op(A@W0 + A2@W1 + bias) [+ fp16 shadow of C] ----------------
__global__ void __launch_bounds__(256) k_gemm_dualA(
    const float* __restrict__ A, const float* __restrict__ A2,
    const uint32_t* __restrict__ pW0, const uint32_t* __restrict__ pW1,
    const float* __restrict__ bias, float* __restrict__ C,
    __half* __restrict__ Ch, int n, int relu)
{
    extern __shared__ uint32_t sm[];
    uint32_t* sA  = sm;
    uint32_t* sA2 = sm + 8448;

    int tid = threadIdx.x;
    int row0 = blockIdx.x * 64;
    for (int idx = tid; idx < 8192; idx += 256) {
        int r = idx >> 7, cc = idx & 127;
        int gr = row0 + r;
        bool ok = gr < n;
        sA [r * 132 + cc] = ok ? f2tf(A [(size_t)gr * HD + cc]) : 0u;
        sA2[r * 132 + cc] = ok ? f2tf(A2[(size_t)gr * HD + cc]) : 0u;
    }
    __syncthreads();

    int wid = tid >> 5, lane = tid & 31;
    int tg = lane & 3, gid = lane >> 2;
    int nt0 = wid * 2;

    float acc[4][8];
#pragma unroll
    for (int s = 0; s < 4; s++)
#pragma unroll
        for (int j = 0; j < 8; j++) acc[s][j] = 0.f;

    const uint2* B0 = reinterpret_cast<const uint2*>(pW0) + (nt0 * 32 + lane);
    const uint2* B1 = reinterpret_cast<const uint2*>(pW1) + (nt0 * 32 + lane);

#pragma unroll 4
    for (int ks = 0; ks < 16; ks++) {
        uint2 b0 = __ldg(B0 + ks * 512);
        uint2 b1 = __ldg(B0 + ks * 512 + 32);
        uint2 d0 = __ldg(B1 + ks * 512);
        uint2 d1 = __ldg(B1 + ks * 512 + 32);
        int ca = ks * 8 + tg;
#pragma unroll
        for (int s = 0; s < 4; s++) {
            int rb = (s * 16 + gid) * 132;
            uint32_t a0 = sA[rb + ca];
            uint32_t a1 = sA[rb + 8 * 132 + ca];
            uint32_t a2 = sA[rb + ca + 4];
            uint32_t a3 = sA[rb + 8 * 132 + ca + 4];
            MMA8(acc[s], a0, a1, a2, a3, b0.x, b0.y);
            MMA8(acc[s] + 4, a0, a1, a2, a3, b1.x, b1.y);
            uint32_t e0 = sA2[rb + ca];
            uint32_t e1 = sA2[rb + 8 * 132 + ca];
            uint32_t e2 = sA2[rb + ca + 4];
            uint32_t e3 = sA2[rb + 8 * 132 + ca + 4];
            MMA8(acc[s], e0, e1, e2, e3, d0.x, d0.y);
            MMA8(acc[s] + 4, e0, e1, e2, e3, d1.x, d1.y);
        }
    }

    int cbase = wid * 16;
    float bb[4];
    bb[0] = __ldg(&bias[cbase + 2 * tg]);
    bb[1] = __ldg(&bias[cbase + 2 * tg + 1]);
    bb[2] = __ldg(&bias[cbase + 8 + 2 * tg]);
    bb[3] = __ldg(&bias[cbase + 8 + 2 * tg + 1]);
#pragma unroll
    for (int s = 0; s < 4; s++) {
#pragma unroll
        for (int t = 0; t < 2; t++) {
            int col = cbase + t * 8 + 2 * tg;
            int r = row0 + s * 16 + gid;
            float v0 = acc[s][t * 4 + 0] + bb[t * 2 + 0];
            float v1 = acc[s][t * 4 + 1] + bb[t * 2 + 1];
            float v2 = acc[s][t * 4 + 2] + bb[t * 2 + 0];
            float v3 = acc[s][t * 4 + 3] + bb[t * 2 + 1];
            if (relu) {
                v0 = fmaxf(v0, 0.f); v1 = fmaxf(v1, 0.f);
                v2 = fmaxf(v2, 0.f); v3 = fmaxf(v3, 0.f);
            }
            if (r < n) {
                *reinterpret_cast<float2*>(&C[(size_t)r * HD + col]) = make_float2(v0, v1);
                if (Ch)
                    *reinterpret_cast<__half2*>(&Ch[(size_t)r * HD + col]) = __floats2half2_rn(v0, v1);
            }
            if (r + 8 < n) {
                *reinterpret_cast<float2*>(&C[(size_t)(r + 8) * HD + col]) = make_float2(v2, v3);
                if (Ch)
                    *reinterpret_cast<__half2*>(&Ch[(size_t)(r + 8) * HD + col]) = __floats2half2_rn(v2, v3);
            }
        }
    }
}

// ---------------- merged head GEMMs: stage xf once, run 3 weight-pairs ----------------
struct HeadArgs {
    const uint32_t* pw0[3];
    const uint32_t* pw1[3];
    const float* b0;
    const float* b1;
    float* o0f;
    float* o1f;
    __half* pa;
    __half* pb;
};

__device__ __forceinline__ void mma_pair(
    const uint32_t* __restrict__ sA,
    const uint32_t* __restrict__ pW0, const uint32_t* __restrict__ pW1,
    int lane, int tg, int gid, int nt0, float acc0[4][8], float acc1[4][8])
{
#pragma unroll
    for (int s = 0; s < 4; s++)
#pragma unroll
        for (int j = 0; j < 8; j++) { acc0[s][j] = 0.f; acc1[s][j] = 0.f; }

    const uint2* B0 = reinterpret_cast<const uint2*>(pW0) + (nt0 * 32 + lane);
    const uint2* B1 = reinterpret_cast<const uint2*>(pW1) + (nt0 * 32 + lane);

#pragma unroll 4
    for (int ks = 0; ks < 16; ks++) {
        uint2 b0 = __ldg(B0 + ks * 512);
        uint2 b1 = __ldg(B0 + ks * 512 + 32);
        uint2 d0 = __ldg(B1 + ks * 512);
        uint2 d1 = __ldg(B1 + ks * 512 + 32);
        int ca = ks * 8 + tg;
#pragma unroll
        for (int s = 0; s < 4; s++) {
            int rb = (s * 16 + gid) * 132;
            uint32_t a0 = sA[rb + ca];
            uint32_t a1 = sA[rb + 8 * 132 + ca];
            uint32_t a2 = sA[rb + ca + 4];
            uint32_t a3 = sA[rb + 8 * 132 + ca + 4];
            MMA8(acc0[s], a0, a1, a2, a3, b0.x, b0.y);
            MMA8(acc0[s] + 4, a0, a1, a2, a3, b1.x, b1.y);
            MMA8(acc1[s], a0, a1, a2, a3, d0.x, d0.y);
            MMA8(acc1[s] + 4, a0, a1, a2, a3, d1.x, d1.y);
        }
    }
}

__global__ void __launch_bounds__(256) k_gemm_heads(
    const float* __restrict__ A, HeadArgs ha, int n)
{
    extern __shared__ uint32_t sm[];
    uint32_t* sA = sm;

    int tid = threadIdx.x;
    int row0 = blockIdx.x * 64;
    for (int idx = tid; idx < 8192; idx += 256) {
        int r = idx >> 7, cc = idx & 127;
        int gr = row0 + r;
        sA[r * 132 + cc] = (gr < n) ? f2tf(A[(size_t)gr * HD + cc]) : 0u;
    }
    __syncthreads();

    int wid = tid >> 5, lane = tid & 31;
    int tg = lane & 3, gid = lane >> 2;
    int nt0 = wid * 2;
    int cbase = wid * 16;

    float acc0[4][8], acc1[4][8];

    // ---- phase 0: nodehead hidden, fp32 + bias + relu, stride 128 ----
    mma_pair(sA, ha.pw0[0], ha.pw1[0], lane, tg, gid, nt0, acc0, acc1);
    {
        float bb0[4], bb1[4];
        bb0[0] = __ldg(&ha.b0[cbase + 2 * tg]);
        bb0[1] = __ldg(&ha.b0[cbase + 2 * tg + 1]);
        bb0[2] = __ldg(&ha.b0[cbase + 8 + 2 * tg]);
        bb0[3] = __ldg(&ha.b0[cbase + 8 + 2 * tg + 1]);
        bb1[0] = __ldg(&ha.b1[cbase + 2 * tg]);
        bb1[1] = __ldg(&ha.b1[cbase + 2 * tg + 1]);
        bb1[2] = __ldg(&ha.b1[cbase + 8 + 2 * tg]);
        bb1[3] = __ldg(&ha.b1[cbase + 8 + 2 * tg + 1]);
#pragma unroll
        for (int s = 0; s < 4; s++) {
#pragma unroll
            for (int t = 0; t < 2; t++) {
                int col = cbase + t * 8 + 2 * tg;
                int r = row0 + s * 16 + gid;
                float u0 = fmaxf(acc0[s][t * 4 + 0] + bb0[t * 2 + 0], 0.f);
                float u1 = fmaxf(acc0[s][t * 4 + 1] + bb0[t * 2 + 1], 0.f);
                float u2 = fmaxf(acc0[s][t * 4 + 2] + bb0[t * 2 + 0], 0.f);
                float u3 = fmaxf(acc0[s][t * 4 + 3] + bb0[t * 2 + 1], 0.f);
                float v0 = fmaxf(acc1[s][t * 4 + 0] + bb1[t * 2 + 0], 0.f);
                float v1 = fmaxf(acc1[s][t * 4 + 1] + bb1[t * 2 + 1], 0.f);
                float v2 = fmaxf(acc1[s][t * 4 + 2] + bb1[t * 2 + 0], 0.f);
                float v3 = fmaxf(acc1[s][t * 4 + 3] + bb1[t * 2 + 1], 0.f);
                if (r < n) {
                    *reinterpret_cast<float2*>(&ha.o0f[(size_t)r * HD + col]) = make_float2(u0, u1);
                    *reinterpret_cast<float2*>(&ha.o1f[(size_t)r * HD + col]) = make_float2(v0, v1);
                }
                if (r + 8 < n) {
                    *reinterpret_cast<float2*>(&ha.o0f[(size_t)(r + 8) * HD + col]) = make_float2(u2, u3);
                    *reinterpret_cast<float2*>(&ha.o1f[(size_t)(r + 8) * HD + col]) = make_float2(v2, v3);
                }
            }
        }
    }

    // ---- phases 1,2: pair tables, fp16, stride 256, col offset 0 / 128 ----
#pragma unroll 1
    for (int ph = 1; ph < 3; ph++) {
        mma_pair(sA, ha.pw0[ph], ha.pw1[ph], lane, tg, gid, nt0, acc0, acc1);
        int coff = (ph - 1) * 128;
#pragma unroll
        for (int s = 0; s < 4; s++) {
#pragma unroll
            for (int t = 0; t < 2; t++) {
                int col = coff + cbase + t * 8 + 2 * tg;
                int r = row0 + s * 16 + gid;
                if (r < n) {
                    *reinterpret_cast<__half2*>(&ha.pa[(size_t)r * 256 + col]) =
                        __floats2half2_rn(acc0[s][t * 4 + 0], acc0[s][t * 4 + 1]);
                    *reinterpret_cast<__half2*>(&ha.pb[(size_t)r * 256 + col]) =
                        __floats2half2_rn(acc1[s][t * 4 + 0], acc1[s][t * 4 + 1]);
                }
                if (r + 8 < n) {
                    *reinterpret_cast<__half2*>(&ha.pa[(size_t)(r + 8) * 256 + col]) =
                        __floats2half2_rn(acc0[s][t * 4 + 2], acc0[s][t * 4 + 3]);
                    *reinterpret_cast<__half2*>(&ha.pb[(size_t)(r + 8) * 256 + col]) =
                        __floats2half2_rn(acc1[s][t * 4 + 2], acc1[s][t * 4 + 3]);
                }
            }
        }
    }
}

// ---------------- node-head second stage: out = hidden . W2 + b2 (two heads) ----------------
__global__ void k_headreduce(const float* __restrict__ ha, const float* __restrict__ w2a,
                             const float* __restrict__ b2a,
                             const float* __restrict__ hb, const float* __restrict__ w2b,
                             const float* __restrict__ b2b,
                             float* __restrict__ pa, float* __restrict__ pb, int n)
{
    __shared__ float swa[128], swb[128];
    int tid = threadIdx.x;
    if (tid < 128) { swa[tid] = w2a[tid]; swb[tid] = w2b[tid]; }
    __syncthreads();
    int node = (blockIdx.x * blockDim.x + tid) >> 5;
    int lane = tid & 31;
    if (node >= n) return;
    float4 va = *reinterpret_cast<const float4*>(&ha[(size_t)node * HD + lane * 4]);
    float4 wa = *reinterpret_cast<const float4*>(&swa[lane * 4]);
    float sa = va.x * wa.x + va.y * wa.y + va.z * wa.z + va.w * wa.w;
    float4 vb = *reinterpret_cast<const float4*>(&hb[(size_t)node * HD + lane * 4]);
    float4 wb = *reinterpret_cast<const float4*>(&swb[lane * 4]);
    float sb = vb.x * wb.x + vb.y * wb.y + vb.z * wb.z + vb.w * wb.w;
#pragma unroll
    for (int off = 16; off; off >>= 1) {
        sa += __shfl_xor_sync(0xffffffffu, sa, off);
        sb += __shfl_xor_sync(0xffffffffu, sb, off);
    }
    if (lane == 0) {
        pa[node] = sa + __ldg(&b2a[0]);
        pb[node] = sb + __ldg(&b2b[0]);
    }
}

// ---------------- edge heads: EPW edges per warp, fp16 pair tables ----------------
__global__ void k_edge(const int* __restrict__ ei,
                       const float* __restrict__ estat, const float* __restrict__ qobs,
                       const int* __restrict__ qmask,
                       const float* __restrict__ erW1, const float* __restrict__ erb1,
                       const float* __restrict__ erW2, const float* __restrict__ erb2,
                       const float* __restrict__ eaW1, const float* __restrict__ eab1,
                       const float* __restrict__ eaW2, const float* __restrict__ eab2,
                       float* __restrict__ qhat, float* __restrict__ elog, int ne)
{
    __shared__ float sE[2][8 * HD];  // per head: rows 0-5 = W1[256+r], 6 = b1, 7 = W2
    int tid = threadIdx.x;
    for (int idx = tid; idx < 2 * 8 * HD; idx += blockDim.x) {
        int h = idx / (8 * HD);
        int rem = idx - h * 8 * HD;
        int r = rem >> 7, c = rem & 127;
        const float* W1 = h ? eaW1 : erW1;
        const float* b1 = h ? eab1 : erb1;
        const float* W2 = h ? eaW2 : erW2;
        float v;
        if (r < 6) v = W1[(256 + r) * HD + c];
        else if (r == 6) v = b1[c];
        else v = W2[c];
        sE[h][rem] = v;
    }
    __syncthreads();

    int warpg = (blockIdx.x * blockDim.x + tid) >> 5;
    int lane = tid & 31;
    int ebase = warpg * EPW;
    if (ebase >= ne) return;
    int eend = min(ebase + EPW, ne);
    int c = lane * 4;
    float eb2r = __ldg(&erb2[0]);
    float eb2a = __ldg(&eab2[0]);

    for (int e = ebase; e < eend; e++) {
        int s = __ldg(&ei[e]), d = __ldg(&ei[ne + e]);
        const __half* srcA = &g_pairAh[(size_t)s * 256];
        const __half* dstB = &g_pairBh[(size_t)d * 256];
        uint2 ua0 = *reinterpret_cast<const uint2*>(&srcA[c]);
        uint2 ub0 = *reinterpret_cast<const uint2*>(&dstB[c]);
        uint2 ua1 = *reinterpret_cast<const uint2*>(&srcA[128 + c]);
        uint2 ub1 = *reinterpret_cast<const uint2*>(&dstB[128 + c]);

        float e0 = __ldg(&estat[e * 4 + 0]), e1 = __ldg(&estat[e * 4 + 1]);
        float e2 = __ldg(&estat[e * 4 + 2]), e3 = __ldg(&estat[e * 4 + 3]);
        float qo = __ldg(&qobs[e]), qm = (float)__ldg(&qmask[e]);

        float acc0 = 0.f, acc1 = 0.f;
        {
            const float* S = sE[0];
            const __half2* pa = reinterpret_cast<const __half2*>(&ua0);
            const __half2* pb = reinterpret_cast<const __half2*>(&ub0);
            float2 a01 = __half22float2(pa[0]), a23 = __half22float2(pa[1]);
            float2 b01 = __half22float2(pb[0]), b23 = __half22float2(pb[1]);
            float av[4] = {a01.x, a01.y, a23.x, a23.y};
            float bv[4] = {b01.x, b01.y, b23.x, b23.y};
#pragma unroll
            for (int t = 0; t < 4; t++) {
                int cc = c + t;
                float hv = av[t] + bv[t] + e0 * S[cc] + e1 * S[HD + cc] + e2 * S[2 * HD + cc]
                         + e3 * S[3 * HD + cc] + qo * S[4 * HD + cc] + qm * S[5 * HD + cc]
                         + S[6 * HD + cc];
                hv = fmaxf(hv, 0.f);
                acc0 += hv * S[7 * HD + cc];
            }
        }
        {
            const float* S = sE[1];
            const __half2* pa = reinterpret_cast<const __half2*>(&ua1);
            const __half2* pb = reinterpret_cast<const __half2*>(&ub1);
            float2 a01 = __half22float2(pa[0]), a23 = __half22float2(pa[1]);
            float2 b01 = __half22float2(pb[0]), b23 = __half22float2(pb[1]);
            float av[4] = {a01.x, a01.y, a23.x, a23.y};
            float bv[4] = {b01.x, b01.y, b23.x, b23.y};
#pragma unroll
            for (int t = 0; t < 4; t++) {
                int cc = c + t;
                float hv = av[t] + bv[t] + e0 * S[cc] + e1 * S[HD + cc] + e2 * S[2 * HD + cc]
                         + e3 * S[3 * HD + cc] + qo * S[4 * HD + cc] + qm * S[5 * HD + cc]
                         + S[6 * HD + cc];
                hv = fmaxf(hv, 0.f);
                acc1 += hv * S[7 * HD + cc];
            }
        }
#pragma unroll
        for (int off = 16; off; off >>= 1) {
            acc0 += __shfl_xor_sync(0xffffffffu, acc0, off);
            acc1 += __shfl_xor_sync(0xffffffffu, acc1, off);
        }
        if (lane == 0) {
            qhat[e] = acc0 + eb2r;
            elog[e] = acc1 + eb2a;
        }
    }
}

// ---------------- launch ----------------
extern "C" void kernel_launch(void* const* d_in, const int* in_sizes, int n_in,
                              void* d_out, int out_size)
{
    const int*   ei           = (const int*)d_in[0];   // edge_index is int32 (jax x64 disabled)
    const float* node_static  = (const float*)d_in[1];
    const float* edge_static  = (const float*)d_in[2];
    const float* p_obs        = (const float*)d_in[3];
    const float* q_obs        = (const float*)d_in[4];
    const int*   p_mask       = (const int*)d_in[5];
    const int*   q_mask       = (const int*)d_in[6];
    const float* W_enc        = (const float*)d_in[7];
    const float* b_enc        = (const float*)d_in[8];
    const float* W_self       = (const float*)d_in[9];
    const float* W_neigh      = (const float*)d_in[10];
    const float* b_gnn        = (const float*)d_in[11];
    const float* nrW1 = (const float*)d_in[12]; const float* nrb1 = (const float*)d_in[13];
    const float* nrW2 = (const float*)d_in[14]; const float* nrb2 = (const float*)d_in[15];
    const float* naW1 = (const float*)d_in[16]; const float* nab1 = (const float*)d_in[17];
    const float* naW2 = (const float*)d_in[18]; const float* nab2 = (const float*)d_in[19];
    const float* erW1 = (const float*)d_in[20]; const float* erb1 = (const float*)d_in[21];
    const float* erW2 = (const float*)d_in[22]; const float* erb2 = (const float*)d_in[23];
    const float* eaW1 = (const float*)d_in[24]; const float* eab1 = (const float*)d_in[25];
    const float* eaW2 = (const float*)d_in[26]; const float* eab2 = (const float*)d_in[27];

    int n  = in_sizes[3];  // N (p_obs)
    int ne = in_sizes[4];  // E (q_obs)

    float* out   = (float*)d_out;
    float* p_hat = out;
    float* q_hat = out + n;
    float* nlog  = out + n + ne;
    float* elog  = out + 2 * n + ne;

    float *gx, *gy, *gagg;
    __half *gpa, *gpb, *gxh0, *gxh1;
    uint32_t* gpw;
    cudaGetSymbolAddress((void**)&gx,   g_x);
    cudaGetSymbolAddress((void**)&gy,   g_y);
    cudaGetSymbolAddress((void**)&gagg, g_agg);
    cudaGetSymbolAddress((void**)&gpa,  g_pairAh);
    cudaGetSymbolAddress((void**)&gpb,  g_pairBh);
    cudaGetSymbolAddress((void**)&gxh0, g_xh0);
    cudaGetSymbolAddress((void**)&gxh1, g_xh1);
    cudaGetSymbolAddress((void**)&gpw,  g_pw);

    const int SM_DUALA = 2 * 8448 * 4;  // 67584 B
    const int SM_ONEA  = 8448 * 4;      // 33792 B
    cudaFuncSetAttribute(k_gemm_dualA, cudaFuncAttributeMaxDynamicSharedMemorySize, SM_DUALA);
    cudaFuncSetAttribute(k_gemm_heads, cudaFuncAttributeMaxDynamicSharedMemorySize, SM_ONEA);

    // pre-pack the 12 weight matrices: 0-2 Wself[l], 3-5 Wneigh[l], 6 nrW1, 7 naW1,
    // 8 erW1 top, 9 erW1 bot, 10 eaW1 top, 11 eaW1 bot
    PackSrc ps;
    ps.s[0] = W_self;                ps.s[1] = W_self + 16384;  ps.s[2] = W_self + 32768;
    ps.s[3] = W_neigh;               ps.s[4] = W_neigh + 16384; ps.s[5] = W_neigh + 32768;
    ps.s[6] = nrW1;                  ps.s[7] = naW1;
    ps.s[8] = erW1;                  ps.s[9] = erW1 + 16384;
    ps.s[10] = eaW1;                 ps.s[11] = eaW1 + 16384;
    k_pack<<<(12 * 16384 + 255) / 256, 256>>>(ps);

    k_encoder<<<(n * HD + 255) / 256, 256>>>(node_static, p_obs, p_mask, W_enc, b_enc,
                                             gx, gxh0, n);
    k_zero_deg<<<(n + 255) / 256, 256>>>(n);
    k_deg<<<(ne + 255) / 256, 256>>>(ei, ne);
    int nb = (n + 1023) / 1024;
    k_scan_local<<<nb, 1024>>>(n);
    k_scan_bsum<<<1, 32>>>(nb);
    k_scan_final<<<(n + 255) / 256, 256>>>(n);
    k_fill<<<(ne + 255) / 256, 256>>>(ei, ne);

    int gblocks = (n + 63) / 64;
    const float* xin = gx;
    float* xout = gy;
    __half* xh_in = gxh0;
    __half* xh_out = gxh1;
    for (int l = 0; l < 3; l++) {
        k_agg<<<(n * 32 + 255) / 256, 256>>>(xh_in, gagg, n);
        // last layer doesn't need an fp16 shadow (heads read fp32)
        __half* sh = (l < 2) ? xh_out : (__half*)nullptr;
        k_gemm_dualA<<<gblocks, 256, SM_DUALA>>>(xin, gagg,
                                                 gpw + l * 16384, gpw + (3 + l) * 16384,
                                                 b_gnn + l * HD, xout, sh, n, (l < 2) ? 1 : 0);
        const float* t = xin;
        xin = xout;
        xout = (float*)t;
        __half* th = xh_in;
        xh_in = xh_out;
        xh_out = th;
    }
    const float* xf = xin;  // final node embeddings (g_y); g_x and g_agg now free

    // all head GEMMs in one launch: nodehead hidden -> gx/gagg; pair tables -> gpa/gpb
    HeadArgs ha;
    ha.pw0[0] = gpw + 6 * 16384;  ha.pw1[0] = gpw + 7 * 16384;
    ha.pw0[1] = gpw + 8 * 16384;  ha.pw1[1] = gpw + 9 * 16384;
    ha.pw0[2] = gpw + 10 * 16384; ha.pw1[2] = gpw + 11 * 16384;
    ha.b0 = nrb1; ha.b1 = nab1;
    ha.o0f = gx;  ha.o1f = gagg;
    ha.pa = gpa;  ha.pb = gpb;
    k_gemm_heads<<<gblocks, 256, SM_ONEA>>>(xf, ha, n);

    k_headreduce<<<(n * 32 + 255) / 256, 256>>>(gx, nrW2, nrb2, gagg, naW2, nab2, p_hat, nlog, n);

    int eblocks = (ne + 8 * EPW - 1) / (8 * EPW);
    k_edge<<<eblocks, 256>>>(ei, edge_static, q_obs, q_mask,
                             erW1, erb1, erW2, erb2,
                             eaW1, eab1, eaW2, eab2,
                             q_hat, elog, ne);
}

// round 14
// speedup vs baseline: 1.4808x; 1.2244x over previous
#include <cuda_runtime.h>
#include <cuda_fp16.h>
#include <cstdint>

#define NN 100000
#define NE 600000
#define HD 128
#define EPW 16   // edges per warp in k_edge

// ---------------- scratch (static device memory; no allocs) ----------------
static __device__ float  g_y  [NN * HD];          // fp32 final embeddings (layer 2 out)
static __device__ float  g_agg[NN * HD];
static __device__ float  g_h0 [NN * HD];          // node-head hidden A
static __device__ float  g_h1 [NN * HD];          // node-head hidden B
static __device__ __half g_xh0[NN * HD];          // fp16 x (ping)
static __device__ __half g_xh1[NN * HD];          // fp16 x (pong)
static __device__ __half g_pairAh[NN * 256];      // [node][0:128)=er A-part, [128:256)=ea A-part
static __device__ __half g_pairBh[NN * 256];      // [node][0:128)=er B-part, [128:256)=ea B-part
static __device__ int    g_deg[NN];
static __device__ int    g_rowptr[NN + 1];
static __device__ int    g_cursor[NN];
static __device__ int    g_col[2 * NE];
static __device__ float  g_invdeg[NN];
static __device__ int    g_tmp[NN];
static __device__ int    g_bsum[128];
static __device__ uint32_t g_pwh[12 * 8192];      // packed fp16 weights, m16n8k16 frag order

// ---------------- fp16 MMA helpers ----------------
#define MMAH(c, a0, a1, a2, a3, b0, b1)                                       \
    asm volatile("mma.sync.aligned.m16n8k16.row.col.f32.f16.f16.f32 "         \
                 "{%0,%1,%2,%3},{%4,%5,%6,%7},{%8,%9},{%0,%1,%2,%3};"         \
                 : "+f"((c)[0]), "+f"((c)[1]), "+f"((c)[2]), "+f"((c)[3])     \
                 : "r"(a0), "r"(a1), "r"(a2), "r"(a3), "r"(b0), "r"(b1))

#define LDSM4(a0, a1, a2, a3, addr)                                           \
    asm volatile("ldmatrix.sync.aligned.m8n8.x4.shared.b16 {%0,%1,%2,%3}, [%4];" \
                 : "=r"(a0), "=r"(a1), "=r"(a2), "=r"(a3) : "r"(addr))

// smem A layout: 64 rows x 136 halves (stride 136 halves = 272B -> ldmatrix conflict-free)
#define SROW 136
#define SROW_U32 68
#define SA_BYTES (64 * SROW * 2)   // 17408

// ---------------- weight pre-pack: 12 matrices into fp16 m16n8k16 fragment order ----------------
// layout: [m][ ((ks*16 + nt)*32 + lane)*2 + reg ] ; reg0 = k in [ks*16, +8), reg1 = +8
struct PackSrc { const float* s[12]; };

__global__ void k_packh(PackSrc ps)
{
    int idx = blockIdx.x * 256 + threadIdx.x;
    if (idx >= 12 * 8192) return;
    int m = idx >> 13, e = idx & 8191;
    int reg = e & 1;
    int lane = (e >> 1) & 31;
    int knt = e >> 6;                // ks*16 + nt
    int ks = knt >> 4, nt = knt & 15;
    int tg = lane & 3, gid = lane >> 2;
    int k = ks * 16 + reg * 8 + tg * 2;
    int n = nt * 8 + gid;
    const float* W = ps.s[m];
    __half2 h = __floats2half2_rn(__ldg(&W[k * HD + n]), __ldg(&W[(k + 1) * HD + n]));
    g_pwh[m * 8192 + e] = *reinterpret_cast<uint32_t*>(&h);
}

// ---------------- encoder: xh = fp16(node_feats(8) @ W_enc + b_enc) ----------------
__global__ void k_encoder(const float* __restrict__ ns, const float* __restrict__ pobs,
                          const int* __restrict__ pmask, const float* __restrict__ Wenc,
                          const float* __restrict__ benc, __half* __restrict__ xh, int n)
{
    __shared__ float sW[8 * HD];
    __shared__ float sb[HD];
    for (int i = threadIdx.x; i < 8 * HD; i += blockDim.x) sW[i] = Wenc[i];
    for (int i = threadIdx.x; i < HD; i += blockDim.x) sb[i] = benc[i];
    __syncthreads();
    int idx = blockIdx.x * blockDim.x + threadIdx.x;
    if (idx >= n * HD) return;
    int node = idx >> 7, h = idx & 127;
    float f0 = ns[node * 6 + 0], f1 = ns[node * 6 + 1], f2 = ns[node * 6 + 2];
    float f3 = ns[node * 6 + 3], f4 = ns[node * 6 + 4], f5 = ns[node * 6 + 5];
    float f6 = pobs[node];
    float f7 = (float)pmask[node];
    float o = sb[h];
    o += f0 * sW[0 * HD + h] + f1 * sW[1 * HD + h] + f2 * sW[2 * HD + h] + f3 * sW[3 * HD + h];
    o += f4 * sW[4 * HD + h] + f5 * sW[5 * HD + h] + f6 * sW[6 * HD + h] + f7 * sW[7 * HD + h];
    xh[idx] = __float2half_rn(o);
}

// ---------------- CSR build ----------------
__global__ void k_zero_deg(int n)
{
    int i = blockIdx.x * blockDim.x + threadIdx.x;
    if (i < n) g_deg[i] = 0;
}

__global__ void k_deg(const int* __restrict__ ei, int ne)
{
    int e = blockIdx.x * blockDim.x + threadIdx.x;
    if (e >= ne) return;
    int s = ei[e], d = ei[ne + e];
    atomicAdd(&g_deg[s], 1);
    atomicAdd(&g_deg[d], 1);
}

__global__ void k_scan_local(int n)
{
    __shared__ int sh[1024];
    int t = threadIdx.x;
    int i = blockIdx.x * 1024 + t;
    int v = (i < n) ? g_deg[i] : 0;
    sh[t] = v;
    __syncthreads();
    for (int off = 1; off < 1024; off <<= 1) {
        int tv = (t >= off) ? sh[t - off] : 0;
        __syncthreads();
        sh[t] += tv;
        __syncthreads();
    }
    if (i < n) g_tmp[i] = sh[t];
    if (t == 1023) g_bsum[blockIdx.x] = sh[1023];
}

__global__ void k_scan_bsum(int nb)
{
    if (threadIdx.x == 0) {
        int acc = 0;
        for (int b = 0; b < nb; b++) { int tv = g_bsum[b]; g_bsum[b] = acc; acc += tv; }
    }
}

__global__ void k_scan_final(int n)
{
    int i = blockIdx.x * blockDim.x + threadIdx.x;
    if (i >= n) return;
    int incl = g_tmp[i] + g_bsum[i >> 10];
    g_rowptr[i + 1] = incl;
    int d = g_deg[i];
    g_cursor[i] = incl - d;
    g_invdeg[i] = 1.0f / (float)(d > 0 ? d : 1);
    if (i == 0) g_rowptr[0] = 0;
}

__global__ void k_fill(const int* __restrict__ ei, int ne)
{
    int e = blockIdx.x * blockDim.x + threadIdx.x;
    if (e >= ne) return;
    int s = ei[e], d = ei[ne + e];
    int p = atomicAdd(&g_cursor[d], 1);
    g_col[p] = s;
    int q = atomicAdd(&g_cursor[s], 1);
    g_col[q] = d;
}

// ---------------- mean aggregation: one warp per node, fp16 gathers, x4 unrolled ----------------
__global__ void k_agg(const __half* __restrict__ xh, float* __restrict__ agg, int n)
{
    int w = (blockIdx.x * blockDim.x + threadIdx.x) >> 5;
    int lane = threadIdx.x & 31;
    if (w >= n) return;
    int beg = g_rowptr[w], end = g_rowptr[w + 1];
    float acc0 = 0.f, acc1 = 0.f, acc2 = 0.f, acc3 = 0.f;
    int i = beg;
    int c = lane * 4;
    for (; i + 4 <= end; i += 4) {
        int n0 = g_col[i], n1 = g_col[i + 1], n2 = g_col[i + 2], n3 = g_col[i + 3];
        uint2 u0 = *reinterpret_cast<const uint2*>(&xh[(size_t)n0 * HD + c]);
        uint2 u1 = *reinterpret_cast<const uint2*>(&xh[(size_t)n1 * HD + c]);
        uint2 u2 = *reinterpret_cast<const uint2*>(&xh[(size_t)n2 * HD + c]);
        uint2 u3 = *reinterpret_cast<const uint2*>(&xh[(size_t)n3 * HD + c]);
        const __half2* p0 = reinterpret_cast<const __half2*>(&u0);
        const __half2* p1 = reinterpret_cast<const __half2*>(&u1);
        const __half2* p2 = reinterpret_cast<const __half2*>(&u2);
        const __half2* p3 = reinterpret_cast<const __half2*>(&u3);
        float2 a0 = __half22float2(p0[0]), a1 = __half22float2(p0[1]);
        float2 b0 = __half22float2(p1[0]), b1 = __half22float2(p1[1]);
        float2 c0 = __half22float2(p2[0]), c1 = __half22float2(p2[1]);
        float2 d0 = __half22float2(p3[0]), d1 = __half22float2(p3[1]);
        acc0 += a0.x + b0.x + c0.x + d0.x;
        acc1 += a0.y + b0.y + c0.y + d0.y;
        acc2 += a1.x + b1.x + c1.x + d1.x;
        acc3 += a1.y + b1.y + c1.y + d1.y;
    }
    for (; i < end; i++) {
        int nb = g_col[i];
        uint2 u = *reinterpret_cast<const uint2*>(&xh[(size_t)nb * HD + c]);
        const __half2* p = reinterpret_cast<const __half2*>(&u);
        float2 a0 = __half22float2(p[0]), a1 = __half22float2(p[1]);
        acc0 += a0.x; acc1 += a0.y; acc2 += a1.x; acc3 += a1.y;
    }
    float sc = g_invdeg[w];
    float4 r = make_float4(acc0 * sc, acc1 * sc, acc2 * sc, acc3 * sc);
    *reinterpret_cast<float4*>(&agg[(size_t)w * HD + c]) = r;
}

// ---------------- GNN layer GEMM (fp16 MMA): C = op(xh@W0 + agg@W1 + bias) ----------------
// A from fp16 shadow, A2 from fp32 agg (cvt). Outputs: fp32 C (nullable) and/or fp16 Ch (nullable).
__global__ void __launch_bounds__(256) k_gemm_dualA(
    const __half* __restrict__ Ah, const float* __restrict__ A2,
    const uint32_t* __restrict__ pW0, const uint32_t* __restrict__ pW1,
    const float* __restrict__ bias, float* __restrict__ C,
    __half* __restrict__ Ch, int n, int relu)
{
    extern __shared__ uint32_t sm[];
    uint32_t* sA  = sm;                 // 64 x 136 halves
    uint32_t* sA2 = sm + 64 * SROW_U32;

    int tid = threadIdx.x;
    int row0 = blockIdx.x * 64;
    // stage: 64 rows x 64 half2-cols
    for (int idx = tid; idx < 4096; idx += 256) {
        int r = idx >> 6, c2 = idx & 63;
        int gr = row0 + r;
        bool ok = gr < n;
        uint32_t va = ok ? reinterpret_cast<const uint32_t*>(Ah)[(size_t)gr * 64 + c2] : 0u;
        sA[r * SROW_U32 + c2] = va;
        float2 f = ok ? *reinterpret_cast<const float2*>(&A2[(size_t)gr * HD + c2 * 2])
                      : make_float2(0.f, 0.f);
        __half2 h = __floats2half2_rn(f.x, f.y);
        sA2[r * SROW_U32 + c2] = *reinterpret_cast<uint32_t*>(&h);
    }
    __syncthreads();

    int wid = tid >> 5, lane = tid & 31;
    int tg = lane & 3, gid = lane >> 2;
    int nt0 = wid * 2;
    int rowA = lane & 15;
    int hi8 = (lane >> 4) << 3;

    uint32_t sAbase  = (uint32_t)__cvta_generic_to_shared(sA);
    uint32_t sA2base = (uint32_t)__cvta_generic_to_shared(sA2);

    float acc[4][8];
#pragma unroll
    for (int s = 0; s < 4; s++)
#pragma unroll
        for (int j = 0; j < 8; j++) acc[s][j] = 0.f;

    const uint2* B0 = reinterpret_cast<const uint2*>(pW0) + (nt0 * 32 + lane);
    const uint2* B1 = reinterpret_cast<const uint2*>(pW1) + (nt0 * 32 + lane);

#pragma unroll 2
    for (int ks = 0; ks < 8; ks++) {
        uint2 b0 = __ldg(B0 + ks * 512);
        uint2 b1 = __ldg(B0 + ks * 512 + 32);
        uint2 d0 = __ldg(B1 + ks * 512);
        uint2 d1 = __ldg(B1 + ks * 512 + 32);
        uint32_t coff = (ks * 16 + hi8) * 2;
#pragma unroll
        for (int s = 0; s < 4; s++) {
            uint32_t radd = ((s * 16 + rowA) * SROW) * 2 + coff;
            uint32_t a0, a1, a2, a3;
            LDSM4(a0, a1, a2, a3, sAbase + radd);
            MMAH(acc[s], a0, a1, a2, a3, b0.x, b0.y);
            MMAH(acc[s] + 4, a0, a1, a2, a3, b1.x, b1.y);
            uint32_t e0, e1, e2, e3;
            LDSM4(e0, e1, e2, e3, sA2base + radd);
            MMAH(acc[s], e0, e1, e2, e3, d0.x, d0.y);
            MMAH(acc[s] + 4, e0, e1, e2, e3, d1.x, d1.y);
        }
    }

    int cbase = wid * 16;
    float bb[4];
    bb[0] = __ldg(&bias[cbase + 2 * tg]);
    bb[1] = __ldg(&bias[cbase + 2 * tg + 1]);
    bb[2] = __ldg(&bias[cbase + 8 + 2 * tg]);
    bb[3] = __ldg(&bias[cbase + 8 + 2 * tg + 1]);
#pragma unroll
    for (int s = 0; s < 4; s++) {
#pragma unroll
        for (int t = 0; t < 2; t++) {
            int col = cbase + t * 8 + 2 * tg;
            int r = row0 + s * 16 + gid;
            float v0 = acc[s][t * 4 + 0] + bb[t * 2 + 0];
            float v1 = acc[s][t * 4 + 1] + bb[t * 2 + 1];
            float v2 = acc[s][t * 4 + 2] + bb[t * 2 + 0];
            float v3 = acc[s][t * 4 + 3] + bb[t * 2 + 1];
            if (relu) {
                v0 = fmaxf(v0, 0.f); v1 = fmaxf(v1, 0.f);
                v2 = fmaxf(v2, 0.f); v3 = fmaxf(v3, 0.f);
            }
            if (r < n) {
                if (C)
                    *reinterpret_cast<float2*>(&C[(size_t)r * HD + col]) = make_float2(v0, v1);
                if (Ch)
                    *reinterpret_cast<__half2*>(&Ch[(size_t)r * HD + col]) = __floats2half2_rn(v0, v1);
            }
            if (r + 8 < n) {
                if (C)
                    *reinterpret_cast<float2*>(&C[(size_t)(r + 8) * HD + col]) = make_float2(v2, v3);
                if (Ch)
                    *reinterpret_cast<__half2*>(&Ch[(size_t)(r + 8) * HD + col]) = __floats2half2_rn(v2, v3);
            }
        }
    }
}

// ---------------- merged head GEMMs (fp16 MMA): stage xf once, run 3 weight-pairs ----------------
struct HeadArgs {
    const uint32_t* pw0[3];
    const uint32_t* pw1[3];
    const float* b0;
    const float* b1;
    float* o0f;
    float* o1f;
    __half* pa;
    __half* pb;
};

__device__ __forceinline__ void mma_pair_h(
    uint32_t sAbase,
    const uint32_t* __restrict__ pW0, const uint32_t* __restrict__ pW1,
    int lane, int nt0, int rowA, int hi8, float acc0[4][8], float acc1[4][8])
{
#pragma unroll
    for (int s = 0; s < 4; s++)
#pragma unroll
        for (int j = 0; j < 8; j++) { acc0[s][j] = 0.f; acc1[s][j] = 0.f; }

    const uint2* B0 = reinterpret_cast<const uint2*>(pW0) + (nt0 * 32 + lane);
    const uint2* B1 = reinterpret_cast<const uint2*>(pW1) + (nt0 * 32 + lane);

#pragma unroll 2
    for (int ks = 0; ks < 8; ks++) {
        uint2 b0 = __ldg(B0 + ks * 512);
        uint2 b1 = __ldg(B0 + ks * 512 + 32);
        uint2 d0 = __ldg(B1 + ks * 512);
        uint2 d1 = __ldg(B1 + ks * 512 + 32);
        uint32_t coff = (ks * 16 + hi8) * 2;
#pragma unroll
        for (int s = 0; s < 4; s++) {
            uint32_t radd = ((s * 16 + rowA) * SROW) * 2 + coff;
            uint32_t a0, a1, a2, a3;
            LDSM4(a0, a1, a2, a3, sAbase + radd);
            MMAH(acc0[s], a0, a1, a2, a3, b0.x, b0.y);
            MMAH(acc0[s] + 4, a0, a1, a2, a3, b1.x, b1.y);
            MMAH(acc1[s], a0, a1, a2, a3, d0.x, d0.y);
            MMAH(acc1[s] + 4, a0, a1, a2, a3, d1.x, d1.y);
        }
    }
}

__global__ void __launch_bounds__(256) k_gemm_heads(
    const float* __restrict__ A, HeadArgs ha, int n)
{
    extern __shared__ uint32_t sm[];
    uint32_t* sA = sm;

    int tid = threadIdx.x;
    int row0 = blockIdx.x * 64;
    for (int idx = tid; idx < 4096; idx += 256) {
        int r = idx >> 6, c2 = idx & 63;
        int gr = row0 + r;
        float2 f = (gr < n) ? *reinterpret_cast<const float2*>(&A[(size_t)gr * HD + c2 * 2])
                            : make_float2(0.f, 0.f);
        __half2 h = __floats2half2_rn(f.x, f.y);
        sA[r * SROW_U32 + c2] = *reinterpret_cast<uint32_t*>(&h);
    }
    __syncthreads();

    int wid = tid >> 5, lane = tid & 31;
    int tg = lane & 3, gid = lane >> 2;
    int nt0 = wid * 2;
    int cbase = wid * 16;
    int rowA = lane & 15;
    int hi8 = (lane >> 4) << 3;
    uint32_t sAbase = (uint32_t)__cvta_generic_to_shared(sA);

    float acc0[4][8], acc1[4][8];

    // ---- phase 0: nodehead hidden, fp32 + bias + relu, stride 128 ----
    mma_pair_h(sAbase, ha.pw0[0], ha.pw1[0], lane, nt0, rowA, hi8, acc0, acc1);
    {
        float bb0[4], bb1[4];
        bb0[0] = __ldg(&ha.b0[cbase + 2 * tg]);
        bb0[1] = __ldg(&ha.b0[cbase + 2 * tg + 1]);
        bb0[2] = __ldg(&ha.b0[cbase + 8 + 2 * tg]);
        bb0[3] = __ldg(&ha.b0[cbase + 8 + 2 * tg + 1]);
        bb1[0] = __ldg(&ha.b1[cbase + 2 * tg]);
        bb1[1] = __ldg(&ha.b1[cbase + 2 * tg + 1]);
        bb1[2] = __ldg(&ha.b1[cbase + 8 + 2 * tg]);
        bb1[3] = __ldg(&ha.b1[cbase + 8 + 2 * tg + 1]);
#pragma unroll
        for (int s = 0; s < 4; s++) {
#pragma unroll
            for (int t = 0; t < 2; t++) {
                int col = cbase + t * 8 + 2 * tg;
                int r = row0 + s * 16 + gid;
                float u0 = fmaxf(acc0[s][t * 4 + 0] + bb0[t * 2 + 0], 0.f);
                float u1 = fmaxf(acc0[s][t * 4 + 1] + bb0[t * 2 + 1], 0.f);
                float u2 = fmaxf(acc0[s][t * 4 + 2] + bb0[t * 2 + 0], 0.f);
                float u3 = fmaxf(acc0[s][t * 4 + 3] + bb0[t * 2 + 1], 0.f);
                float v0 = fmaxf(acc1[s][t * 4 + 0] + bb1[t * 2 + 0], 0.f);
                float v1 = fmaxf(acc1[s][t * 4 + 1] + bb1[t * 2 + 1], 0.f);
                float v2 = fmaxf(acc1[s][t * 4 + 2] + bb1[t * 2 + 0], 0.f);
                float v3 = fmaxf(acc1[s][t * 4 + 3] + bb1[t * 2 + 1], 0.f);
                if (r < n) {
                    *reinterpret_cast<float2*>(&ha.o0f[(size_t)r * HD + col]) = make_float2(u0, u1);
                    *reinterpret_cast<float2*>(&ha.o1f[(size_t)r * HD + col]) = make_float2(v0, v1);
                }
                if (r + 8 < n) {
                    *reinterpret_cast<float2*>(&ha.o0f[(size_t)(r + 8) * HD + col]) = make_float2(u2, u3);
                    *reinterpret_cast<float2*>(&ha.o1f[(size_t)(r + 8) * HD + col]) = make_float2(v2, v3);
                }
            }
        }
    }

    // ---- phases 1,2: pair tables, fp16, stride 256, col offset 0 / 128 ----
#pragma unroll 1
    for (int ph = 1; ph < 3; ph++) {
        mma_pair_h(sAbase, ha.pw0[ph], ha.pw1[ph], lane, nt0, rowA, hi8, acc0, acc1);
        int coff = (ph - 1) * 128;
#pragma unroll
        for (int s = 0; s < 4; s++) {
#pragma unroll
            for (int t = 0; t < 2; t++) {
                int col = coff + cbase + t * 8 + 2 * tg;
                int r = row0 + s * 16 + gid;
                if (r < n) {
                    *reinterpret_cast<__half2*>(&ha.pa[(size_t)r * 256 + col]) =
                        __floats2half2_rn(acc0[s][t * 4 + 0], acc0[s][t * 4 + 1]);
                    *reinterpret_cast<__half2*>(&ha.pb[(size_t)r * 256 + col]) =
                        __floats2half2_rn(acc1[s][t * 4 + 0], acc1[s][t * 4 + 1]);
                }
                if (r + 8 < n) {
                    *reinterpret_cast<__half2*>(&ha.pa[(size_t)(r + 8) * 256 + col]) =
                        __floats2half2_rn(acc0[s][t * 4 + 2], acc0[s][t * 4 + 3]);
                    *reinterpret_cast<__half2*>(&ha.pb[(size_t)(r + 8) * 256 + col]) =
                        __floats2half2_rn(acc1[s][t * 4 + 2], acc1[s][t * 4 + 3]);
                }
            }
        }
    }
}

// ---------------- node-head second stage: out = hidden . W2 + b2 (two heads) ----------------
__global__ void k_headreduce(const float* __restrict__ ha, const float* __restrict__ w2a,
                             const float* __restrict__ b2a,
                             const float* __restrict__ hb, const float* __restrict__ w2b,
                             const float* __restrict__ b2b,
                             float* __restrict__ pa, float* __restrict__ pb, int n)
{
    __shared__ float swa[128], swb[128];
    int tid = threadIdx.x;
    if (tid < 128) { swa[tid] = w2a[tid]; swb[tid] = w2b[tid]; }
    __syncthreads();
    int node = (blockIdx.x * blockDim.x + tid) >> 5;
    int lane = tid & 31;
    if (node >= n) return;
    float4 va = *reinterpret_cast<const float4*>(&ha[(size_t)node * HD + lane * 4]);
    float4 wa = *reinterpret_cast<const float4*>(&swa[lane * 4]);
    float sa = va.x * wa.x + va.y * wa.y + va.z * wa.z + va.w * wa.w;
    float4 vb = *reinterpret_cast<const float4*>(&hb[(size_t)node * HD + lane * 4]);
    float4 wb = *reinterpret_cast<const float4*>(&swb[lane * 4]);
    float sb = vb.x * wb.x + vb.y * wb.y + vb.z * wb.z + vb.w * wb.w;
#pragma unroll
    for (int off = 16; off; off >>= 1) {
        sa += __shfl_xor_sync(0xffffffffu, sa, off);
        sb += __shfl_xor_sync(0xffffffffu, sb, off);
    }
    if (lane == 0) {
        pa[node] = sa + __ldg(&b2a[0]);
        pb[node] = sb + __ldg(&b2b[0]);
    }
}

// ---------------- edge heads: EPW edges per warp, fp16 pair tables ----------------
__global__ void k_edge(const int* __restrict__ ei,
                       const float* __restrict__ estat, const float* __restrict__ qobs,
                       const int* __restrict__ qmask,
                       const float* __restrict__ erW1, const float* __restrict__ erb1,
                       const float* __restrict__ erW2, const float* __restrict__ erb2,
                       const float* __restrict__ eaW1, const float* __restrict__ eab1,
                       const float* __restrict__ eaW2, const float* __restrict__ eab2,
                       float* __restrict__ qhat, float* __restrict__ elog, int ne)
{
    __shared__ float sE[2][8 * HD];  // per head: rows 0-5 = W1[256+r], 6 = b1, 7 = W2
    int tid = threadIdx.x;
    for (int idx = tid; idx < 2 * 8 * HD; idx += blockDim.x) {
        int h = idx / (8 * HD);
        int rem = idx - h * 8 * HD;
        int r = rem >> 7, c = rem & 127;
        const float* W1 = h ? eaW1 : erW1;
        const float* b1 = h ? eab1 : erb1;
        const float* W2 = h ? eaW2 : erW2;
        float v;
        if (r < 6) v = W1[(256 + r) * HD + c];
        else if (r == 6) v = b1[c];
        else v = W2[c];
        sE[h][rem] = v;
    }
    __syncthreads();

    int warpg = (blockIdx.x * blockDim.x + tid) >> 5;
    int lane = tid & 31;
    int ebase = warpg * EPW;
    if (ebase >= ne) return;
    int eend = min(ebase + EPW, ne);
    int c = lane * 4;
    float eb2r = __ldg(&erb2[0]);
    float eb2a = __ldg(&eab2[0]);

    for (int e = ebase; e < eend; e++) {
        int s = __ldg(&ei[e]), d = __ldg(&ei[ne + e]);
        const __half* srcA = &g_pairAh[(size_t)s * 256];
        const __half* dstB = &g_pairBh[(size_t)d * 256];
        uint2 ua0 = *reinterpret_cast<const uint2*>(&srcA[c]);
        uint2 ub0 = *reinterpret_cast<const uint2*>(&dstB[c]);
        uint2 ua1 = *reinterpret_cast<const uint2*>(&srcA[128 + c]);
        uint2 ub1 = *reinterpret_cast<const uint2*>(&dstB[128 + c]);

        float e0 = __ldg(&estat[e * 4 + 0]), e1 = __ldg(&estat[e * 4 + 1]);
        float e2 = __ldg(&estat[e * 4 + 2]), e3 = __ldg(&estat[e * 4 + 3]);
        float qo = __ldg(&qobs[e]), qm = (float)__ldg(&qmask[e]);

        float acc0 = 0.f, acc1 = 0.f;
        {
            const float* S = sE[0];
            const __half2* pa = reinterpret_cast<const __half2*>(&ua0);
            const __half2* pb = reinterpret_cast<const __half2*>(&ub0);
            float2 a01 = __half22float2(pa[0]), a23 = __half22float2(pa[1]);
            float2 b01 = __half22float2(pb[0]), b23 = __half22float2(pb[1]);
            float av[4] = {a01.x, a01.y, a23.x, a23.y};
            float bv[4] = {b01.x, b01.y, b23.x, b23.y};
#pragma unroll
            for (int t = 0; t < 4; t++) {
                int cc = c + t;
                float hv = av[t] + bv[t] + e0 * S[cc] + e1 * S[HD + cc] + e2 * S[2 * HD + cc]
                         + e3 * S[3 * HD + cc] + qo * S[4 * HD + cc] + qm * S[5 * HD + cc]
                         + S[6 * HD + cc];
                hv = fmaxf(hv, 0.f);
                acc0 += hv * S[7 * HD + cc];
            }
        }
        {
            const float* S = sE[1];
            const __half2* pa = reinterpret_cast<const __half2*>(&ua1);
            const __half2* pb = reinterpret_cast<const __half2*>(&ub1);
            float2 a01 = __half22float2(pa[0]), a23 = __half22float2(pa[1]);
            float2 b01 = __half22float2(pb[0]), b23 = __half22float2(pb[1]);
            float av[4] = {a01.x, a01.y, a23.x, a23.y};
            float bv[4] = {b01.x, b01.y, b23.x, b23.y};
#pragma unroll
            for (int t = 0; t < 4; t++) {
                int cc = c + t;
                float hv = av[t] + bv[t] + e0 * S[cc] + e1 * S[HD + cc] + e2 * S[2 * HD + cc]
                         + e3 * S[3 * HD + cc] + qo * S[4 * HD + cc] + qm * S[5 * HD + cc]
                         + S[6 * HD + cc];
                hv = fmaxf(hv, 0.f);
                acc1 += hv * S[7 * HD + cc];
            }
        }
#pragma unroll
        for (int off = 16; off; off >>= 1) {
            acc0 += __shfl_xor_sync(0xffffffffu, acc0, off);
            acc1 += __shfl_xor_sync(0xffffffffu, acc1, off);
        }
        if (lane == 0) {
            qhat[e] = acc0 + eb2r;
            elog[e] = acc1 + eb2a;
        }
    }
}

// ---------------- launch ----------------
extern "C" void kernel_launch(void* const* d_in, const int* in_sizes, int n_in,
                              void* d_out, int out_size)
{
    const int*   ei           = (const int*)d_in[0];   // edge_index is int32 (jax x64 disabled)
    const float* node_static  = (const float*)d_in[1];
    const float* edge_static  = (const float*)d_in[2];
    const float* p_obs        = (const float*)d_in[3];
    const float* q_obs        = (const float*)d_in[4];
    const int*   p_mask       = (const int*)d_in[5];
    const int*   q_mask       = (const int*)d_in[6];
    const float* W_enc        = (const float*)d_in[7];
    const float* b_enc        = (const float*)d_in[8];
    const float* W_self       = (const float*)d_in[9];
    const float* W_neigh      = (const float*)d_in[10];
    const float* b_gnn        = (const float*)d_in[11];
    const float* nrW1 = (const float*)d_in[12]; const float* nrb1 = (const float*)d_in[13];
    const float* nrW2 = (const float*)d_in[14]; const float* nrb2 = (const float*)d_in[15];
    const float* naW1 = (const float*)d_in[16]; const float* nab1 = (const float*)d_in[17];
    const float* naW2 = (const float*)d_in[18]; const float* nab2 = (const float*)d_in[19];
    const float* erW1 = (const float*)d_in[20]; const float* erb1 = (const float*)d_in[21];
    const float* erW2 = (const float*)d_in[22]; const float* erb2 = (const float*)d_in[23];
    const float* eaW1 = (const float*)d_in[24]; const float* eab1 = (const float*)d_in[25];
    const float* eaW2 = (const float*)d_in[26]; const float* eab2 = (const float*)d_in[27];

    int n  = in_sizes[3];  // N (p_obs)
    int ne = in_sizes[4];  // E (q_obs)

    float* out   = (float*)d_out;
    float* p_hat = out;
    float* q_hat = out + n;
    float* nlog  = out + n + ne;
    float* elog  = out + 2 * n + ne;

    float *gy, *gagg, *gh0, *gh1;
    __half *gpa, *gpb, *gxh0, *gxh1;
    uint32_t* gpwh;
    cudaGetSymbolAddress((void**)&gy,   g_y);
    cudaGetSymbolAddress((void**)&gagg, g_agg);
    cudaGetSymbolAddress((void**)&gh0,  g_h0);
    cudaGetSymbolAddress((void**)&gh1,  g_h1);
    cudaGetSymbolAddress((void**)&gpa,  g_pairAh);
    cudaGetSymbolAddress((void**)&gpb,  g_pairBh);
    cudaGetSymbolAddress((void**)&gxh0, g_xh0);
    cudaGetSymbolAddress((void**)&gxh1, g_xh1);
    cudaGetSymbolAddress((void**)&gpwh, g_pwh);

    const int SM_DUALA = 2 * SA_BYTES;  // 34816 B
    const int SM_ONEA  = SA_BYTES;      // 17408 B
    cudaFuncSetAttribute(k_gemm_dualA, cudaFuncAttributeMaxDynamicSharedMemorySize, SM_DUALA);
    cudaFuncSetAttribute(k_gemm_heads, cudaFuncAttributeMaxDynamicSharedMemorySize, SM_ONEA);

    // pre-pack the 12 weight matrices: 0-2 Wself[l], 3-5 Wneigh[l], 6 nrW1, 7 naW1,
    // 8 erW1 top, 9 erW1 bot, 10 eaW1 top, 11 eaW1 bot
    PackSrc ps;
    ps.s[0] = W_self;                ps.s[1] = W_self + 16384;  ps.s[2] = W_self + 32768;
    ps.s[3] = W_neigh;               ps.s[4] = W_neigh + 16384; ps.s[5] = W_neigh + 32768;
    ps.s[6] = nrW1;                  ps.s[7] = naW1;
    ps.s[8] = erW1;                  ps.s[9] = erW1 + 16384;
    ps.s[10] = eaW1;                 ps.s[11] = eaW1 + 16384;
    k_packh<<<(12 * 8192 + 255) / 256, 256>>>(ps);

    k_encoder<<<(n * HD + 255) / 256, 256>>>(node_static, p_obs, p_mask, W_enc, b_enc, gxh0, n);
    k_zero_deg<<<(n + 255) / 256, 256>>>(n);
    k_deg<<<(ne + 255) / 256, 256>>>(ei, ne);
    int nb = (n + 1023) / 1024;
    k_scan_local<<<nb, 1024>>>(n);
    k_scan_bsum<<<1, 32>>>(nb);
    k_scan_final<<<(n + 255) / 256, 256>>>(n);
    k_fill<<<(ne + 255) / 256, 256>>>(ei, ne);

    int gblocks = (n + 63) / 64;
    __half* xh_in = gxh0;
    __half* xh_out = gxh1;
    for (int l = 0; l < 3; l++) {
        k_agg<<<(n * 32 + 255) / 256, 256>>>(xh_in, gagg, n);
        // layers 0,1: fp16 shadow only (with relu); layer 2: fp32 only (no relu)
        float* cf = (l < 2) ? (float*)nullptr : gy;
        __half* ch = (l < 2) ? xh_out : (__half*)nullptr;
        k_gemm_dualA<<<gblocks, 256, SM_DUALA>>>(xh_in, gagg,
                                                 gpwh + l * 8192, gpwh + (3 + l) * 8192,
                                                 b_gnn + l * HD, cf, ch, n, (l < 2) ? 1 : 0);
        __half* th = xh_in;
        xh_in = xh_out;
        xh_out = th;
    }
    const float* xf = gy;  // final node embeddings (fp32)

    // all head GEMMs in one launch: nodehead hidden -> gh0/gh1; pair tables -> gpa/gpb
    HeadArgs ha;
    ha.pw0[0] = gpwh + 6 * 8192;  ha.pw1[0] = gpwh + 7 * 8192;
    ha.pw0[1] = gpwh + 8 * 8192;  ha.pw1[1] = gpwh + 9 * 8192;
    ha.pw0[2] = gpwh + 10 * 8192; ha.pw1[2] = gpwh + 11 * 8192;
    ha.b0 = nrb1; ha.b1 = nab1;
    ha.o0f = gh0; ha.o1f = gh1;
    ha.pa = gpa;  ha.pb = gpb;
    k_gemm_heads<<<gblocks, 256, SM_ONEA>>>(xf, ha, n);

    k_headreduce<<<(n * 32 + 255) / 256, 256>>>(gh0, nrW2, nrb2, gh1, naW2, nab2, p_hat, nlog, n);

    int eblocks = (ne + 8 * EPW - 1) / (8 * EPW);
    k_edge<<<eblocks, 256>>>(ei, edge_static, q_obs, q_mask,
                             erW1, erb1, erW2, erb2,
                             eaW1, eab1, eaW2, eab2,
                             q_hat, elog, ne);
}

// round 15
// speedup vs baseline: 1.5150x; 1.0231x over previous
#include <cuda_runtime.h>
#include <cuda_fp16.h>
#include <cstdint>

#define NN 100000
#define NE 600000
#define HD 128
#define EPW 16   // edges per warp in k_edge

// ---------------- scratch (static device memory; no allocs) ----------------
static __device__ float  g_y  [NN * HD];          // fp32 final embeddings (layer 2 out)
static __device__ __half g_aggh[NN * HD];         // fp16 aggregation output
static __device__ __half g_xh0[NN * HD];          // fp16 x (ping)
static __device__ __half g_xh1[NN * HD];          // fp16 x (pong)
static __device__ __half g_pairAh[NN * 256];      // [node][0:128)=er A-part, [128:256)=ea A-part
static __device__ __half g_pairBh[NN * 256];      // [node][0:128)=er B-part, [128:256)=ea B-part
static __device__ int    g_deg[NN];
static __device__ int    g_rowptr[NN + 1];
static __device__ int    g_cursor[NN];
static __device__ int    g_col[2 * NE];
static __device__ float  g_invdeg[NN];
static __device__ int    g_tmp[NN];
static __device__ int    g_bsum[128];
static __device__ uint32_t g_pwh[12 * 8192];      // packed fp16 weights, m16n8k16 frag order

// ---------------- fp16 MMA helpers ----------------
#define MMAH(c, a0, a1, a2, a3, b0, b1)                                       \
    asm volatile("mma.sync.aligned.m16n8k16.row.col.f32.f16.f16.f32 "         \
                 "{%0,%1,%2,%3},{%4,%5,%6,%7},{%8,%9},{%0,%1,%2,%3};"         \
                 : "+f"((c)[0]), "+f"((c)[1]), "+f"((c)[2]), "+f"((c)[3])     \
                 : "r"(a0), "r"(a1), "r"(a2), "r"(a3), "r"(b0), "r"(b1))

#define LDSM4(a0, a1, a2, a3, addr)                                           \
    asm volatile("ldmatrix.sync.aligned.m8n8.x4.shared.b16 {%0,%1,%2,%3}, [%4];" \
                 : "=r"(a0), "=r"(a1), "=r"(a2), "=r"(a3) : "r"(addr))

// smem A layout: 64 rows x 136 halves (stride 136 halves = 272B -> ldmatrix conflict-free)
#define SROW 136
#define SROW_U32 68
#define SA_BYTES (64 * SROW * 2)   // 17408

// ---------------- weight pre-pack: 12 matrices into fp16 m16n8k16 fragment order ----------------
struct PackSrc { const float* s[12]; };

__global__ void k_packh(PackSrc ps)
{
    int idx = blockIdx.x * 256 + threadIdx.x;
    if (idx >= 12 * 8192) return;
    int m = idx >> 13, e = idx & 8191;
    int reg = e & 1;
    int lane = (e >> 1) & 31;
    int knt = e >> 6;                // ks*16 + nt
    int ks = knt >> 4, nt = knt & 15;
    int tg = lane & 3, gid = lane >> 2;
    int k = ks * 16 + reg * 8 + tg * 2;
    int n = nt * 8 + gid;
    const float* W = ps.s[m];
    __half2 h = __floats2half2_rn(__ldg(&W[k * HD + n]), __ldg(&W[(k + 1) * HD + n]));
    g_pwh[m * 8192 + e] = *reinterpret_cast<uint32_t*>(&h);
}

// ---------------- encoder: xh = fp16(node_feats(8) @ W_enc + b_enc) ----------------
__global__ void k_encoder(const float* __restrict__ ns, const float* __restrict__ pobs,
                          const int* __restrict__ pmask, const float* __restrict__ Wenc,
                          const float* __restrict__ benc, __half* __restrict__ xh, int n)
{
    __shared__ float sW[8 * HD];
    __shared__ float sb[HD];
    for (int i = threadIdx.x; i < 8 * HD; i += blockDim.x) sW[i] = Wenc[i];
    for (int i = threadIdx.x; i < HD; i += blockDim.x) sb[i] = benc[i];
    __syncthreads();
    int idx = blockIdx.x * blockDim.x + threadIdx.x;
    if (idx >= n * HD) return;
    int node = idx >> 7, h = idx & 127;
    float f0 = ns[node * 6 + 0], f1 = ns[node * 6 + 1], f2 = ns[node * 6 + 2];
    float f3 = ns[node * 6 + 3], f4 = ns[node * 6 + 4], f5 = ns[node * 6 + 5];
    float f6 = pobs[node];
    float f7 = (float)pmask[node];
    float o = sb[h];
    o += f0 * sW[0 * HD + h] + f1 * sW[1 * HD + h] + f2 * sW[2 * HD + h] + f3 * sW[3 * HD + h];
    o += f4 * sW[4 * HD + h] + f5 * sW[5 * HD + h] + f6 * sW[6 * HD + h] + f7 * sW[7 * HD + h];
    xh[idx] = __float2half_rn(o);
}

// ---------------- CSR build ----------------
__global__ void k_zero_deg(int n)
{
    int i = blockIdx.x * blockDim.x + threadIdx.x;
    if (i < n) g_deg[i] = 0;
}

__global__ void k_deg(const int* __restrict__ ei, int ne)
{
    int e = blockIdx.x * blockDim.x + threadIdx.x;
    if (e >= ne) return;
    int s = ei[e], d = ei[ne + e];
    atomicAdd(&g_deg[s], 1);
    atomicAdd(&g_deg[d], 1);
}

__global__ void k_scan_local(int n)
{
    __shared__ int sh[1024];
    int t = threadIdx.x;
    int i = blockIdx.x * 1024 + t;
    int v = (i < n) ? g_deg[i] : 0;
    sh[t] = v;
    __syncthreads();
    for (int off = 1; off < 1024; off <<= 1) {
        int tv = (t >= off) ? sh[t - off] : 0;
        __syncthreads();
        sh[t] += tv;
        __syncthreads();
    }
    if (i < n) g_tmp[i] = sh[t];
    if (t == 1023) g_bsum[blockIdx.x] = sh[1023];
}

__global__ void k_scan_bsum(int nb)
{
    if (threadIdx.x == 0) {
        int acc = 0;
        for (int b = 0; b < nb; b++) { int tv = g_bsum[b]; g_bsum[b] = acc; acc += tv; }
    }
}

__global__ void k_scan_final(int n)
{
    int i = blockIdx.x * blockDim.x + threadIdx.x;
    if (i >= n) return;
    int incl = g_tmp[i] + g_bsum[i >> 10];
    g_rowptr[i + 1] = incl;
    int d = g_deg[i];
    g_cursor[i] = incl - d;
    g_invdeg[i] = 1.0f / (float)(d > 0 ? d : 1);
    if (i == 0) g_rowptr[0] = 0;
}

__global__ void k_fill(const int* __restrict__ ei, int ne)
{
    int e = blockIdx.x * blockDim.x + threadIdx.x;
    if (e >= ne) return;
    int s = ei[e], d = ei[ne + e];
    int p = atomicAdd(&g_cursor[d], 1);
    g_col[p] = s;
    int q = atomicAdd(&g_cursor[s], 1);
    g_col[q] = d;
}

// ---------------- mean aggregation: one warp per node, fp16 in / fp16 out ----------------
__global__ void k_agg(const __half* __restrict__ xh, __half* __restrict__ agg, int n)
{
    int w = (blockIdx.x * blockDim.x + threadIdx.x) >> 5;
    int lane = threadIdx.x & 31;
    if (w >= n) return;
    int beg = g_rowptr[w], end = g_rowptr[w + 1];
    float acc0 = 0.f, acc1 = 0.f, acc2 = 0.f, acc3 = 0.f;
    int i = beg;
    int c = lane * 4;
    for (; i + 4 <= end; i += 4) {
        int n0 = g_col[i], n1 = g_col[i + 1], n2 = g_col[i + 2], n3 = g_col[i + 3];
        uint2 u0 = *reinterpret_cast<const uint2*>(&xh[(size_t)n0 * HD + c]);
        uint2 u1 = *reinterpret_cast<const uint2*>(&xh[(size_t)n1 * HD + c]);
        uint2 u2 = *reinterpret_cast<const uint2*>(&xh[(size_t)n2 * HD + c]);
        uint2 u3 = *reinterpret_cast<const uint2*>(&xh[(size_t)n3 * HD + c]);
        const __half2* p0 = reinterpret_cast<const __half2*>(&u0);
        const __half2* p1 = reinterpret_cast<const __half2*>(&u1);
        const __half2* p2 = reinterpret_cast<const __half2*>(&u2);
        const __half2* p3 = reinterpret_cast<const __half2*>(&u3);
        float2 a0 = __half22float2(p0[0]), a1 = __half22float2(p0[1]);
        float2 b0 = __half22float2(p1[0]), b1 = __half22float2(p1[1]);
        float2 c0 = __half22float2(p2[0]), c1 = __half22float2(p2[1]);
        float2 d0 = __half22float2(p3[0]), d1 = __half22float2(p3[1]);
        acc0 += a0.x + b0.x + c0.x + d0.x;
        acc1 += a0.y + b0.y + c0.y + d0.y;
        acc2 += a1.x + b1.x + c1.x + d1.x;
        acc3 += a1.y + b1.y + c1.y + d1.y;
    }
    for (; i < end; i++) {
        int nb = g_col[i];
        uint2 u = *reinterpret_cast<const uint2*>(&xh[(size_t)nb * HD + c]);
        const __half2* p = reinterpret_cast<const __half2*>(&u);
        float2 a0 = __half22float2(p[0]), a1 = __half22float2(p[1]);
        acc0 += a0.x; acc1 += a0.y; acc2 += a1.x; acc3 += a1.y;
    }
    float sc = g_invdeg[w];
    __half2 h01 = __floats2half2_rn(acc0 * sc, acc1 * sc);
    __half2 h23 = __floats2half2_rn(acc2 * sc, acc3 * sc);
    uint2 o;
    o.x = *reinterpret_cast<uint32_t*>(&h01);
    o.y = *reinterpret_cast<uint32_t*>(&h23);
    *reinterpret_cast<uint2*>(&agg[(size_t)w * HD + c]) = o;
}

// ---------------- GNN layer GEMM (fp16 MMA): C = op(xh@W0 + agg@W1 + bias) ----------------
__global__ void __launch_bounds__(256) k_gemm_dualA(
    const __half* __restrict__ Ah, const __half* __restrict__ A2h,
    const uint32_t* __restrict__ pW0, const uint32_t* __restrict__ pW1,
    const float* __restrict__ bias, float* __restrict__ C,
    __half* __restrict__ Ch, int n, int relu)
{
    extern __shared__ uint32_t sm[];
    uint32_t* sA  = sm;                 // 64 x 136 halves
    uint32_t* sA2 = sm + 64 * SROW_U32;

    int tid = threadIdx.x;
    int row0 = blockIdx.x * 64;
    for (int idx = tid; idx < 4096; idx += 256) {
        int r = idx >> 6, c2 = idx & 63;
        int gr = row0 + r;
        bool ok = gr < n;
        sA [r * SROW_U32 + c2] = ok ? reinterpret_cast<const uint32_t*>(Ah)[(size_t)gr * 64 + c2] : 0u;
        sA2[r * SROW_U32 + c2] = ok ? reinterpret_cast<const uint32_t*>(A2h)[(size_t)gr * 64 + c2] : 0u;
    }
    __syncthreads();

    int wid = tid >> 5, lane = tid & 31;
    int tg = lane & 3, gid = lane >> 2;
    int nt0 = wid * 2;
    int rowA = lane & 15;
    int hi8 = (lane >> 4) << 3;

    uint32_t sAbase  = (uint32_t)__cvta_generic_to_shared(sA);
    uint32_t sA2base = (uint32_t)__cvta_generic_to_shared(sA2);

    float acc[4][8];
#pragma unroll
    for (int s = 0; s < 4; s++)
#pragma unroll
        for (int j = 0; j < 8; j++) acc[s][j] = 0.f;

    const uint2* B0 = reinterpret_cast<const uint2*>(pW0) + (nt0 * 32 + lane);
    const uint2* B1 = reinterpret_cast<const uint2*>(pW1) + (nt0 * 32 + lane);

#pragma unroll 2
    for (int ks = 0; ks < 8; ks++) {
        uint2 b0 = __ldg(B0 + ks * 512);
        uint2 b1 = __ldg(B0 + ks * 512 + 32);
        uint2 d0 = __ldg(B1 + ks * 512);
        uint2 d1 = __ldg(B1 + ks * 512 + 32);
        uint32_t coff = (ks * 16 + hi8) * 2;
#pragma unroll
        for (int s = 0; s < 4; s++) {
            uint32_t radd = ((s * 16 + rowA) * SROW) * 2 + coff;
            uint32_t a0, a1, a2, a3;
            LDSM4(a0, a1, a2, a3, sAbase + radd);
            MMAH(acc[s], a0, a1, a2, a3, b0.x, b0.y);
            MMAH(acc[s] + 4, a0, a1, a2, a3, b1.x, b1.y);
            uint32_t e0, e1, e2, e3;
            LDSM4(e0, e1, e2, e3, sA2base + radd);
            MMAH(acc[s], e0, e1, e2, e3, d0.x, d0.y);
            MMAH(acc[s] + 4, e0, e1, e2, e3, d1.x, d1.y);
        }
    }

    int cbase = wid * 16;
    float bb[4];
    bb[0] = __ldg(&bias[cbase + 2 * tg]);
    bb[1] = __ldg(&bias[cbase + 2 * tg + 1]);
    bb[2] = __ldg(&bias[cbase + 8 + 2 * tg]);
    bb[3] = __ldg(&bias[cbase + 8 + 2 * tg + 1]);
#pragma unroll
    for (int s = 0; s < 4; s++) {
#pragma unroll
        for (int t = 0; t < 2; t++) {
            int col = cbase + t * 8 + 2 * tg;
            int r = row0 + s * 16 + gid;
            float v0 = acc[s][t * 4 + 0] + bb[t * 2 + 0];
            float v1 = acc[s][t * 4 + 1] + bb[t * 2 + 1];
            float v2 = acc[s][t * 4 + 2] + bb[t * 2 + 0];
            float v3 = acc[s][t * 4 + 3] + bb[t * 2 + 1];
            if (relu) {
                v0 = fmaxf(v0, 0.f); v1 = fmaxf(v1, 0.f);
                v2 = fmaxf(v2, 0.f); v3 = fmaxf(v3, 0.f);
            }
            if (r < n) {
                if (C)
                    *reinterpret_cast<float2*>(&C[(size_t)r * HD + col]) = make_float2(v0, v1);
                if (Ch)
                    *reinterpret_cast<__half2*>(&Ch[(size_t)r * HD + col]) = __floats2half2_rn(v0, v1);
            }
            if (r + 8 < n) {
                if (C)
                    *reinterpret_cast<float2*>(&C[(size_t)(r + 8) * HD + col]) = make_float2(v2, v3);
                if (Ch)
                    *reinterpret_cast<__half2*>(&Ch[(size_t)(r + 8) * HD + col]) = __floats2half2_rn(v2, v3);
            }
        }
    }
}

// ---------------- merged head GEMMs (fp16 MMA): stage xf once, 3 weight-pairs, fused W2 dot ----------------
// phase 0: nodehead hidden in registers -> bias+relu -> dot W2 -> p_hat/nlog (no hidden buffers)
// phases 1,2: pair tables, fp16, stride 256
struct HeadArgs {
    const uint32_t* pw0[3];
    const uint32_t* pw1[3];
    const float* b0;
    const float* b1;
    const float* w2a;
    const float* w2b;
    const float* b2a;
    const float* b2b;
    float* ph;   // p_hat
    float* nl;   // node_logits
    __half* pa;
    __half* pb;
};

__device__ __forceinline__ void mma_pair_h(
    uint32_t sAbase,
    const uint32_t* __restrict__ pW0, const uint32_t* __restrict__ pW1,
    int lane, int nt0, int rowA, int hi8, float acc0[4][8], float acc1[4][8])
{
#pragma unroll
    for (int s = 0; s < 4; s++)
#pragma unroll
        for (int j = 0; j < 8; j++) { acc0[s][j] = 0.f; acc1[s][j] = 0.f; }

    const uint2* B0 = reinterpret_cast<const uint2*>(pW0) + (nt0 * 32 + lane);
    const uint2* B1 = reinterpret_cast<const uint2*>(pW1) + (nt0 * 32 + lane);

#pragma unroll 2
    for (int ks = 0; ks < 8; ks++) {
        uint2 b0 = __ldg(B0 + ks * 512);
        uint2 b1 = __ldg(B0 + ks * 512 + 32);
        uint2 d0 = __ldg(B1 + ks * 512);
        uint2 d1 = __ldg(B1 + ks * 512 + 32);
        uint32_t coff = (ks * 16 + hi8) * 2;
#pragma unroll
        for (int s = 0; s < 4; s++) {
            uint32_t radd = ((s * 16 + rowA) * SROW) * 2 + coff;
            uint32_t a0, a1, a2, a3;
            LDSM4(a0, a1, a2, a3, sAbase + radd);
            MMAH(acc0[s], a0, a1, a2, a3, b0.x, b0.y);
            MMAH(acc0[s] + 4, a0, a1, a2, a3, b1.x, b1.y);
            MMAH(acc1[s], a0, a1, a2, a3, d0.x, d0.y);
            MMAH(acc1[s] + 4, a0, a1, a2, a3, d1.x, d1.y);
        }
    }
}

__global__ void __launch_bounds__(256) k_gemm_heads(
    const float* __restrict__ A, HeadArgs ha, int n)
{
    extern __shared__ uint32_t sm[];
    uint32_t* sA = sm;                           // 17408 B
    float* sred_a = (float*)(sm + 64 * SROW_U32);  // 64 rows x 8 warps
    float* sred_b = sred_a + 512;

    int tid = threadIdx.x;
    int row0 = blockIdx.x * 64;
    for (int idx = tid; idx < 4096; idx += 256) {
        int r = idx >> 6, c2 = idx & 63;
        int gr = row0 + r;
        float2 f = (gr < n) ? *reinterpret_cast<const float2*>(&A[(size_t)gr * HD + c2 * 2])
                            : make_float2(0.f, 0.f);
        __half2 h = __floats2half2_rn(f.x, f.y);
        sA[r * SROW_U32 + c2] = *reinterpret_cast<uint32_t*>(&h);
    }
    __syncthreads();

    int wid = tid >> 5, lane = tid & 31;
    int tg = lane & 3, gid = lane >> 2;
    int nt0 = wid * 2;
    int cbase = wid * 16;
    int rowA = lane & 15;
    int hi8 = (lane >> 4) << 3;
    uint32_t sAbase = (uint32_t)__cvta_generic_to_shared(sA);

    float acc0[4][8], acc1[4][8];

    // ---- phase 0: nodehead hidden + fused W2 dot ----
    mma_pair_h(sAbase, ha.pw0[0], ha.pw1[0], lane, nt0, rowA, hi8, acc0, acc1);
    {
        float bb0[4], bb1[4], wa[4], wb[4];
        bb0[0] = __ldg(&ha.b0[cbase + 2 * tg]);
        bb0[1] = __ldg(&ha.b0[cbase + 2 * tg + 1]);
        bb0[2] = __ldg(&ha.b0[cbase + 8 + 2 * tg]);
        bb0[3] = __ldg(&ha.b0[cbase + 8 + 2 * tg + 1]);
        bb1[0] = __ldg(&ha.b1[cbase + 2 * tg]);
        bb1[1] = __ldg(&ha.b1[cbase + 2 * tg + 1]);
        bb1[2] = __ldg(&ha.b1[cbase + 8 + 2 * tg]);
        bb1[3] = __ldg(&ha.b1[cbase + 8 + 2 * tg + 1]);
        wa[0] = __ldg(&ha.w2a[cbase + 2 * tg]);
        wa[1] = __ldg(&ha.w2a[cbase + 2 * tg + 1]);
        wa[2] = __ldg(&ha.w2a[cbase + 8 + 2 * tg]);
        wa[3] = __ldg(&ha.w2a[cbase + 8 + 2 * tg + 1]);
        wb[0] = __ldg(&ha.w2b[cbase + 2 * tg]);
        wb[1] = __ldg(&ha.w2b[cbase + 2 * tg + 1]);
        wb[2] = __ldg(&ha.w2b[cbase + 8 + 2 * tg]);
        wb[3] = __ldg(&ha.w2b[cbase + 8 + 2 * tg + 1]);
#pragma unroll
        for (int s = 0; s < 4; s++) {
            float ra_lo = 0.f, ra_hi = 0.f, rb_lo = 0.f, rb_hi = 0.f;
#pragma unroll
            for (int t = 0; t < 2; t++) {
                float u0 = fmaxf(acc0[s][t * 4 + 0] + bb0[t * 2 + 0], 0.f);
                float u1 = fmaxf(acc0[s][t * 4 + 1] + bb0[t * 2 + 1], 0.f);
                float u2 = fmaxf(acc0[s][t * 4 + 2] + bb0[t * 2 + 0], 0.f);
                float u3 = fmaxf(acc0[s][t * 4 + 3] + bb0[t * 2 + 1], 0.f);
                float v0 = fmaxf(acc1[s][t * 4 + 0] + bb1[t * 2 + 0], 0.f);
                float v1 = fmaxf(acc1[s][t * 4 + 1] + bb1[t * 2 + 1], 0.f);
                float v2 = fmaxf(acc1[s][t * 4 + 2] + bb1[t * 2 + 0], 0.f);
                float v3 = fmaxf(acc1[s][t * 4 + 3] + bb1[t * 2 + 1], 0.f);
                ra_lo += u0 * wa[t * 2 + 0] + u1 * wa[t * 2 + 1];
                ra_hi += u2 * wa[t * 2 + 0] + u3 * wa[t * 2 + 1];
                rb_lo += v0 * wb[t * 2 + 0] + v1 * wb[t * 2 + 1];
                rb_hi += v2 * wb[t * 2 + 0] + v3 * wb[t * 2 + 1];
            }
            // reduce over tg (lanes xor 1, 2 within the quad)
#pragma unroll
            for (int o = 1; o <= 2; o <<= 1) {
                ra_lo += __shfl_xor_sync(0xffffffffu, ra_lo, o);
                ra_hi += __shfl_xor_sync(0xffffffffu, ra_hi, o);
                rb_lo += __shfl_xor_sync(0xffffffffu, rb_lo, o);
                rb_hi += __shfl_xor_sync(0xffffffffu, rb_hi, o);
            }
            if (tg == 0) {
                int lr = s * 16 + gid;
                sred_a[lr * 8 + wid] = ra_lo;
                sred_a[(lr + 8) * 8 + wid] = ra_hi;
                sred_b[lr * 8 + wid] = rb_lo;
                sred_b[(lr + 8) * 8 + wid] = rb_hi;
            }
        }
    }
    __syncthreads();
    if (tid < 64) {
        int gr = row0 + tid;
        if (gr < n) {
            float sa = 0.f, sb = 0.f;
#pragma unroll
            for (int c = 0; c < 8; c++) { sa += sred_a[tid * 8 + c]; sb += sred_b[tid * 8 + c]; }
            ha.ph[gr] = sa + __ldg(&ha.b2a[0]);
            ha.nl[gr] = sb + __ldg(&ha.b2b[0]);
        }
    }

    // ---- phases 1,2: pair tables, fp16, stride 256, col offset 0 / 128 ----
#pragma unroll 1
    for (int ph = 1; ph < 3; ph++) {
        mma_pair_h(sAbase, ha.pw0[ph], ha.pw1[ph], lane, nt0, rowA, hi8, acc0, acc1);
        int coff = (ph - 1) * 128;
#pragma unroll
        for (int s = 0; s < 4; s++) {
#pragma unroll
            for (int t = 0; t < 2; t++) {
                int col = coff + cbase + t * 8 + 2 * tg;
                int r = row0 + s * 16 + gid;
                if (r < n) {
                    *reinterpret_cast<__half2*>(&ha.pa[(size_t)r * 256 + col]) =
                        __floats2half2_rn(acc0[s][t * 4 + 0], acc0[s][t * 4 + 1]);
                    *reinterpret_cast<__half2*>(&ha.pb[(size_t)r * 256 + col]) =
                        __floats2half2_rn(acc1[s][t * 4 + 0], acc1[s][t * 4 + 1]);
                }
                if (r + 8 < n) {
                    *reinterpret_cast<__half2*>(&ha.pa[(size_t)(r + 8) * 256 + col]) =
                        __floats2half2_rn(acc0[s][t * 4 + 2], acc0[s][t * 4 + 3]);
                    *reinterpret_cast<__half2*>(&ha.pb[(size_t)(r + 8) * 256 + col]) =
                        __floats2half2_rn(acc1[s][t * 4 + 2], acc1[s][t * 4 + 3]);
                }
            }
        }
    }
}

// ---------------- edge heads: EPW edges per warp, fp16 pair tables ----------------
__global__ void k_edge(const int* __restrict__ ei,
                       const float* __restrict__ estat, const float* __restrict__ qobs,
                       const int* __restrict__ qmask,
                       const float* __restrict__ erW1, const float* __restrict__ erb1,
                       const float* __restrict__ erW2, const float* __restrict__ erb2,
                       const float* __restrict__ eaW1, const float* __restrict__ eab1,
                       const float* __restrict__ eaW2, const float* __restrict__ eab2,
                       float* __restrict__ qhat, float* __restrict__ elog, int ne)
{
    __shared__ float sE[2][8 * HD];  // per head: rows 0-5 = W1[256+r], 6 = b1, 7 = W2
    int tid = threadIdx.x;
    for (int idx = tid; idx < 2 * 8 * HD; idx += blockDim.x) {
        int h = idx / (8 * HD);
        int rem = idx - h * 8 * HD;
        int r = rem >> 7, c = rem & 127;
        const float* W1 = h ? eaW1 : erW1;
        const float* b1 = h ? eab1 : erb1;
        const float* W2 = h ? eaW2 : erW2;
        float v;
        if (r < 6) v = W1[(256 + r) * HD + c];
        else if (r == 6) v = b1[c];
        else v = W2[c];
        sE[h][rem] = v;
    }
    __syncthreads();

    int warpg = (blockIdx.x * blockDim.x + tid) >> 5;
    int lane = tid & 31;
    int ebase = warpg * EPW;
    if (ebase >= ne) return;
    int eend = min(ebase + EPW, ne);
    int c = lane * 4;
    float eb2r = __ldg(&erb2[0]);
    float eb2a = __ldg(&eab2[0]);

    for (int e = ebase; e < eend; e++) {
        int s = __ldg(&ei[e]), d = __ldg(&ei[ne + e]);
        const __half* srcA = &g_pairAh[(size_t)s * 256];
        const __half* dstB = &g_pairBh[(size_t)d * 256];
        uint2 ua0 = *reinterpret_cast<const uint2*>(&srcA[c]);
        uint2 ub0 = *reinterpret_cast<const uint2*>(&dstB[c]);
        uint2 ua1 = *reinterpret_cast<const uint2*>(&srcA[128 + c]);
        uint2 ub1 = *reinterpret_cast<const uint2*>(&dstB[128 + c]);

        float e0 = __ldg(&estat[e * 4 + 0]), e1 = __ldg(&estat[e * 4 + 1]);
        float e2 = __ldg(&estat[e * 4 + 2]), e3 = __ldg(&estat[e * 4 + 3]);
        float qo = __ldg(&qobs[e]), qm = (float)__ldg(&qmask[e]);

        float acc0 = 0.f, acc1 = 0.f;
        {
            const float* S = sE[0];
            const __half2* pa = reinterpret_cast<const __half2*>(&ua0);
            const __half2* pb = reinterpret_cast<const __half2*>(&ub0);
            float2 a01 = __half22float2(pa[0]), a23 = __half22float2(pa[1]);
            float2 b01 = __half22float2(pb[0]), b23 = __half22float2(pb[1]);
            float av[4] = {a01.x, a01.y, a23.x, a23.y};
            float bv[4] = {b01.x, b01.y, b23.x, b23.y};
#pragma unroll
            for (int t = 0; t < 4; t++) {
                int cc = c + t;
                float hv = av[t] + bv[t] + e0 * S[cc] + e1 * S[HD + cc] + e2 * S[2 * HD + cc]
                         + e3 * S[3 * HD + cc] + qo * S[4 * HD + cc] + qm * S[5 * HD + cc]
                         + S[6 * HD + cc];
                hv = fmaxf(hv, 0.f);
                acc0 += hv * S[7 * HD + cc];
            }
        }
        {
            const float* S = sE[1];
            const __half2* pa = reinterpret_cast<const __half2*>(&ua1);
            const __half2* pb = reinterpret_cast<const __half2*>(&ub1);
            float2 a01 = __half22float2(pa[0]), a23 = __half22float2(pa[1]);
            float2 b01 = __half22float2(pb[0]), b23 = __half22float2(pb[1]);
            float av[4] = {a01.x, a01.y, a23.x, a23.y};
            float bv[4] = {b01.x, b01.y, b23.x, b23.y};
#pragma unroll
            for (int t = 0; t < 4; t++) {
                int cc = c + t;
                float hv = av[t] + bv[t] + e0 * S[cc] + e1 * S[HD + cc] + e2 * S[2 * HD + cc]
                         + e3 * S[3 * HD + cc] + qo * S[4 * HD + cc] + qm * S[5 * HD + cc]
                         + S[6 * HD + cc];
                hv = fmaxf(hv, 0.f);
                acc1 += hv * S[7 * HD + cc];
            }
        }
#pragma unroll
        for (int off = 16; off; off >>= 1) {
            acc0 += __shfl_xor_sync(0xffffffffu, acc0, off);
            acc1 += __shfl_xor_sync(0xffffffffu, acc1, off);
        }
        if (lane == 0) {
            qhat[e] = acc0 + eb2r;
            elog[e] = acc1 + eb2a;
        }
    }
}

// ---------------- launch ----------------
extern "C" void kernel_launch(void* const* d_in, const int* in_sizes, int n_in,
                              void* d_out, int out_size)
{
    const int*   ei           = (const int*)d_in[0];   // edge_index is int32 (jax x64 disabled)
    const float* node_static  = (const float*)d_in[1];
    const float* edge_static  = (const float*)d_in[2];
    const float* p_obs        = (const float*)d_in[3];
    const float* q_obs        = (const float*)d_in[4];
    const int*   p_mask       = (const int*)d_in[5];
    const int*   q_mask       = (const int*)d_in[6];
    const float* W_enc        = (const float*)d_in[7];
    const float* b_enc        = (const float*)d_in[8];
    const float* W_self       = (const float*)d_in[9];
    const float* W_neigh      = (const float*)d_in[10];
    const float* b_gnn        = (const float*)d_in[11];
    const float* nrW1 = (const float*)d_in[12]; const float* nrb1 = (const float*)d_in[13];
    const float* nrW2 = (const float*)d_in[14]; const float* nrb2 = (const float*)d_in[15];
    const float* naW1 = (const float*)d_in[16]; const float* nab1 = (const float*)d_in[17];
    const float* naW2 = (const float*)d_in[18]; const float* nab2 = (const float*)d_in[19];
    const float* erW1 = (const float*)d_in[20]; const float* erb1 = (const float*)d_in[21];
    const float* erW2 = (const float*)d_in[22]; const float* erb2 = (const float*)d_in[23];
    const float* eaW1 = (const float*)d_in[24]; const float* eab1 = (const float*)d_in[25];
    const float* eaW2 = (const float*)d_in[26]; const float* eab2 = (const float*)d_in[27];

    int n  = in_sizes[3];  // N (p_obs)
    int ne = in_sizes[4];  // E (q_obs)

    float* out   = (float*)d_out;
    float* p_hat = out;
    float* q_hat = out + n;
    float* nlog  = out + n + ne;
    float* elog  = out + 2 * n + ne;

    float* gy;
    __half *gpa, *gpb, *gxh0, *gxh1, *gaggh;
    uint32_t* gpwh;
    cudaGetSymbolAddress((void**)&gy,    g_y);
    cudaGetSymbolAddress((void**)&gaggh, g_aggh);
    cudaGetSymbolAddress((void**)&gpa,   g_pairAh);
    cudaGetSymbolAddress((void**)&gpb,   g_pairBh);
    cudaGetSymbolAddress((void**)&gxh0,  g_xh0);
    cudaGetSymbolAddress((void**)&gxh1,  g_xh1);
    cudaGetSymbolAddress((void**)&gpwh,  g_pwh);

    const int SM_DUALA = 2 * SA_BYTES;        // 34816 B
    const int SM_HEADS = SA_BYTES + 4096;     // 21504 B (sA + 2x 64x8 reduce arrays)
    cudaFuncSetAttribute(k_gemm_dualA, cudaFuncAttributeMaxDynamicSharedMemorySize, SM_DUALA);
    cudaFuncSetAttribute(k_gemm_heads, cudaFuncAttributeMaxDynamicSharedMemorySize, SM_HEADS);

    // pre-pack the 12 weight matrices: 0-2 Wself[l], 3-5 Wneigh[l], 6 nrW1, 7 naW1,
    // 8 erW1 top, 9 erW1 bot, 10 eaW1 top, 11 eaW1 bot
    PackSrc ps;
    ps.s[0] = W_self;                ps.s[1] = W_self + 16384;  ps.s[2] = W_self + 32768;
    ps.s[3] = W_neigh;               ps.s[4] = W_neigh + 16384; ps.s[5] = W_neigh + 32768;
    ps.s[6] = nrW1;                  ps.s[7] = naW1;
    ps.s[8] = erW1;                  ps.s[9] = erW1 + 16384;
    ps.s[10] = eaW1;                 ps.s[11] = eaW1 + 16384;
    k_packh<<<(12 * 8192 + 255) / 256, 256>>>(ps);

    k_encoder<<<(n * HD + 255) / 256, 256>>>(node_static, p_obs, p_mask, W_enc, b_enc, gxh0, n);
    k_zero_deg<<<(n + 255) / 256, 256>>>(n);
    k_deg<<<(ne + 255) / 256, 256>>>(ei, ne);
    int nb = (n + 1023) / 1024;
    k_scan_local<<<nb, 1024>>>(n);
    k_scan_bsum<<<1, 32>>>(nb);
    k_scan_final<<<(n + 255) / 256, 256>>>(n);
    k_fill<<<(ne + 255) / 256, 256>>>(ei, ne);

    int gblocks = (n + 63) / 64;
    __half* xh_in = gxh0;
    __half* xh_out = gxh1;
    for (int l = 0; l < 3; l++) {
        k_agg<<<(n * 32 + 255) / 256, 256>>>(xh_in, gaggh, n);
        // layers 0,1: fp16 shadow only (with relu); layer 2: fp32 only (no relu)
        float* cf = (l < 2) ? (float*)nullptr : gy;
        __half* ch = (l < 2) ? xh_out : (__half*)nullptr;
        k_gemm_dualA<<<gblocks, 256, SM_DUALA>>>(xh_in, gaggh,
                                                 gpwh + l * 8192, gpwh + (3 + l) * 8192,
                                                 b_gnn + l * HD, cf, ch, n, (l < 2) ? 1 : 0);
        __half* th = xh_in;
        xh_in = xh_out;
        xh_out = th;
    }
    const float* xf = gy;  // final node embeddings (fp32)

    // all head GEMMs in one launch: node heads fully fused; pair tables -> gpa/gpb
    HeadArgs ha;
    ha.pw0[0] = gpwh + 6 * 8192;  ha.pw1[0] = gpwh + 7 * 8192;
    ha.pw0[1] = gpwh + 8 * 8192;  ha.pw1[1] = gpwh + 9 * 8192;
    ha.pw0[2] = gpwh + 10 * 8192; ha.pw1[2] = gpwh + 11 * 8192;
    ha.b0 = nrb1; ha.b1 = nab1;
    ha.w2a = nrW2; ha.w2b = naW2;
    ha.b2a = nrb2; ha.b2b = nab2;
    ha.ph = p_hat; ha.nl = nlog;
    ha.pa = gpa;  ha.pb = gpb;
    k_gemm_heads<<<gblocks, 256, SM_HEADS>>>(xf, ha, n);

    int eblocks = (ne + 8 * EPW - 1) / (8 * EPW);
    k_edge<<<eblocks, 256>>>(ei, edge_static, q_obs, q_mask,
                             erW1, erb1, erW2, erb2,
                             eaW1, eab1, eaW2, eab2,
                             q_hat, elog, ne);
}

// round 16
// speedup vs baseline: 1.7565x; 1.1594x over previous
#include <cuda_runtime.h>
#include <cuda_fp16.h>
#include <cstdint>

#define NN 100000
#define NE 600000
#define HD 128
#define EPW 16   // edges per warp in k_edge

// ---------------- scratch (static device memory; no allocs) ----------------
static __device__ float  g_y  [NN * HD];          // fp32 final embeddings (layer 2 out)
static __device__ __half g_aggh[NN * HD];         // fp16 aggregation output
static __device__ __half g_xh0[NN * HD];          // fp16 x (ping)
static __device__ __half g_xh1[NN * HD];          // fp16 x (pong)
static __device__ __half g_pairAh[NN * 256];      // [node][0:128)=er A-part, [128:256)=ea A-part
static __device__ __half g_pairBh[NN * 256];      // [node][0:128)=er B-part, [128:256)=ea B-part
static __device__ int    g_deg[NN];
static __device__ int    g_rowptr[NN + 1];
static __device__ int    g_cursor[NN];
static __device__ int    g_col[2 * NE];
static __device__ float  g_invdeg[NN];
static __device__ int    g_tmp[NN];
static __device__ int    g_bsum[128];
static __device__ uint32_t g_pwh[12 * 8192];      // packed fp16 weights, m16n8k16 frag order

// ---------------- fp16 MMA helpers ----------------
#define MMAH(c, a0, a1, a2, a3, b0, b1)                                       \
    asm volatile("mma.sync.aligned.m16n8k16.row.col.f32.f16.f16.f32 "         \
                 "{%0,%1,%2,%3},{%4,%5,%6,%7},{%8,%9},{%0,%1,%2,%3};"         \
                 : "+f"((c)[0]), "+f"((c)[1]), "+f"((c)[2]), "+f"((c)[3])     \
                 : "r"(a0), "r"(a1), "r"(a2), "r"(a3), "r"(b0), "r"(b1))

#define LDSM4(a0, a1, a2, a3, addr)                                           \
    asm volatile("ldmatrix.sync.aligned.m8n8.x4.shared.b16 {%0,%1,%2,%3}, [%4];" \
                 : "=r"(a0), "=r"(a1), "=r"(a2), "=r"(a3) : "r"(addr))

// smem A layout: rows x 136 halves (stride 136 halves = 272B -> ldmatrix conflict-free)
#define SROW 136
#define SROW_U32 68
#define SA64_BYTES  (64 * SROW * 2)    // 17408 (heads kernel, 64-row tile)
#define SA128_BYTES (128 * SROW * 2)   // 34816 (layer kernel, 128-row tile)

// ---------------- weight pre-pack: 12 matrices into fp16 m16n8k16 fragment order ----------------
struct PackSrc { const float* s[12]; };

__global__ void k_packh(PackSrc ps)
{
    int idx = blockIdx.x * 256 + threadIdx.x;
    if (idx >= 12 * 8192) return;
    int m = idx >> 13, e = idx & 8191;
    int reg = e & 1;
    int lane = (e >> 1) & 31;
    int knt = e >> 6;                // ks*16 + nt
    int ks = knt >> 4, nt = knt & 15;
    int tg = lane & 3, gid = lane >> 2;
    int k = ks * 16 + reg * 8 + tg * 2;
    int n = nt * 8 + gid;
    const float* W = ps.s[m];
    __half2 h = __floats2half2_rn(__ldg(&W[k * HD + n]), __ldg(&W[(k + 1) * HD + n]));
    g_pwh[m * 8192 + e] = *reinterpret_cast<uint32_t*>(&h);
}

// ---------------- encoder: xh = fp16(node_feats(8) @ W_enc + b_enc) ----------------
__global__ void k_encoder(const float* __restrict__ ns, const float* __restrict__ pobs,
                          const int* __restrict__ pmask, const float* __restrict__ Wenc,
                          const float* __restrict__ benc, __half* __restrict__ xh, int n)
{
    __shared__ float sW[8 * HD];
    __shared__ float sb[HD];
    for (int i = threadIdx.x; i < 8 * HD; i += blockDim.x) sW[i] = Wenc[i];
    for (int i = threadIdx.x; i < HD; i += blockDim.x) sb[i] = benc[i];
    __syncthreads();
    int idx = blockIdx.x * blockDim.x + threadIdx.x;
    if (idx >= n * HD) return;
    int node = idx >> 7, h = idx & 127;
    float f0 = ns[node * 6 + 0], f1 = ns[node * 6 + 1], f2 = ns[node * 6 + 2];
    float f3 = ns[node * 6 + 3], f4 = ns[node * 6 + 4], f5 = ns[node * 6 + 5];
    float f6 = pobs[node];
    float f7 = (float)pmask[node];
    float o = sb[h];
    o += f0 * sW[0 * HD + h] + f1 * sW[1 * HD + h] + f2 * sW[2 * HD + h] + f3 * sW[3 * HD + h];
    o += f4 * sW[4 * HD + h] + f5 * sW[5 * HD + h] + f6 * sW[6 * HD + h] + f7 * sW[7 * HD + h];
    xh[idx] = __float2half_rn(o);
}

// ---------------- CSR build ----------------
__global__ void k_zero_deg(int n)
{
    int i = blockIdx.x * blockDim.x + threadIdx.x;
    if (i < n) g_deg[i] = 0;
}

__global__ void k_deg(const int* __restrict__ ei, int ne)
{
    int e = blockIdx.x * blockDim.x + threadIdx.x;
    if (e >= ne) return;
    int s = ei[e], d = ei[ne + e];
    atomicAdd(&g_deg[s], 1);
    atomicAdd(&g_deg[d], 1);
}

__global__ void k_scan_local(int n)
{
    __shared__ int sh[1024];
    int t = threadIdx.x;
    int i = blockIdx.x * 1024 + t;
    int v = (i < n) ? g_deg[i] : 0;
    sh[t] = v;
    __syncthreads();
    for (int off = 1; off < 1024; off <<= 1) {
        int tv = (t >= off) ? sh[t - off] : 0;
        __syncthreads();
        sh[t] += tv;
        __syncthreads();
    }
    if (i < n) g_tmp[i] = sh[t];
    if (t == 1023) g_bsum[blockIdx.x] = sh[1023];
}

__global__ void k_scan_bsum(int nb)
{
    if (threadIdx.x == 0) {
        int acc = 0;
        for (int b = 0; b < nb; b++) { int tv = g_bsum[b]; g_bsum[b] = acc; acc += tv; }
    }
}

__global__ void k_scan_final(int n)
{
    int i = blockIdx.x * blockDim.x + threadIdx.x;
    if (i >= n) return;
    int incl = g_tmp[i] + g_bsum[i >> 10];
    g_rowptr[i + 1] = incl;
    int d = g_deg[i];
    g_cursor[i] = incl - d;
    g_invdeg[i] = 1.0f / (float)(d > 0 ? d : 1);
    if (i == 0) g_rowptr[0] = 0;
}

__global__ void k_fill(const int* __restrict__ ei, int ne)
{
    int e = blockIdx.x * blockDim.x + threadIdx.x;
    if (e >= ne) return;
    int s = ei[e], d = ei[ne + e];
    int p = atomicAdd(&g_cursor[d], 1);
    g_col[p] = s;
    int q = atomicAdd(&g_cursor[s], 1);
    g_col[q] = d;
}

// ---------------- mean aggregation: one warp per node, fp16 in / fp16 out ----------------
__global__ void k_agg(const __half* __restrict__ xh, __half* __restrict__ agg, int n)
{
    int w = (blockIdx.x * blockDim.x + threadIdx.x) >> 5;
    int lane = threadIdx.x & 31;
    if (w >= n) return;
    int beg = g_rowptr[w], end = g_rowptr[w + 1];
    float acc0 = 0.f, acc1 = 0.f, acc2 = 0.f, acc3 = 0.f;
    int i = beg;
    int c = lane * 4;
    for (; i + 4 <= end; i += 4) {
        int n0 = g_col[i], n1 = g_col[i + 1], n2 = g_col[i + 2], n3 = g_col[i + 3];
        uint2 u0 = *reinterpret_cast<const uint2*>(&xh[(size_t)n0 * HD + c]);
        uint2 u1 = *reinterpret_cast<const uint2*>(&xh[(size_t)n1 * HD + c]);
        uint2 u2 = *reinterpret_cast<const uint2*>(&xh[(size_t)n2 * HD + c]);
        uint2 u3 = *reinterpret_cast<const uint2*>(&xh[(size_t)n3 * HD + c]);
        const __half2* p0 = reinterpret_cast<const __half2*>(&u0);
        const __half2* p1 = reinterpret_cast<const __half2*>(&u1);
        const __half2* p2 = reinterpret_cast<const __half2*>(&u2);
        const __half2* p3 = reinterpret_cast<const __half2*>(&u3);
        float2 a0 = __half22float2(p0[0]), a1 = __half22float2(p0[1]);
        float2 b0 = __half22float2(p1[0]), b1 = __half22float2(p1[1]);
        float2 c0 = __half22float2(p2[0]), c1 = __half22float2(p2[1]);
        float2 d0 = __half22float2(p3[0]), d1 = __half22float2(p3[1]);
        acc0 += a0.x + b0.x + c0.x + d0.x;
        acc1 += a0.y + b0.y + c0.y + d0.y;
        acc2 += a1.x + b1.x + c1.x + d1.x;
        acc3 += a1.y + b1.y + c1.y + d1.y;
    }
    for (; i < end; i++) {
        int nb = g_col[i];
        uint2 u = *reinterpret_cast<const uint2*>(&xh[(size_t)nb * HD + c]);
        const __half2* p = reinterpret_cast<const __half2*>(&u);
        float2 a0 = __half22float2(p[0]), a1 = __half22float2(p[1]);
        acc0 += a0.x; acc1 += a0.y; acc2 += a1.x; acc3 += a1.y;
    }
    float sc = g_invdeg[w];
    __half2 h01 = __floats2half2_rn(acc0 * sc, acc1 * sc);
    __half2 h23 = __floats2half2_rn(acc2 * sc, acc3 * sc);
    uint2 o;
    o.x = *reinterpret_cast<uint32_t*>(&h01);
    o.y = *reinterpret_cast<uint32_t*>(&h23);
    *reinterpret_cast<uint2*>(&agg[(size_t)w * HD + c]) = o;
}

// ---------------- GNN layer GEMM (fp16 MMA, 128-row tile): C = op(xh@W0 + agg@W1 + b) ----------------
__global__ void __launch_bounds__(256) k_gemm_dualA(
    const __half* __restrict__ Ah, const __half* __restrict__ A2h,
    const uint32_t* __restrict__ pW0, const uint32_t* __restrict__ pW1,
    const float* __restrict__ bias, float* __restrict__ C,
    __half* __restrict__ Ch, int n, int relu)
{
    extern __shared__ uint32_t sm[];
    uint32_t* sA  = sm;                       // 128 x 136 halves
    uint32_t* sA2 = sm + 128 * SROW_U32;

    int tid = threadIdx.x;
    int row0 = blockIdx.x * 128;
    for (int idx = tid; idx < 8192; idx += 256) {
        int r = idx >> 6, c2 = idx & 63;
        int gr = row0 + r;
        bool ok = gr < n;
        sA [r * SROW_U32 + c2] = ok ? reinterpret_cast<const uint32_t*>(Ah)[(size_t)gr * 64 + c2] : 0u;
        sA2[r * SROW_U32 + c2] = ok ? reinterpret_cast<const uint32_t*>(A2h)[(size_t)gr * 64 + c2] : 0u;
    }
    __syncthreads();

    int wid = tid >> 5, lane = tid & 31;
    int tg = lane & 3, gid = lane >> 2;
    int nt0 = wid * 2;
    int rowA = lane & 15;
    int hi8 = (lane >> 4) << 3;

    uint32_t sAbase  = (uint32_t)__cvta_generic_to_shared(sA);
    uint32_t sA2base = (uint32_t)__cvta_generic_to_shared(sA2);

    float acc[8][8];
#pragma unroll
    for (int s = 0; s < 8; s++)
#pragma unroll
        for (int j = 0; j < 8; j++) acc[s][j] = 0.f;

    const uint2* B0 = reinterpret_cast<const uint2*>(pW0) + (nt0 * 32 + lane);
    const uint2* B1 = reinterpret_cast<const uint2*>(pW1) + (nt0 * 32 + lane);

#pragma unroll 1
    for (int ks = 0; ks < 8; ks++) {
        uint2 b0 = __ldg(B0 + ks * 512);
        uint2 b1 = __ldg(B0 + ks * 512 + 32);
        uint2 d0 = __ldg(B1 + ks * 512);
        uint2 d1 = __ldg(B1 + ks * 512 + 32);
        uint32_t coff = (ks * 16 + hi8) * 2;
#pragma unroll
        for (int s = 0; s < 8; s++) {
            uint32_t radd = ((s * 16 + rowA) * SROW) * 2 + coff;
            uint32_t a0, a1, a2, a3;
            LDSM4(a0, a1, a2, a3, sAbase + radd);
            MMAH(acc[s], a0, a1, a2, a3, b0.x, b0.y);
            MMAH(acc[s] + 4, a0, a1, a2, a3, b1.x, b1.y);
            uint32_t e0, e1, e2, e3;
            LDSM4(e0, e1, e2, e3, sA2base + radd);
            MMAH(acc[s], e0, e1, e2, e3, d0.x, d0.y);
            MMAH(acc[s] + 4, e0, e1, e2, e3, d1.x, d1.y);
        }
    }

    int cbase = wid * 16;
    float bb[4];
    bb[0] = __ldg(&bias[cbase + 2 * tg]);
    bb[1] = __ldg(&bias[cbase + 2 * tg + 1]);
    bb[2] = __ldg(&bias[cbase + 8 + 2 * tg]);
    bb[3] = __ldg(&bias[cbase + 8 + 2 * tg + 1]);
#pragma unroll
    for (int s = 0; s < 8; s++) {
#pragma unroll
        for (int t = 0; t < 2; t++) {
            int col = cbase + t * 8 + 2 * tg;
            int r = row0 + s * 16 + gid;
            float v0 = acc[s][t * 4 + 0] + bb[t * 2 + 0];
            float v1 = acc[s][t * 4 + 1] + bb[t * 2 + 1];
            float v2 = acc[s][t * 4 + 2] + bb[t * 2 + 0];
            float v3 = acc[s][t * 4 + 3] + bb[t * 2 + 1];
            if (relu) {
                v0 = fmaxf(v0, 0.f); v1 = fmaxf(v1, 0.f);
                v2 = fmaxf(v2, 0.f); v3 = fmaxf(v3, 0.f);
            }
            if (r < n) {
                if (C)
                    *reinterpret_cast<float2*>(&C[(size_t)r * HD + col]) = make_float2(v0, v1);
                if (Ch)
                    *reinterpret_cast<__half2*>(&Ch[(size_t)r * HD + col]) = __floats2half2_rn(v0, v1);
            }
            if (r + 8 < n) {
                if (C)
                    *reinterpret_cast<float2*>(&C[(size_t)(r + 8) * HD + col]) = make_float2(v2, v3);
                if (Ch)
                    *reinterpret_cast<__half2*>(&Ch[(size_t)(r + 8) * HD + col]) = __floats2half2_rn(v2, v3);
            }
        }
    }
}

// ---------------- merged head GEMMs (fp16 MMA, 64-row tile): fused W2 dot + pair tables ----------------
struct HeadArgs {
    const uint32_t* pw0[3];
    const uint32_t* pw1[3];
    const float* b0;
    const float* b1;
    const float* w2a;
    const float* w2b;
    const float* b2a;
    const float* b2b;
    float* ph;   // p_hat
    float* nl;   // node_logits
    __half* pa;
    __half* pb;
};

__device__ __forceinline__ void mma_pair_h(
    uint32_t sAbase,
    const uint32_t* __restrict__ pW0, const uint32_t* __restrict__ pW1,
    int lane, int nt0, int rowA, int hi8, float acc0[4][8], float acc1[4][8])
{
#pragma unroll
    for (int s = 0; s < 4; s++)
#pragma unroll
        for (int j = 0; j < 8; j++) { acc0[s][j] = 0.f; acc1[s][j] = 0.f; }

    const uint2* B0 = reinterpret_cast<const uint2*>(pW0) + (nt0 * 32 + lane);
    const uint2* B1 = reinterpret_cast<const uint2*>(pW1) + (nt0 * 32 + lane);

#pragma unroll 2
    for (int ks = 0; ks < 8; ks++) {
        uint2 b0 = __ldg(B0 + ks * 512);
        uint2 b1 = __ldg(B0 + ks * 512 + 32);
        uint2 d0 = __ldg(B1 + ks * 512);
        uint2 d1 = __ldg(B1 + ks * 512 + 32);
        uint32_t coff = (ks * 16 + hi8) * 2;
#pragma unroll
        for (int s = 0; s < 4; s++) {
            uint32_t radd = ((s * 16 + rowA) * SROW) * 2 + coff;
            uint32_t a0, a1, a2, a3;
            LDSM4(a0, a1, a2, a3, sAbase + radd);
            MMAH(acc0[s], a0, a1, a2, a3, b0.x, b0.y);
            MMAH(acc0[s] + 4, a0, a1, a2, a3, b1.x, b1.y);
            MMAH(acc1[s], a0, a1, a2, a3, d0.x, d0.y);
            MMAH(acc1[s] + 4, a0, a1, a2, a3, d1.x, d1.y);
        }
    }
}

__global__ void __launch_bounds__(256) k_gemm_heads(
    const float* __restrict__ A, HeadArgs ha, int n)
{
    extern __shared__ uint32_t sm[];
    uint32_t* sA = sm;                           // 17408 B
    float* sred_a = (float*)(sm + 64 * SROW_U32);  // 64 rows x 8 warps
    float* sred_b = sred_a + 512;

    int tid = threadIdx.x;
    int row0 = blockIdx.x * 64;
    for (int idx = tid; idx < 4096; idx += 256) {
        int r = idx >> 6, c2 = idx & 63;
        int gr = row0 + r;
        float2 f = (gr < n) ? *reinterpret_cast<const float2*>(&A[(size_t)gr * HD + c2 * 2])
                            : make_float2(0.f, 0.f);
        __half2 h = __floats2half2_rn(f.x, f.y);
        sA[r * SROW_U32 + c2] = *reinterpret_cast<uint32_t*>(&h);
    }
    __syncthreads();

    int wid = tid >> 5, lane = tid & 31;
    int tg = lane & 3, gid = lane >> 2;
    int nt0 = wid * 2;
    int cbase = wid * 16;
    int rowA = lane & 15;
    int hi8 = (lane >> 4) << 3;
    uint32_t sAbase = (uint32_t)__cvta_generic_to_shared(sA);

    float acc0[4][8], acc1[4][8];

    // ---- phase 0: nodehead hidden + fused W2 dot ----
    mma_pair_h(sAbase, ha.pw0[0], ha.pw1[0], lane, nt0, rowA, hi8, acc0, acc1);
    {
        float bb0[4], bb1[4], wa[4], wb[4];
        bb0[0] = __ldg(&ha.b0[cbase + 2 * tg]);
        bb0[1] = __ldg(&ha.b0[cbase + 2 * tg + 1]);
        bb0[2] = __ldg(&ha.b0[cbase + 8 + 2 * tg]);
        bb0[3] = __ldg(&ha.b0[cbase + 8 + 2 * tg + 1]);
        bb1[0] = __ldg(&ha.b1[cbase + 2 * tg]);
        bb1[1] = __ldg(&ha.b1[cbase + 2 * tg + 1]);
        bb1[2] = __ldg(&ha.b1[cbase + 8 + 2 * tg]);
        bb1[3] = __ldg(&ha.b1[cbase + 8 + 2 * tg + 1]);
        wa[0] = __ldg(&ha.w2a[cbase + 2 * tg]);
        wa[1] = __ldg(&ha.w2a[cbase + 2 * tg + 1]);
        wa[2] = __ldg(&ha.w2a[cbase + 8 + 2 * tg]);
        wa[3] = __ldg(&ha.w2a[cbase + 8 + 2 * tg + 1]);
        wb[0] = __ldg(&ha.w2b[cbase + 2 * tg]);
        wb[1] = __ldg(&ha.w2b[cbase + 2 * tg + 1]);
        wb[2] = __ldg(&ha.w2b[cbase + 8 + 2 * tg]);
        wb[3] = __ldg(&ha.w2b[cbase + 8 + 2 * tg + 1]);
#pragma unroll
        for (int s = 0; s < 4; s++) {
            float ra_lo = 0.f, ra_hi = 0.f, rb_lo = 0.f, rb_hi = 0.f;
#pragma unroll
            for (int t = 0; t < 2; t++) {
                float u0 = fmaxf(acc0[s][t * 4 + 0] + bb0[t * 2 + 0], 0.f);
                float u1 = fmaxf(acc0[s][t * 4 + 1] + bb0[t * 2 + 1], 0.f);
                float u2 = fmaxf(acc0[s][t * 4 + 2] + bb0[t * 2 + 0], 0.f);
                float u3 = fmaxf(acc0[s][t * 4 + 3] + bb0[t * 2 + 1], 0.f);
                float v0 = fmaxf(acc1[s][t * 4 + 0] + bb1[t * 2 + 0], 0.f);
                float v1 = fmaxf(acc1[s][t * 4 + 1] + bb1[t * 2 + 1], 0.f);
                float v2 = fmaxf(acc1[s][t * 4 + 2] + bb1[t * 2 + 0], 0.f);
                float v3 = fmaxf(acc1[s][t * 4 + 3] + bb1[t * 2 + 1], 0.f);
                ra_lo += u0 * wa[t * 2 + 0] + u1 * wa[t * 2 + 1];
                ra_hi += u2 * wa[t * 2 + 0] + u3 * wa[t * 2 + 1];
                rb_lo += v0 * wb[t * 2 + 0] + v1 * wb[t * 2 + 1];
                rb_hi += v2 * wb[t * 2 + 0] + v3 * wb[t * 2 + 1];
            }
#pragma unroll
            for (int o = 1; o <= 2; o <<= 1) {
                ra_lo += __shfl_xor_sync(0xffffffffu, ra_lo, o);
                ra_hi += __shfl_xor_sync(0xffffffffu, ra_hi, o);
                rb_lo += __shfl_xor_sync(0xffffffffu, rb_lo, o);
                rb_hi += __shfl_xor_sync(0xffffffffu, rb_hi, o);
            }
            if (tg == 0) {
                int lr = s * 16 + gid;
                sred_a[lr * 8 + wid] = ra_lo;
                sred_a[(lr + 8) * 8 + wid] = ra_hi;
                sred_b[lr * 8 + wid] = rb_lo;
                sred_b[(lr + 8) * 8 + wid] = rb_hi;
            }
        }
    }
    __syncthreads();
    if (tid < 64) {
        int gr = row0 + tid;
        if (gr < n) {
            float sa = 0.f, sb = 0.f;
#pragma unroll
            for (int c = 0; c < 8; c++) { sa += sred_a[tid * 8 + c]; sb += sred_b[tid * 8 + c]; }
            ha.ph[gr] = sa + __ldg(&ha.b2a[0]);
            ha.nl[gr] = sb + __ldg(&ha.b2b[0]);
        }
    }

    // ---- phases 1,2: pair tables, fp16, stride 256, col offset 0 / 128 ----
#pragma unroll 1
    for (int ph = 1; ph < 3; ph++) {
        mma_pair_h(sAbase, ha.pw0[ph], ha.pw1[ph], lane, nt0, rowA, hi8, acc0, acc1);
        int coff = (ph - 1) * 128;
#pragma unroll
        for (int s = 0; s < 4; s++) {
#pragma unroll
            for (int t = 0; t < 2; t++) {
                int col = coff + cbase + t * 8 + 2 * tg;
                int r = row0 + s * 16 + gid;
                if (r < n) {
                    *reinterpret_cast<__half2*>(&ha.pa[(size_t)r * 256 + col]) =
                        __floats2half2_rn(acc0[s][t * 4 + 0], acc0[s][t * 4 + 1]);
                    *reinterpret_cast<__half2*>(&ha.pb[(size_t)r * 256 + col]) =
                        __floats2half2_rn(acc1[s][t * 4 + 0], acc1[s][t * 4 + 1]);
                }
                if (r + 8 < n) {
                    *reinterpret_cast<__half2*>(&ha.pa[(size_t)(r + 8) * 256 + col]) =
                        __floats2half2_rn(acc0[s][t * 4 + 2], acc0[s][t * 4 + 3]);
                    *reinterpret_cast<__half2*>(&ha.pb[(size_t)(r + 8) * 256 + col]) =
                        __floats2half2_rn(acc1[s][t * 4 + 2], acc1[s][t * 4 + 3]);
                }
            }
        }
    }
}

// ---------------- edge heads: EPW edges per warp, 2-edge software pipeline ----------------
__device__ __forceinline__ float edge_head_eval(
    const float* S, uint2 ua, uint2 ub, int c,
    float e0, float e1, float e2, float e3, float qo, float qm)
{
    const __half2* pa = reinterpret_cast<const __half2*>(&ua);
    const __half2* pb = reinterpret_cast<const __half2*>(&ub);
    float2 a01 = __half22float2(pa[0]), a23 = __half22float2(pa[1]);
    float2 b01 = __half22float2(pb[0]), b23 = __half22float2(pb[1]);
    float av[4] = {a01.x, a01.y, a23.x, a23.y};
    float bv[4] = {b01.x, b01.y, b23.x, b23.y};
    float acc = 0.f;
#pragma unroll
    for (int t = 0; t < 4; t++) {
        int cc = c + t;
        float hv = av[t] + bv[t] + e0 * S[cc] + e1 * S[HD + cc] + e2 * S[2 * HD + cc]
                 + e3 * S[3 * HD + cc] + qo * S[4 * HD + cc] + qm * S[5 * HD + cc]
                 + S[6 * HD + cc];
        hv = fmaxf(hv, 0.f);
        acc += hv * S[7 * HD + cc];
    }
    return acc;
}

__global__ void k_edge(const int* __restrict__ ei,
                       const float* __restrict__ estat, const float* __restrict__ qobs,
                       const int* __restrict__ qmask,
                       const float* __restrict__ erW1, const float* __restrict__ erb1,
                       const float* __restrict__ erW2, const float* __restrict__ erb2,
                       const float* __restrict__ eaW1, const float* __restrict__ eab1,
                       const float* __restrict__ eaW2, const float* __restrict__ eab2,
                       float* __restrict__ qhat, float* __restrict__ elog, int ne)
{
    __shared__ float sE[2][8 * HD];  // per head: rows 0-5 = W1[256+r], 6 = b1, 7 = W2
    int tid = threadIdx.x;
    for (int idx = tid; idx < 2 * 8 * HD; idx += blockDim.x) {
        int h = idx / (8 * HD);
        int rem = idx - h * 8 * HD;
        int r = rem >> 7, c = rem & 127;
        const float* W1 = h ? eaW1 : erW1;
        const float* b1 = h ? eab1 : erb1;
        const float* W2 = h ? eaW2 : erW2;
        float v;
        if (r < 6) v = W1[(256 + r) * HD + c];
        else if (r == 6) v = b1[c];
        else v = W2[c];
        sE[h][rem] = v;
    }
    __syncthreads();

    int warpg = (blockIdx.x * blockDim.x + tid) >> 5;
    int lane = tid & 31;
    int ebase = warpg * EPW;
    if (ebase >= ne) return;
    int eend = min(ebase + EPW, ne);
    int c = lane * 4;
    float eb2r = __ldg(&erb2[0]);
    float eb2a = __ldg(&eab2[0]);

    for (int e = ebase; e < eend; e += 2) {
        int e1i = e + 1;
        bool has2 = (e1i < eend);
        int e1c = has2 ? e1i : e;

        // issue all gathers for BOTH edges before any compute (MLP = 8)
        int sA0 = __ldg(&ei[e]),   dA0 = __ldg(&ei[ne + e]);
        int sB0 = __ldg(&ei[e1c]), dB0 = __ldg(&ei[ne + e1c]);
        const __half* A0 = &g_pairAh[(size_t)sA0 * 256];
        const __half* B0 = &g_pairBh[(size_t)dA0 * 256];
        const __half* A1 = &g_pairAh[(size_t)sB0 * 256];
        const __half* B1 = &g_pairBh[(size_t)dB0 * 256];
        uint2 x_ua0 = *reinterpret_cast<const uint2*>(&A0[c]);
        uint2 x_ub0 = *reinterpret_cast<const uint2*>(&B0[c]);
        uint2 x_ua1 = *reinterpret_cast<const uint2*>(&A0[128 + c]);
        uint2 x_ub1 = *reinterpret_cast<const uint2*>(&B0[128 + c]);
        uint2 y_ua0 = *reinterpret_cast<const uint2*>(&A1[c]);
        uint2 y_ub0 = *reinterpret_cast<const uint2*>(&B1[c]);
        uint2 y_ua1 = *reinterpret_cast<const uint2*>(&A1[128 + c]);
        uint2 y_ub1 = *reinterpret_cast<const uint2*>(&B1[128 + c]);

        float4 es0 = *reinterpret_cast<const float4*>(&estat[e * 4]);
        float4 es1 = *reinterpret_cast<const float4*>(&estat[e1c * 4]);
        float qo0 = __ldg(&qobs[e]),   qm0 = (float)__ldg(&qmask[e]);
        float qo1 = __ldg(&qobs[e1c]), qm1 = (float)__ldg(&qmask[e1c]);

        float x0 = edge_head_eval(sE[0], x_ua0, x_ub0, c, es0.x, es0.y, es0.z, es0.w, qo0, qm0);
        float x1 = edge_head_eval(sE[1], x_ua1, x_ub1, c, es0.x, es0.y, es0.z, es0.w, qo0, qm0);
        float y0 = edge_head_eval(sE[0], y_ua0, y_ub0, c, es1.x, es1.y, es1.z, es1.w, qo1, qm1);
        float y1 = edge_head_eval(sE[1], y_ua1, y_ub1, c, es1.x, es1.y, es1.z, es1.w, qo1, qm1);

#pragma unroll
        for (int off = 16; off; off >>= 1) {
            x0 += __shfl_xor_sync(0xffffffffu, x0, off);
            x1 += __shfl_xor_sync(0xffffffffu, x1, off);
            y0 += __shfl_xor_sync(0xffffffffu, y0, off);
            y1 += __shfl_xor_sync(0xffffffffu, y1, off);
        }
        if (lane == 0) {
            qhat[e] = x0 + eb2r;
            elog[e] = x1 + eb2a;
            if (has2) {
                qhat[e1i] = y0 + eb2r;
                elog[e1i] = y1 + eb2a;
            }
        }
    }
}

// ---------------- launch ----------------
extern "C" void kernel_launch(void* const* d_in, const int* in_sizes, int n_in,
                              void* d_out, int out_size)
{
    const int*   ei           = (const int*)d_in[0];   // edge_index is int32 (jax x64 disabled)
    const float* node_static  = (const float*)d_in[1];
    const float* edge_static  = (const float*)d_in[2];
    const float* p_obs        = (const float*)d_in[3];
    const float* q_obs        = (const float*)d_in[4];
    const int*   p_mask       = (const int*)d_in[5];
    const int*   q_mask       = (const int*)d_in[6];
    const float* W_enc        = (const float*)d_in[7];
    const float* b_enc        = (const float*)d_in[8];
    const float* W_self       = (const float*)d_in[9];
    const float* W_neigh      = (const float*)d_in[10];
    const float* b_gnn        = (const float*)d_in[11];
    const float* nrW1 = (const float*)d_in[12]; const float* nrb1 = (const float*)d_in[13];
    const float* nrW2 = (const float*)d_in[14]; const float* nrb2 = (const float*)d_in[15];
    const float* naW1 = (const float*)d_in[16]; const float* nab1 = (const float*)d_in[17];
    const float* naW2 = (const float*)d_in[18]; const float* nab2 = (const float*)d_in[19];
    const float* erW1 = (const float*)d_in[20]; const float* erb1 = (const float*)d_in[21];
    const float* erW2 = (const float*)d_in[22]; const float* erb2 = (const float*)d_in[23];
    const float* eaW1 = (const float*)d_in[24]; const float* eab1 = (const float*)d_in[25];
    const float* eaW2 = (const float*)d_in[26]; const float* eab2 = (const float*)d_in[27];

    int n  = in_sizes[3];  // N (p_obs)
    int ne = in_sizes[4];  // E (q_obs)

    float* out   = (float*)d_out;
    float* p_hat = out;
    float* q_hat = out + n;
    float* nlog  = out + n + ne;
    float* elog  = out + 2 * n + ne;

    float* gy;
    __half *gpa, *gpb, *gxh0, *gxh1, *gaggh;
    uint32_t* gpwh;
    cudaGetSymbolAddress((void**)&gy,    g_y);
    cudaGetSymbolAddress((void**)&gaggh, g_aggh);
    cudaGetSymbolAddress((void**)&gpa,   g_pairAh);
    cudaGetSymbolAddress((void**)&gpb,   g_pairBh);
    cudaGetSymbolAddress((void**)&gxh0,  g_xh0);
    cudaGetSymbolAddress((void**)&gxh1,  g_xh1);
    cudaGetSymbolAddress((void**)&gpwh,  g_pwh);

    const int SM_DUALA = 2 * SA128_BYTES;      // 69632 B (two 128-row tiles)
    const int SM_HEADS = SA64_BYTES + 4096;    // 21504 B
    cudaFuncSetAttribute(k_gemm_dualA, cudaFuncAttributeMaxDynamicSharedMemorySize, SM_DUALA);
    cudaFuncSetAttribute(k_gemm_heads, cudaFuncAttributeMaxDynamicSharedMemorySize, SM_HEADS);

    // pre-pack the 12 weight matrices: 0-2 Wself[l], 3-5 Wneigh[l], 6 nrW1, 7 naW1,
    // 8 erW1 top, 9 erW1 bot, 10 eaW1 top, 11 eaW1 bot
    PackSrc ps;
    ps.s[0] = W_self;                ps.s[1] = W_self + 16384;  ps.s[2] = W_self + 32768;
    ps.s[3] = W_neigh;               ps.s[4] = W_neigh + 16384; ps.s[5] = W_neigh + 32768;
    ps.s[6] = nrW1;                  ps.s[7] = naW1;
    ps.s[8] = erW1;                  ps.s[9] = erW1 + 16384;
    ps.s[10] = eaW1;                 ps.s[11] = eaW1 + 16384;
    k_packh<<<(12 * 8192 + 255) / 256, 256>>>(ps);

    k_encoder<<<(n * HD + 255) / 256, 256>>>(node_static, p_obs, p_mask, W_enc, b_enc, gxh0, n);
    k_zero_deg<<<(n + 255) / 256, 256>>>(n);
    k_deg<<<(ne + 255) / 256, 256>>>(ei, ne);
    int nb = (n + 1023) / 1024;
    k_scan_local<<<nb, 1024>>>(n);
    k_scan_bsum<<<1, 32>>>(nb);
    k_scan_final<<<(n + 255) / 256, 256>>>(n);
    k_fill<<<(ne + 255) / 256, 256>>>(ei, ne);

    int gblocks128 = (n + 127) / 128;
    int gblocks64  = (n + 63) / 64;
    __half* xh_in = gxh0;
    __half* xh_out = gxh1;
    for (int l = 0; l < 3; l++) {
        k_agg<<<(n * 32 + 255) / 256, 256>>>(xh_in, gaggh, n);
        // layers 0,1: fp16 shadow only (with relu); layer 2: fp32 only (no relu)
        float* cf = (l < 2) ? (float*)nullptr : gy;
        __half* ch = (l < 2) ? xh_out : (__half*)nullptr;
        k_gemm_dualA<<<gblocks128, 256, SM_DUALA>>>(xh_in, gaggh,
                                                    gpwh + l * 8192, gpwh + (3 + l) * 8192,
                                                    b_gnn + l * HD, cf, ch, n, (l < 2) ? 1 : 0);
        __half* th = xh_in;
        xh_in = xh_out;
        xh_out = th;
    }
    const float* xf = gy;  // final node embeddings (fp32)

    // all head GEMMs in one launch: node heads fully fused; pair tables -> gpa/gpb
    HeadArgs ha;
    ha.pw0[0] = gpwh + 6 * 8192;  ha.pw1[0] = gpwh + 7 * 8192;
    ha.pw0[1] = gpwh + 8 * 8192;  ha.pw1[1] = gpwh + 9 * 8192;
    ha.pw0[2] = gpwh + 10 * 8192; ha.pw1[2] = gpwh + 11 * 8192;
    ha.b0 = nrb1; ha.b1 = nab1;
    ha.w2a = nrW2; ha.w2b = naW2;
    ha.b2a = nrb2; ha.b2b = nab2;
    ha.ph = p_hat; ha.nl = nlog;
    ha.pa = gpa;  ha.pb = gpb;
    k_gemm_heads<<<gblocks64, 256, SM_HEADS>>>(xf, ha, n);

    int eblocks = (ne + 8 * EPW - 1) / (8 * EPW);
    k_edge<<<eblocks, 256>>>(ei, edge_static, q_obs, q_mask,
                             erW1, erb1, erW2, erb2,
                             eaW1, eab1, eaW2, eab2,
                             q_hat, elog, ne);
}

// round 17
// speedup vs baseline: 1.8421x; 1.0487x over previous
#include <cuda_runtime.h>
#include <cuda_fp16.h>
#include <cstdint>

#define NN 100000
#define NE 600000
#define HD 128
#define EPW 16   // edges per warp in k_edge

// ---------------- scratch (static device memory; no allocs) ----------------
static __device__ float  g_y  [NN * HD];          // fp32 final embeddings (layer 2 out)
static __device__ __half g_aggh[NN * HD];         // fp16 aggregation output
static __device__ __half g_xh0[NN * HD];          // fp16 x (ping)
static __device__ __half g_xh1[NN * HD];          // fp16 x (pong)
static __device__ __half g_pairAh[NN * 256];      // [node][0:128)=er A-part, [128:256)=ea A-part
static __device__ __half g_pairBh[NN * 256];      // [node][0:128)=er B-part, [128:256)=ea B-part
static __device__ int    g_deg[NN];
static __device__ int    g_rowptr[NN + 1];
static __device__ int    g_cursor[NN];
static __device__ int    g_col[2 * NE];
static __device__ float  g_invdeg[NN];
static __device__ int    g_tmp[NN];
static __device__ int    g_bsum[128];
static __device__ uint32_t g_pwh[12 * 8192];      // packed fp16 weights, m16n8k16 frag order

// ---------------- fp16 MMA helpers ----------------
#define MMAH(c, a0, a1, a2, a3, b0, b1)                                       \
    asm volatile("mma.sync.aligned.m16n8k16.row.col.f32.f16.f16.f32 "         \
                 "{%0,%1,%2,%3},{%4,%5,%6,%7},{%8,%9},{%0,%1,%2,%3};"         \
                 : "+f"((c)[0]), "+f"((c)[1]), "+f"((c)[2]), "+f"((c)[3])     \
                 : "r"(a0), "r"(a1), "r"(a2), "r"(a3), "r"(b0), "r"(b1))

#define LDSM4(a0, a1, a2, a3, addr)                                           \
    asm volatile("ldmatrix.sync.aligned.m8n8.x4.shared.b16 {%0,%1,%2,%3}, [%4];" \
                 : "=r"(a0), "=r"(a1), "=r"(a2), "=r"(a3) : "r"(addr))

// smem A layout: rows x 136 halves (stride 136 halves = 272B -> ldmatrix conflict-free)
#define SROW 136
#define SROW_U32 68
#define SA64_BYTES  (64 * SROW * 2)    // 17408 (heads kernel, 64-row tile)
#define SA128_BYTES (128 * SROW * 2)   // 34816 (layer kernel, 128-row tile)

// ---------------- weight pre-pack: 12 matrices into fp16 m16n8k16 fragment order ----------------
struct PackSrc { const float* s[12]; };

__global__ void k_packh(PackSrc ps)
{
    int idx = blockIdx.x * 256 + threadIdx.x;
    if (idx >= 12 * 8192) return;
    int m = idx >> 13, e = idx & 8191;
    int reg = e & 1;
    int lane = (e >> 1) & 31;
    int knt = e >> 6;                // ks*16 + nt
    int ks = knt >> 4, nt = knt & 15;
    int tg = lane & 3, gid = lane >> 2;
    int k = ks * 16 + reg * 8 + tg * 2;
    int n = nt * 8 + gid;
    const float* W = ps.s[m];
    __half2 h = __floats2half2_rn(__ldg(&W[k * HD + n]), __ldg(&W[(k + 1) * HD + n]));
    g_pwh[m * 8192 + e] = *reinterpret_cast<uint32_t*>(&h);
}

// ---------------- encoder: xh = fp16(node_feats(8) @ W_enc + b_enc) ----------------
__global__ void k_encoder(const float* __restrict__ ns, const float* __restrict__ pobs,
                          const int* __restrict__ pmask, const float* __restrict__ Wenc,
                          const float* __restrict__ benc, __half* __restrict__ xh, int n)
{
    __shared__ float sW[8 * HD];
    __shared__ float sb[HD];
    for (int i = threadIdx.x; i < 8 * HD; i += blockDim.x) sW[i] = Wenc[i];
    for (int i = threadIdx.x; i < HD; i += blockDim.x) sb[i] = benc[i];
    __syncthreads();
    int idx = blockIdx.x * blockDim.x + threadIdx.x;
    if (idx >= n * HD) return;
    int node = idx >> 7, h = idx & 127;
    float f0 = ns[node * 6 + 0], f1 = ns[node * 6 + 1], f2 = ns[node * 6 + 2];
    float f3 = ns[node * 6 + 3], f4 = ns[node * 6 + 4], f5 = ns[node * 6 + 5];
    float f6 = pobs[node];
    float f7 = (float)pmask[node];
    float o = sb[h];
    o += f0 * sW[0 * HD + h] + f1 * sW[1 * HD + h] + f2 * sW[2 * HD + h] + f3 * sW[3 * HD + h];
    o += f4 * sW[4 * HD + h] + f5 * sW[5 * HD + h] + f6 * sW[6 * HD + h] + f7 * sW[7 * HD + h];
    xh[idx] = __float2half_rn(o);
}

// ---------------- CSR build ----------------
__global__ void k_zero_deg(int n)
{
    int i = blockIdx.x * blockDim.x + threadIdx.x;
    if (i < n) g_deg[i] = 0;
}

__global__ void k_deg(const int* __restrict__ ei, int ne)
{
    int e = blockIdx.x * blockDim.x + threadIdx.x;
    if (e >= ne) return;
    int s = ei[e], d = ei[ne + e];
    atomicAdd(&g_deg[s], 1);
    atomicAdd(&g_deg[d], 1);
}

__global__ void k_scan_local(int n)
{
    __shared__ int sh[1024];
    int t = threadIdx.x;
    int i = blockIdx.x * 1024 + t;
    int v = (i < n) ? g_deg[i] : 0;
    sh[t] = v;
    __syncthreads();
    for (int off = 1; off < 1024; off <<= 1) {
        int tv = (t >= off) ? sh[t - off] : 0;
        __syncthreads();
        sh[t] += tv;
        __syncthreads();
    }
    if (i < n) g_tmp[i] = sh[t];
    if (t == 1023) g_bsum[blockIdx.x] = sh[1023];
}

__global__ void k_scan_bsum(int nb)
{
    if (threadIdx.x == 0) {
        int acc = 0;
        for (int b = 0; b < nb; b++) { int tv = g_bsum[b]; g_bsum[b] = acc; acc += tv; }
    }
}

__global__ void k_scan_final(int n)
{
    int i = blockIdx.x * blockDim.x + threadIdx.x;
    if (i >= n) return;
    int incl = g_tmp[i] + g_bsum[i >> 10];
    g_rowptr[i + 1] = incl;
    int d = g_deg[i];
    g_cursor[i] = incl - d;
    g_invdeg[i] = 1.0f / (float)(d > 0 ? d : 1);
    if (i == 0) g_rowptr[0] = 0;
}

__global__ void k_fill(const int* __restrict__ ei, int ne)
{
    int e = blockIdx.x * blockDim.x + threadIdx.x;
    if (e >= ne) return;
    int s = ei[e], d = ei[ne + e];
    int p = atomicAdd(&g_cursor[d], 1);
    g_col[p] = s;
    int q = atomicAdd(&g_cursor[s], 1);
    g_col[q] = d;
}

// ---------------- mean aggregation: 2 nodes per warp (16 lanes each), uint4 loads ----------------
__global__ void k_agg(const __half* __restrict__ xh, __half* __restrict__ agg, int n)
{
    int warp = (blockIdx.x * blockDim.x + threadIdx.x) >> 5;
    int lane = threadIdx.x & 31;
    int half_id = lane >> 4;         // 0 or 1: which node within the warp
    int hl = lane & 15;              // lane within half-warp
    int w = warp * 2 + half_id;
    if (w >= n) return;
    int beg = g_rowptr[w], end = g_rowptr[w + 1];
    int c = hl * 8;                  // halves offset; uint4 = 8 halves = 16B
    float a0 = 0.f, a1 = 0.f, a2 = 0.f, a3 = 0.f;
    float a4 = 0.f, a5 = 0.f, a6 = 0.f, a7 = 0.f;
    int i = beg;
    for (; i + 4 <= end; i += 4) {
        int n0 = g_col[i], n1 = g_col[i + 1], n2 = g_col[i + 2], n3 = g_col[i + 3];
        uint4 u0 = *reinterpret_cast<const uint4*>(&xh[(size_t)n0 * HD + c]);
        uint4 u1 = *reinterpret_cast<const uint4*>(&xh[(size_t)n1 * HD + c]);
        uint4 u2 = *reinterpret_cast<const uint4*>(&xh[(size_t)n2 * HD + c]);
        uint4 u3 = *reinterpret_cast<const uint4*>(&xh[(size_t)n3 * HD + c]);
#define ACC8(u)                                                                 \
        {                                                                       \
            const __half2* p = reinterpret_cast<const __half2*>(&(u));          \
            float2 f0 = __half22float2(p[0]), f1 = __half22float2(p[1]);        \
            float2 f2 = __half22float2(p[2]), f3 = __half22float2(p[3]);        \
            a0 += f0.x; a1 += f0.y; a2 += f1.x; a3 += f1.y;                     \
            a4 += f2.x; a5 += f2.y; a6 += f3.x; a7 += f3.y;                     \
        }
        ACC8(u0) ACC8(u1) ACC8(u2) ACC8(u3)
    }
    for (; i < end; i++) {
        int nb = g_col[i];
        uint4 u = *reinterpret_cast<const uint4*>(&xh[(size_t)nb * HD + c]);
        ACC8(u)
    }
#undef ACC8
    float sc = g_invdeg[w];
    __half2 h0 = __floats2half2_rn(a0 * sc, a1 * sc);
    __half2 h1 = __floats2half2_rn(a2 * sc, a3 * sc);
    __half2 h2 = __floats2half2_rn(a4 * sc, a5 * sc);
    __half2 h3 = __floats2half2_rn(a6 * sc, a7 * sc);
    uint4 o;
    o.x = *reinterpret_cast<uint32_t*>(&h0);
    o.y = *reinterpret_cast<uint32_t*>(&h1);
    o.z = *reinterpret_cast<uint32_t*>(&h2);
    o.w = *reinterpret_cast<uint32_t*>(&h3);
    *reinterpret_cast<uint4*>(&agg[(size_t)w * HD + c]) = o;
}

// ---------------- GNN layer GEMM (fp16 MMA, 128-row tile): C = op(xh@W0 + agg@W1 + b) ----------------
__global__ void __launch_bounds__(256) k_gemm_dualA(
    const __half* __restrict__ Ah, const __half* __restrict__ A2h,
    const uint32_t* __restrict__ pW0, const uint32_t* __restrict__ pW1,
    const float* __restrict__ bias, float* __restrict__ C,
    __half* __restrict__ Ch, int n, int relu)
{
    extern __shared__ uint32_t sm[];
    uint32_t* sA  = sm;                       // 128 x 136 halves
    uint32_t* sA2 = sm + 128 * SROW_U32;

    int tid = threadIdx.x;
    int row0 = blockIdx.x * 128;
    for (int idx = tid; idx < 8192; idx += 256) {
        int r = idx >> 6, c2 = idx & 63;
        int gr = row0 + r;
        bool ok = gr < n;
        sA [r * SROW_U32 + c2] = ok ? reinterpret_cast<const uint32_t*>(Ah)[(size_t)gr * 64 + c2] : 0u;
        sA2[r * SROW_U32 + c2] = ok ? reinterpret_cast<const uint32_t*>(A2h)[(size_t)gr * 64 + c2] : 0u;
    }
    __syncthreads();

    int wid = tid >> 5, lane = tid & 31;
    int tg = lane & 3, gid = lane >> 2;
    int nt0 = wid * 2;
    int rowA = lane & 15;
    int hi8 = (lane >> 4) << 3;

    uint32_t sAbase  = (uint32_t)__cvta_generic_to_shared(sA);
    uint32_t sA2base = (uint32_t)__cvta_generic_to_shared(sA2);

    float acc[8][8];
#pragma unroll
    for (int s = 0; s < 8; s++)
#pragma unroll
        for (int j = 0; j < 8; j++) acc[s][j] = 0.f;

    const uint2* B0 = reinterpret_cast<const uint2*>(pW0) + (nt0 * 32 + lane);
    const uint2* B1 = reinterpret_cast<const uint2*>(pW1) + (nt0 * 32 + lane);

#pragma unroll 1
    for (int ks = 0; ks < 8; ks++) {
        uint2 b0 = __ldg(B0 + ks * 512);
        uint2 b1 = __ldg(B0 + ks * 512 + 32);
        uint2 d0 = __ldg(B1 + ks * 512);
        uint2 d1 = __ldg(B1 + ks * 512 + 32);
        uint32_t coff = (ks * 16 + hi8) * 2;
#pragma unroll
        for (int s = 0; s < 8; s++) {
            uint32_t radd = ((s * 16 + rowA) * SROW) * 2 + coff;
            uint32_t a0, a1, a2, a3;
            LDSM4(a0, a1, a2, a3, sAbase + radd);
            MMAH(acc[s], a0, a1, a2, a3, b0.x, b0.y);
            MMAH(acc[s] + 4, a0, a1, a2, a3, b1.x, b1.y);
            uint32_t e0, e1, e2, e3;
            LDSM4(e0, e1, e2, e3, sA2base + radd);
            MMAH(acc[s], e0, e1, e2, e3, d0.x, d0.y);
            MMAH(acc[s] + 4, e0, e1, e2, e3, d1.x, d1.y);
        }
    }

    int cbase = wid * 16;
    float bb[4];
    bb[0] = __ldg(&bias[cbase + 2 * tg]);
    bb[1] = __ldg(&bias[cbase + 2 * tg + 1]);
    bb[2] = __ldg(&bias[cbase + 8 + 2 * tg]);
    bb[3] = __ldg(&bias[cbase + 8 + 2 * tg + 1]);
#pragma unroll
    for (int s = 0; s < 8; s++) {
#pragma unroll
        for (int t = 0; t < 2; t++) {
            int col = cbase + t * 8 + 2 * tg;
            int r = row0 + s * 16 + gid;
            float v0 = acc[s][t * 4 + 0] + bb[t * 2 + 0];
            float v1 = acc[s][t * 4 + 1] + bb[t * 2 + 1];
            float v2 = acc[s][t * 4 + 2] + bb[t * 2 + 0];
            float v3 = acc[s][t * 4 + 3] + bb[t * 2 + 1];
            if (relu) {
                v0 = fmaxf(v0, 0.f); v1 = fmaxf(v1, 0.f);
                v2 = fmaxf(v2, 0.f); v3 = fmaxf(v3, 0.f);
            }
            if (r < n) {
                if (C)
                    *reinterpret_cast<float2*>(&C[(size_t)r * HD + col]) = make_float2(v0, v1);
                if (Ch)
                    *reinterpret_cast<__half2*>(&Ch[(size_t)r * HD + col]) = __floats2half2_rn(v0, v1);
            }
            if (r + 8 < n) {
                if (C)
                    *reinterpret_cast<float2*>(&C[(size_t)(r + 8) * HD + col]) = make_float2(v2, v3);
                if (Ch)
                    *reinterpret_cast<__half2*>(&Ch[(size_t)(r + 8) * HD + col]) = __floats2half2_rn(v2, v3);
            }
        }
    }
}

// ---------------- merged head GEMMs (fp16 MMA, 64-row tile): fused W2 dot + pair tables ----------------
struct HeadArgs {
    const uint32_t* pw0[3];
    const uint32_t* pw1[3];
    const float* b0;
    const float* b1;
    const float* w2a;
    const float* w2b;
    const float* b2a;
    const float* b2b;
    float* ph;   // p_hat
    float* nl;   // node_logits
    __half* pa;
    __half* pb;
};

__device__ __forceinline__ void mma_pair_h(
    uint32_t sAbase,
    const uint32_t* __restrict__ pW0, const uint32_t* __restrict__ pW1,
    int lane, int nt0, int rowA, int hi8, float acc0[4][8], float acc1[4][8])
{
#pragma unroll
    for (int s = 0; s < 4; s++)
#pragma unroll
        for (int j = 0; j < 8; j++) { acc0[s][j] = 0.f; acc1[s][j] = 0.f; }

    const uint2* B0 = reinterpret_cast<const uint2*>(pW0) + (nt0 * 32 + lane);
    const uint2* B1 = reinterpret_cast<const uint2*>(pW1) + (nt0 * 32 + lane);

#pragma unroll 2
    for (int ks = 0; ks < 8; ks++) {
        uint2 b0 = __ldg(B0 + ks * 512);
        uint2 b1 = __ldg(B0 + ks * 512 + 32);
        uint2 d0 = __ldg(B1 + ks * 512);
        uint2 d1 = __ldg(B1 + ks * 512 + 32);
        uint32_t coff = (ks * 16 + hi8) * 2;
#pragma unroll
        for (int s = 0; s < 4; s++) {
            uint32_t radd = ((s * 16 + rowA) * SROW) * 2 + coff;
            uint32_t a0, a1, a2, a3;
            LDSM4(a0, a1, a2, a3, sAbase + radd);
            MMAH(acc0[s], a0, a1, a2, a3, b0.x, b0.y);
            MMAH(acc0[s] + 4, a0, a1, a2, a3, b1.x, b1.y);
            MMAH(acc1[s], a0, a1, a2, a3, d0.x, d0.y);
            MMAH(acc1[s] + 4, a0, a1, a2, a3, d1.x, d1.y);
        }
    }
}

__global__ void __launch_bounds__(256) k_gemm_heads(
    const float* __restrict__ A, HeadArgs ha, int n)
{
    extern __shared__ uint32_t sm[];
    uint32_t* sA = sm;                           // 17408 B
    float* sred_a = (float*)(sm + 64 * SROW_U32);  // 64 rows x 8 warps
    float* sred_b = sred_a + 512;

    int tid = threadIdx.x;
    int row0 = blockIdx.x * 64;
    for (int idx = tid; idx < 4096; idx += 256) {
        int r = idx >> 6, c2 = idx & 63;
        int gr = row0 + r;
        float2 f = (gr < n) ? *reinterpret_cast<const float2*>(&A[(size_t)gr * HD + c2 * 2])
                            : make_float2(0.f, 0.f);
        __half2 h = __floats2half2_rn(f.x, f.y);
        sA[r * SROW_U32 + c2] = *reinterpret_cast<uint32_t*>(&h);
    }
    __syncthreads();

    int wid = tid >> 5, lane = tid & 31;
    int tg = lane & 3, gid = lane >> 2;
    int nt0 = wid * 2;
    int cbase = wid * 16;
    int rowA = lane & 15;
    int hi8 = (lane >> 4) << 3;
    uint32_t sAbase = (uint32_t)__cvta_generic_to_shared(sA);

    float acc0[4][8], acc1[4][8];

    // ---- phase 0: nodehead hidden + fused W2 dot ----
    mma_pair_h(sAbase, ha.pw0[0], ha.pw1[0], lane, nt0, rowA, hi8, acc0, acc1);
    {
        float bb0[4], bb1[4], wa[4], wb[4];
        bb0[0] = __ldg(&ha.b0[cbase + 2 * tg]);
        bb0[1] = __ldg(&ha.b0[cbase + 2 * tg + 1]);
        bb0[2] = __ldg(&ha.b0[cbase + 8 + 2 * tg]);
        bb0[3] = __ldg(&ha.b0[cbase + 8 + 2 * tg + 1]);
        bb1[0] = __ldg(&ha.b1[cbase + 2 * tg]);
        bb1[1] = __ldg(&ha.b1[cbase + 2 * tg + 1]);
        bb1[2] = __ldg(&ha.b1[cbase + 8 + 2 * tg]);
        bb1[3] = __ldg(&ha.b1[cbase + 8 + 2 * tg + 1]);
        wa[0] = __ldg(&ha.w2a[cbase + 2 * tg]);
        wa[1] = __ldg(&ha.w2a[cbase + 2 * tg + 1]);
        wa[2] = __ldg(&ha.w2a[cbase + 8 + 2 * tg]);
        wa[3] = __ldg(&ha.w2a[cbase + 8 + 2 * tg + 1]);
        wb[0] = __ldg(&ha.w2b[cbase + 2 * tg]);
        wb[1] = __ldg(&ha.w2b[cbase + 2 * tg + 1]);
        wb[2] = __ldg(&ha.w2b[cbase + 8 + 2 * tg]);
        wb[3] = __ldg(&ha.w2b[cbase + 8 + 2 * tg + 1]);
#pragma unroll
        for (int s = 0; s < 4; s++) {
            float ra_lo = 0.f, ra_hi = 0.f, rb_lo = 0.f, rb_hi = 0.f;
#pragma unroll
            for (int t = 0; t < 2; t++) {
                float u0 = fmaxf(acc0[s][t * 4 + 0] + bb0[t * 2 + 0], 0.f);
                float u1 = fmaxf(acc0[s][t * 4 + 1] + bb0[t * 2 + 1], 0.f);
                float u2 = fmaxf(acc0[s][t * 4 + 2] + bb0[t * 2 + 0], 0.f);
                float u3 = fmaxf(acc0[s][t * 4 + 3] + bb0[t * 2 + 1], 0.f);
                float v0 = fmaxf(acc1[s][t * 4 + 0] + bb1[t * 2 + 0], 0.f);
                float v1 = fmaxf(acc1[s][t * 4 + 1] + bb1[t * 2 + 1], 0.f);
                float v2 = fmaxf(acc1[s][t * 4 + 2] + bb1[t * 2 + 0], 0.f);
                float v3 = fmaxf(acc1[s][t * 4 + 3] + bb1[t * 2 + 1], 0.f);
                ra_lo += u0 * wa[t * 2 + 0] + u1 * wa[t * 2 + 1];
                ra_hi += u2 * wa[t * 2 + 0] + u3 * wa[t * 2 + 1];
                rb_lo += v0 * wb[t * 2 + 0] + v1 * wb[t * 2 + 1];
                rb_hi += v2 * wb[t * 2 + 0] + v3 * wb[t * 2 + 1];
            }
#pragma unroll
            for (int o = 1; o <= 2; o <<= 1) {
                ra_lo += __shfl_xor_sync(0xffffffffu, ra_lo, o);
                ra_hi += __shfl_xor_sync(0xffffffffu, ra_hi, o);
                rb_lo += __shfl_xor_sync(0xffffffffu, rb_lo, o);
                rb_hi += __shfl_xor_sync(0xffffffffu, rb_hi, o);
            }
            if (tg == 0) {
                int lr = s * 16 + gid;
                sred_a[lr * 8 + wid] = ra_lo;
                sred_a[(lr + 8) * 8 + wid] = ra_hi;
                sred_b[lr * 8 + wid] = rb_lo;
                sred_b[(lr + 8) * 8 + wid] = rb_hi;
            }
        }
    }
    __syncthreads();
    if (tid < 64) {
        int gr = row0 + tid;
        if (gr < n) {
            float sa = 0.f, sb = 0.f;
#pragma unroll
            for (int c = 0; c < 8; c++) { sa += sred_a[tid * 8 + c]; sb += sred_b[tid * 8 + c]; }
            ha.ph[gr] = sa + __ldg(&ha.b2a[0]);
            ha.nl[gr] = sb + __ldg(&ha.b2b[0]);
        }
    }

    // ---- phases 1,2: pair tables, fp16, stride 256, col offset 0 / 128 ----
#pragma unroll 1
    for (int ph = 1; ph < 3; ph++) {
        mma_pair_h(sAbase, ha.pw0[ph], ha.pw1[ph], lane, nt0, rowA, hi8, acc0, acc1);
        int coff = (ph - 1) * 128;
#pragma unroll
        for (int s = 0; s < 4; s++) {
#pragma unroll
            for (int t = 0; t < 2; t++) {
                int col = coff + cbase + t * 8 + 2 * tg;
                int r = row0 + s * 16 + gid;
                if (r < n) {
                    *reinterpret_cast<__half2*>(&ha.pa[(size_t)r * 256 + col]) =
                        __floats2half2_rn(acc0[s][t * 4 + 0], acc0[s][t * 4 + 1]);
                    *reinterpret_cast<__half2*>(&ha.pb[(size_t)r * 256 + col]) =
                        __floats2half2_rn(acc1[s][t * 4 + 0], acc1[s][t * 4 + 1]);
                }
                if (r + 8 < n) {
                    *reinterpret_cast<__half2*>(&ha.pa[(size_t)(r + 8) * 256 + col]) =
                        __floats2half2_rn(acc0[s][t * 4 + 2], acc0[s][t * 4 + 3]);
                    *reinterpret_cast<__half2*>(&ha.pb[(size_t)(r + 8) * 256 + col]) =
                        __floats2half2_rn(acc1[s][t * 4 + 2], acc1[s][t * 4 + 3]);
                }
            }
        }
    }
}

// ---------------- edge heads: EPW edges per warp, 4-edge software pipeline ----------------
__device__ __forceinline__ float edge_head_eval(
    const float* S, uint2 ua, uint2 ub, int c,
    float e0, float e1, float e2, float e3, float qo, float qm)
{
    const __half2* pa = reinterpret_cast<const __half2*>(&ua);
    const __half2* pb = reinterpret_cast<const __half2*>(&ub);
    float2 a01 = __half22float2(pa[0]), a23 = __half22float2(pa[1]);
    float2 b01 = __half22float2(pb[0]), b23 = __half22float2(pb[1]);
    float av[4] = {a01.x, a01.y, a23.x, a23.y};
    float bv[4] = {b01.x, b01.y, b23.x, b23.y};
    float acc = 0.f;
#pragma unroll
    for (int t = 0; t < 4; t++) {
        int cc = c + t;
        float hv = av[t] + bv[t] + e0 * S[cc] + e1 * S[HD + cc] + e2 * S[2 * HD + cc]
                 + e3 * S[3 * HD + cc] + qo * S[4 * HD + cc] + qm * S[5 * HD + cc]
                 + S[6 * HD + cc];
        hv = fmaxf(hv, 0.f);
        acc += hv * S[7 * HD + cc];
    }
    return acc;
}

__global__ void k_edge(const int* __restrict__ ei,
                       const float* __restrict__ estat, const float* __restrict__ qobs,
                       const int* __restrict__ qmask,
                       const float* __restrict__ erW1, const float* __restrict__ erb1,
                       const float* __restrict__ erW2, const float* __restrict__ erb2,
                       const float* __restrict__ eaW1, const float* __restrict__ eab1,
                       const float* __restrict__ eaW2, const float* __restrict__ eab2,
                       float* __restrict__ qhat, float* __restrict__ elog, int ne)
{
    __shared__ float sE[2][8 * HD];  // per head: rows 0-5 = W1[256+r], 6 = b1, 7 = W2
    int tid = threadIdx.x;
    for (int idx = tid; idx < 2 * 8 * HD; idx += blockDim.x) {
        int h = idx / (8 * HD);
        int rem = idx - h * 8 * HD;
        int r = rem >> 7, c = rem & 127;
        const float* W1 = h ? eaW1 : erW1;
        const float* b1 = h ? eab1 : erb1;
        const float* W2 = h ? eaW2 : erW2;
        float v;
        if (r < 6) v = W1[(256 + r) * HD + c];
        else if (r == 6) v = b1[c];
        else v = W2[c];
        sE[h][rem] = v;
    }
    __syncthreads();

    int warpg = (blockIdx.x * blockDim.x + tid) >> 5;
    int lane = tid & 31;
    int ebase = warpg * EPW;
    if (ebase >= ne) return;
    int eend = min(ebase + EPW, ne);
    int c = lane * 4;
    float eb2r = __ldg(&erb2[0]);
    float eb2a = __ldg(&eab2[0]);

    for (int e = ebase; e < eend; e += 4) {
        int ec[4];
        ec[0] = e;
        ec[1] = (e + 1 < eend) ? e + 1 : e;
        ec[2] = (e + 2 < eend) ? e + 2 : e;
        ec[3] = (e + 3 < eend) ? e + 3 : e;

        // issue ALL gathers for 4 edges before any compute (MLP = 16)
        uint2 ua0[4], ub0[4], ua1[4], ub1[4];
        float4 es[4];
        float qo[4], qm[4];
#pragma unroll
        for (int j = 0; j < 4; j++) {
            int s = __ldg(&ei[ec[j]]), d = __ldg(&ei[ne + ec[j]]);
            const __half* A = &g_pairAh[(size_t)s * 256];
            const __half* B = &g_pairBh[(size_t)d * 256];
            ua0[j] = *reinterpret_cast<const uint2*>(&A[c]);
            ub0[j] = *reinterpret_cast<const uint2*>(&B[c]);
            ua1[j] = *reinterpret_cast<const uint2*>(&A[128 + c]);
            ub1[j] = *reinterpret_cast<const uint2*>(&B[128 + c]);
            es[j] = *reinterpret_cast<const float4*>(&estat[ec[j] * 4]);
            qo[j] = __ldg(&qobs[ec[j]]);
            qm[j] = (float)__ldg(&qmask[ec[j]]);
        }

        float r0[4], r1[4];
#pragma unroll
        for (int j = 0; j < 4; j++) {
            r0[j] = edge_head_eval(sE[0], ua0[j], ub0[j], c, es[j].x, es[j].y, es[j].z, es[j].w, qo[j], qm[j]);
            r1[j] = edge_head_eval(sE[1], ua1[j], ub1[j], c, es[j].x, es[j].y, es[j].z, es[j].w, qo[j], qm[j]);
        }
#pragma unroll
        for (int off = 16; off; off >>= 1) {
#pragma unroll
            for (int j = 0; j < 4; j++) {
                r0[j] += __shfl_xor_sync(0xffffffffu, r0[j], off);
                r1[j] += __shfl_xor_sync(0xffffffffu, r1[j], off);
            }
        }
        if (lane == 0) {
#pragma unroll
            for (int j = 0; j < 4; j++) {
                if (e + j < eend) {
                    qhat[e + j] = r0[j] + eb2r;
                    elog[e + j] = r1[j] + eb2a;
                }
            }
        }
    }
}

// ---------------- launch ----------------
extern "C" void kernel_launch(void* const* d_in, const int* in_sizes, int n_in,
                              void* d_out, int out_size)
{
    const int*   ei           = (const int*)d_in[0];   // edge_index is int32 (jax x64 disabled)
    const float* node_static  = (const float*)d_in[1];
    const float* edge_static  = (const float*)d_in[2];
    const float* p_obs        = (const float*)d_in[3];
    const float* q_obs        = (const float*)d_in[4];
    const int*   p_mask       = (const int*)d_in[5];
    const int*   q_mask       = (const int*)d_in[6];
    const float* W_enc        = (const float*)d_in[7];
    const float* b_enc        = (const float*)d_in[8];
    const float* W_self       = (const float*)d_in[9];
    const float* W_neigh      = (const float*)d_in[10];
    const float* b_gnn        = (const float*)d_in[11];
    const float* nrW1 = (const float*)d_in[12]; const float* nrb1 = (const float*)d_in[13];
    const float* nrW2 = (const float*)d_in[14]; const float* nrb2 = (const float*)d_in[15];
    const float* naW1 = (const float*)d_in[16]; const float* nab1 = (const float*)d_in[17];
    const float* naW2 = (const float*)d_in[18]; const float* nab2 = (const float*)d_in[19];
    const float* erW1 = (const float*)d_in[20]; const float* erb1 = (const float*)d_in[21];
    const float* erW2 = (const float*)d_in[22]; const float* erb2 = (const float*)d_in[23];
    const float* eaW1 = (const float*)d_in[24]; const float* eab1 = (const float*)d_in[25];
    const float* eaW2 = (const float*)d_in[26]; const float* eab2 = (const float*)d_in[27];

    int n  = in_sizes[3];  // N (p_obs)
    int ne = in_sizes[4];  // E (q_obs)

    float* out   = (float*)d_out;
    float* p_hat = out;
    float* q_hat = out + n;
    float* nlog  = out + n + ne;
    float* elog  = out + 2 * n + ne;

    float* gy;
    __half *gpa, *gpb, *gxh0, *gxh1, *gaggh;
    uint32_t* gpwh;
    cudaGetSymbolAddress((void**)&gy,    g_y);
    cudaGetSymbolAddress((void**)&gaggh, g_aggh);
    cudaGetSymbolAddress((void**)&gpa,   g_pairAh);
    cudaGetSymbolAddress((void**)&gpb,   g_pairBh);
    cudaGetSymbolAddress((void**)&gxh0,  g_xh0);
    cudaGetSymbolAddress((void**)&gxh1,  g_xh1);
    cudaGetSymbolAddress((void**)&gpwh,  g_pwh);

    const int SM_DUALA = 2 * SA128_BYTES;      // 69632 B (two 128-row tiles)
    const int SM_HEADS = SA64_BYTES + 4096;    // 21504 B
    cudaFuncSetAttribute(k_gemm_dualA, cudaFuncAttributeMaxDynamicSharedMemorySize, SM_DUALA);
    cudaFuncSetAttribute(k_gemm_heads, cudaFuncAttributeMaxDynamicSharedMemorySize, SM_HEADS);

    // pre-pack the 12 weight matrices: 0-2 Wself[l], 3-5 Wneigh[l], 6 nrW1, 7 naW1,
    // 8 erW1 top, 9 erW1 bot, 10 eaW1 top, 11 eaW1 bot
    PackSrc ps;
    ps.s[0] = W_self;                ps.s[1] = W_self + 16384;  ps.s[2] = W_self + 32768;
    ps.s[3] = W_neigh;               ps.s[4] = W_neigh + 16384; ps.s[5] = W_neigh + 32768;
    ps.s[6] = nrW1;                  ps.s[7] = naW1;
    ps.s[8] = erW1;                  ps.s[9] = erW1 + 16384;
    ps.s[10] = eaW1;                 ps.s[11] = eaW1 + 16384;
    k_packh<<<(12 * 8192 + 255) / 256, 256>>>(ps);

    k_encoder<<<(n * HD + 255) / 256, 256>>>(node_static, p_obs, p_mask, W_enc, b_enc, gxh0, n);
    k_zero_deg<<<(n + 255) / 256, 256>>>(n);
    k_deg<<<(ne + 255) / 256, 256>>>(ei, ne);
    int nb = (n + 1023) / 1024;
    k_scan_local<<<nb, 1024>>>(n);
    k_scan_bsum<<<1, 32>>>(nb);
    k_scan_final<<<(n + 255) / 256, 256>>>(n);
    k_fill<<<(ne + 255) / 256, 256>>>(ei, ne);

    int gblocks128 = (n + 127) / 128;
    int gblocks64  = (n + 63) / 64;
    __half* xh_in = gxh0;
    __half* xh_out = gxh1;
    for (int l = 0; l < 3; l++) {
        // 2 nodes per warp -> n/2 warps
        int aggwarps = (n + 1) / 2;
        k_agg<<<(aggwarps * 32 + 255) / 256, 256>>>(xh_in, gaggh, n);
        // layers 0,1: fp16 shadow only (with relu); layer 2: fp32 only (no relu)
        float* cf = (l < 2) ? (float*)nullptr : gy;
        __half* ch = (l < 2) ? xh_out : (__half*)nullptr;
        k_gemm_dualA<<<gblocks128, 256, SM_DUALA>>>(xh_in, gaggh,
                                                    gpwh + l * 8192, gpwh + (3 + l) * 8192,
                                                    b_gnn + l * HD, cf, ch, n, (l < 2) ? 1 : 0);
        __half* th = xh_in;
        xh_in = xh_out;
        xh_out = th;
    }
    const float* xf = gy;  // final node embeddings (fp32)

    // all head GEMMs in one launch: node heads fully fused; pair tables -> gpa/gpb
    HeadArgs ha;
    ha.pw0[0] = gpwh + 6 * 8192;  ha.pw1[0] = gpwh + 7 * 8192;
    ha.pw0[1] = gpwh + 8 * 8192;  ha.pw1[1] = gpwh + 9 * 8192;
    ha.pw0[2] = gpwh + 10 * 8192; ha.pw1[2] = gpwh + 11 * 8192;
    ha.b0 = nrb1; ha.b1 = nab1;
    ha.w2a = nrW2; ha.w2b = naW2;
    ha.b2a = nrb2; ha.b2b = nab2;
    ha.ph = p_hat; ha.nl = nlog;
    ha.pa = gpa;  ha.pb = gpb;
    k_gemm_heads<<<gblocks64, 256, SM_HEADS>>>(xf, ha, n);

    int eblocks = (ne + 8 * EPW - 1) / (8 * EPW);
    k_edge<<<eblocks, 256>>>(ei, edge_static, q_obs, q_mask,
                             erW1, erb1, erW2, erb2,
                             eaW1, eab1, eaW2, eab2,
                             q_hat, elog, ne);
}